// round 1
// baseline (speedup 1.0000x reference)
#include <cuda_runtime.h>
#include <math.h>

#define S_LEN 4096
#define D_MODEL 1024
#define NHEAD 16
#define HDK 64

// Scratch (allocation-free rule: __device__ globals)
__device__ float g_Q[S_LEN * D_MODEL];
__device__ float g_K[S_LEN * D_MODEL];
__device__ float g_V[S_LEN * D_MODEL];
__device__ float g_A[S_LEN * D_MODEL];

// ---------------------------------------------------------------------------
// GEMM: C[M,N] = A[M,K] * B[N,K]^T   (both operands row-major, K contiguous)
// 128x128 tile, BK=8, 256 threads, 8x8 per thread.
// ---------------------------------------------------------------------------
template<int M, int N, int K>
__global__ void __launch_bounds__(256, 2)
gemm_nt(const float* __restrict__ A, const float* __restrict__ B, float* __restrict__ C) {
    __shared__ float As[8][128];
    __shared__ float Bs[8][128];
    const int tid  = threadIdx.x;
    const int bm   = blockIdx.y * 128;
    const int bn   = blockIdx.x * 128;
    const int trow = (tid >> 4) << 3;   // 0..120
    const int tcol = (tid & 15) << 3;   // 0..120
    const int lr   = tid >> 1;          // 0..127
    const int lk   = (tid & 1) << 2;    // 0 or 4

    float acc[8][8];
    #pragma unroll
    for (int i = 0; i < 8; i++)
        #pragma unroll
        for (int j = 0; j < 8; j++) acc[i][j] = 0.f;

    const float* Ap = A + (bm + lr) * K + lk;
    const float* Bp = B + (bn + lr) * K + lk;

    for (int kt = 0; kt < K; kt += 8) {
        float4 a = *(const float4*)(Ap + kt);
        float4 b = *(const float4*)(Bp + kt);
        As[lk + 0][lr] = a.x; As[lk + 1][lr] = a.y;
        As[lk + 2][lr] = a.z; As[lk + 3][lr] = a.w;
        Bs[lk + 0][lr] = b.x; Bs[lk + 1][lr] = b.y;
        Bs[lk + 2][lr] = b.z; Bs[lk + 3][lr] = b.w;
        __syncthreads();
        #pragma unroll
        for (int k = 0; k < 8; k++) {
            float4 a0 = *(const float4*)&As[k][trow];
            float4 a1 = *(const float4*)&As[k][trow + 4];
            float4 b0 = *(const float4*)&Bs[k][tcol];
            float4 b1 = *(const float4*)&Bs[k][tcol + 4];
            float ra[8] = {a0.x, a0.y, a0.z, a0.w, a1.x, a1.y, a1.z, a1.w};
            float rb[8] = {b0.x, b0.y, b0.z, b0.w, b1.x, b1.y, b1.z, b1.w};
            #pragma unroll
            for (int i = 0; i < 8; i++)
                #pragma unroll
                for (int j = 0; j < 8; j++)
                    acc[i][j] = fmaf(ra[i], rb[j], acc[i][j]);
        }
        __syncthreads();
    }
    #pragma unroll
    for (int i = 0; i < 8; i++) {
        #pragma unroll
        for (int j = 0; j < 8; j += 4) {
            float4 v = make_float4(acc[i][j], acc[i][j+1], acc[i][j+2], acc[i][j+3]);
            *(float4*)(C + (bm + trow + i) * N + bn + tcol + j) = v;
        }
    }
}

// ---------------------------------------------------------------------------
// RoPE applied in-place to Q and K. One thread per (token, head, pair):
// cos/sin computed once, applied to both tensors.
// ---------------------------------------------------------------------------
__global__ void rope_kernel(float* __restrict__ Q, float* __restrict__ K,
                            const int* __restrict__ pos) {
    int idx = blockIdx.x * blockDim.x + threadIdx.x;
    if (idx >= S_LEN * (D_MODEL / 2)) return;
    int s = idx >> 9;        // / 512 pairs per row
    int p = idx & 511;
    int h = p >> 5;          // head
    int i = p & 31;          // pair index within head (dk=64 -> 32 pairs)

    // inv_freq = 10000^(-(2i)/64), computed in fp64 -> correctly-rounded fp32
    float inv = (float)exp(-(double)i * (1.0 / 32.0) * 9.210340371976184);
    float ang = (float)pos[s] * inv;
    float sn, cs;
    sincosf(ang, &sn, &cs);

    int base = s * D_MODEL + h * HDK + 2 * i;
    float q1 = Q[base], q2 = Q[base + 1];
    Q[base]     = q1 * cs - q2 * sn;
    Q[base + 1] = q1 * sn + q2 * cs;
    float k1 = K[base], k2 = K[base + 1];
    K[base]     = k1 * cs - k2 * sn;
    K[base + 1] = k1 * sn + k2 * cs;
}

// ---------------------------------------------------------------------------
// Flash attention (causal), fp32. 64 queries x 64 keys per block-tile,
// 256 threads, 4x4 micro-tile, online softmax.
// smem: Qt[64][68] (d-major), Kt[64][68] (d-major), Vs[64][64], Ps[64][64]
// ---------------------------------------------------------------------------
#define PADW 68
#define ATTN_SMEM ((64 * PADW * 2 + 64 * 64 * 2) * 4)

__global__ void __launch_bounds__(256, 2)
attn_kernel(const float* __restrict__ Q, const float* __restrict__ K,
            const float* __restrict__ V, float* __restrict__ Out) {
    extern __shared__ float sm[];
    float* Qt = sm;                     // [64][PADW]  Qt[d][m]
    float* Kt = Qt + 64 * PADW;         // [64][PADW]  Kt[d][n]
    float* Vs = Kt + 64 * PADW;         // [64][64]    Vs[n][c]
    float* Ps = Vs + 64 * 64;           // [64][64]

    const int tid = threadIdx.x;
    const int h   = blockIdx.y;
    const int q0  = blockIdx.x * 64;
    const int ty  = tid >> 4, tx = tid & 15;
    const int row = ty << 2, col = tx << 2;

    // Load Q tile transposed into smem, pre-scaled by 1/sqrt(dk) = 0.125
    {
        const int r  = tid >> 2;            // 0..63 (query row)
        const int db = (tid & 3) << 4;      // 0,16,32,48
        const float* src = Q + (q0 + r) * D_MODEL + h * HDK + db;
        #pragma unroll
        for (int v4 = 0; v4 < 4; v4++) {
            float4 a = *(const float4*)(src + v4 * 4);
            int d = db + v4 * 4;
            Qt[(d + 0) * PADW + r] = a.x * 0.125f;
            Qt[(d + 1) * PADW + r] = a.y * 0.125f;
            Qt[(d + 2) * PADW + r] = a.z * 0.125f;
            Qt[(d + 3) * PADW + r] = a.w * 0.125f;
        }
    }

    float o[4][4];
    float m_run[4], l_run[4];
    #pragma unroll
    for (int i = 0; i < 4; i++) {
        m_run[i] = -1e30f; l_run[i] = 0.f;
        #pragma unroll
        for (int j = 0; j < 4; j++) o[i][j] = 0.f;
    }

    const int ntiles = blockIdx.x + 1;  // causal: kv tiles 0..q-tile
    for (int jt = 0; jt < ntiles; jt++) {
        const int n0 = jt * 64;
        __syncthreads();  // previous O-GEMM reads done before overwriting K/V
        {
            const int r  = tid >> 2;
            const int db = (tid & 3) << 4;
            const float* ksrc = K + (n0 + r) * D_MODEL + h * HDK + db;
            const float* vsrc = V + (n0 + r) * D_MODEL + h * HDK + db;
            #pragma unroll
            for (int v4 = 0; v4 < 4; v4++) {
                int d = db + v4 * 4;
                float4 a = *(const float4*)(ksrc + v4 * 4);
                Kt[(d + 0) * PADW + r] = a.x;
                Kt[(d + 1) * PADW + r] = a.y;
                Kt[(d + 2) * PADW + r] = a.z;
                Kt[(d + 3) * PADW + r] = a.w;
                float4 b = *(const float4*)(vsrc + v4 * 4);
                *(float4*)&Vs[r * 64 + d] = b;
            }
        }
        __syncthreads();

        // S = (Q/8) K^T  : 4x4 per thread over d=0..63
        float s[4][4];
        #pragma unroll
        for (int i = 0; i < 4; i++)
            #pragma unroll
            for (int j = 0; j < 4; j++) s[i][j] = 0.f;
        #pragma unroll 8
        for (int d = 0; d < 64; d++) {
            float4 qa = *(const float4*)&Qt[d * PADW + row];
            float4 kb = *(const float4*)&Kt[d * PADW + col];
            float ra[4] = {qa.x, qa.y, qa.z, qa.w};
            float rb[4] = {kb.x, kb.y, kb.z, kb.w};
            #pragma unroll
            for (int i = 0; i < 4; i++)
                #pragma unroll
                for (int j = 0; j < 4; j++)
                    s[i][j] = fmaf(ra[i], rb[j], s[i][j]);
        }

        // Causal mask only matters on the diagonal tile
        if (jt == blockIdx.x) {
            #pragma unroll
            for (int i = 0; i < 4; i++)
                #pragma unroll
                for (int j = 0; j < 4; j++)
                    if (col + j > row + i) s[i][j] = -1e30f;
        }

        // Online softmax: per row (replicated over the 16 tx lanes)
        #pragma unroll
        for (int i = 0; i < 4; i++) {
            float mx = fmaxf(fmaxf(s[i][0], s[i][1]), fmaxf(s[i][2], s[i][3]));
            mx = fmaxf(mx, __shfl_xor_sync(0xffffffffu, mx, 1));
            mx = fmaxf(mx, __shfl_xor_sync(0xffffffffu, mx, 2));
            mx = fmaxf(mx, __shfl_xor_sync(0xffffffffu, mx, 4));
            mx = fmaxf(mx, __shfl_xor_sync(0xffffffffu, mx, 8));
            float m_new = fmaxf(m_run[i], mx);
            float corr  = __expf(m_run[i] - m_new);
            float sum = 0.f;
            #pragma unroll
            for (int j = 0; j < 4; j++) {
                float pv = __expf(s[i][j] - m_new);
                s[i][j] = pv;
                sum += pv;
            }
            sum += __shfl_xor_sync(0xffffffffu, sum, 1);
            sum += __shfl_xor_sync(0xffffffffu, sum, 2);
            sum += __shfl_xor_sync(0xffffffffu, sum, 4);
            sum += __shfl_xor_sync(0xffffffffu, sum, 8);
            l_run[i] = l_run[i] * corr + sum;
            m_run[i] = m_new;
            #pragma unroll
            for (int j = 0; j < 4; j++) o[i][j] *= corr;
            *(float4*)&Ps[(row + i) * 64 + col] =
                make_float4(s[i][0], s[i][1], s[i][2], s[i][3]);
        }
        __syncthreads();

        // O += P * V
        #pragma unroll 4
        for (int n = 0; n < 64; n++) {
            float4 v = *(const float4*)&Vs[n * 64 + col];
            #pragma unroll
            for (int i = 0; i < 4; i++) {
                float pv = Ps[(row + i) * 64 + n];
                o[i][0] = fmaf(pv, v.x, o[i][0]);
                o[i][1] = fmaf(pv, v.y, o[i][1]);
                o[i][2] = fmaf(pv, v.z, o[i][2]);
                o[i][3] = fmaf(pv, v.w, o[i][3]);
            }
        }
    }

    // Epilogue: normalize and write attn[s, h*64 + c]
    #pragma unroll
    for (int i = 0; i < 4; i++) {
        float inv = 1.f / l_run[i];
        float4 v = make_float4(o[i][0] * inv, o[i][1] * inv,
                               o[i][2] * inv, o[i][3] * inv);
        *(float4*)(Out + (q0 + row + i) * D_MODEL + h * HDK + col) = v;
    }
}

// ---------------------------------------------------------------------------
extern "C" void kernel_launch(void* const* d_in, const int* in_sizes, int n_in,
                              void* d_out, int out_size) {
    const float* x   = (const float*)d_in[0];
    const int*   pos = (const int*)d_in[1];
    const float* Wq  = (const float*)d_in[2];
    const float* Wk  = (const float*)d_in[3];
    const float* Wv  = (const float*)d_in[4];
    const float* Wo  = (const float*)d_in[5];
    float* out = (float*)d_out;

    float *qp, *kp, *vp, *ap;
    cudaGetSymbolAddress((void**)&qp, g_Q);
    cudaGetSymbolAddress((void**)&kp, g_K);
    cudaGetSymbolAddress((void**)&vp, g_V);
    cudaGetSymbolAddress((void**)&ap, g_A);

    cudaFuncSetAttribute(attn_kernel,
                         cudaFuncAttributeMaxDynamicSharedMemorySize, ATTN_SMEM);

    dim3 gproj(D_MODEL / 128, S_LEN / 128);   // (8, 32)
    gemm_nt<S_LEN, D_MODEL, D_MODEL><<<gproj, 256>>>(x, Wq, qp);
    gemm_nt<S_LEN, D_MODEL, D_MODEL><<<gproj, 256>>>(x, Wk, kp);
    gemm_nt<S_LEN, D_MODEL, D_MODEL><<<gproj, 256>>>(x, Wv, vp);

    int npairs = S_LEN * (D_MODEL / 2);
    rope_kernel<<<(npairs + 255) / 256, 256>>>(qp, kp, pos);

    dim3 gattn(S_LEN / 64, NHEAD);            // (64, 16)
    attn_kernel<<<gattn, 256, ATTN_SMEM>>>(qp, kp, vp, ap);

    gemm_nt<S_LEN, D_MODEL, D_MODEL><<<gproj, 256>>>(ap, Wo, out);
}

// round 6
// speedup vs baseline: 1.3359x; 1.3359x over previous
#include <cuda_runtime.h>
#include <cuda_bf16.h>
#include <stdint.h>
#include <math.h>

#define S_LEN 4096
#define D_MODEL 1024
#define NHEAD 16
#define HDK 64

// ---------------------------------------------------------------------------
// Scratch (__device__ globals; allocation-free rule)
// ---------------------------------------------------------------------------
__device__ float g_Q[S_LEN * D_MODEL];
__device__ float g_K[S_LEN * D_MODEL];
__device__ float g_V[S_LEN * D_MODEL];
__device__ float g_A[S_LEN * D_MODEL];

__device__ __nv_bfloat16 g_xh[S_LEN * D_MODEL];
__device__ __nv_bfloat16 g_xl[S_LEN * D_MODEL];
__device__ __nv_bfloat16 g_ah[S_LEN * D_MODEL];
__device__ __nv_bfloat16 g_al[S_LEN * D_MODEL];
__device__ __nv_bfloat16 g_wqh[D_MODEL * D_MODEL];
__device__ __nv_bfloat16 g_wql[D_MODEL * D_MODEL];
__device__ __nv_bfloat16 g_wkh[D_MODEL * D_MODEL];
__device__ __nv_bfloat16 g_wkl[D_MODEL * D_MODEL];
__device__ __nv_bfloat16 g_wvh[D_MODEL * D_MODEL];
__device__ __nv_bfloat16 g_wvl[D_MODEL * D_MODEL];
__device__ __nv_bfloat16 g_woh[D_MODEL * D_MODEL];
__device__ __nv_bfloat16 g_wol[D_MODEL * D_MODEL];

// ---------------------------------------------------------------------------
// Portable (sm_80+) tensor-core primitives: ldmatrix + mma.sync + cp.async
// ---------------------------------------------------------------------------
__device__ __forceinline__ uint32_t smem_u32(const void* p) {
    uint32_t a;
    asm("{ .reg .u64 t; cvta.to.shared.u64 t, %1; cvt.u32.u64 %0, t; }"
        : "=r"(a) : "l"(p));
    return a;
}

__device__ __forceinline__ void ldsm4(uint32_t* r, uint32_t addr) {
    asm volatile("ldmatrix.sync.aligned.m8n8.x4.shared.b16 {%0,%1,%2,%3}, [%4];"
        : "=r"(r[0]), "=r"(r[1]), "=r"(r[2]), "=r"(r[3]) : "r"(addr));
}

__device__ __forceinline__ void mma16816(float* d, const uint32_t* a, const uint32_t* b) {
    asm volatile(
        "mma.sync.aligned.m16n8k16.row.col.f32.bf16.bf16.f32 "
        "{%0,%1,%2,%3}, {%4,%5,%6,%7}, {%8,%9}, {%0,%1,%2,%3};"
        : "+f"(d[0]), "+f"(d[1]), "+f"(d[2]), "+f"(d[3])
        : "r"(a[0]), "r"(a[1]), "r"(a[2]), "r"(a[3]), "r"(b[0]), "r"(b[1]));
}

#define CP_ASYNC16(sa, ga) \
    asm volatile("cp.async.cg.shared.global [%0], [%1], 16;" :: "r"(sa), "l"(ga))
#define CP_COMMIT()  asm volatile("cp.async.commit_group;")
#define CP_WAIT(N)   asm volatile("cp.async.wait_group %0;" :: "n"(N))

// ---------------------------------------------------------------------------
// fp32 -> bf16 hi/lo split (two-term representation for bf16x3 GEMM)
// ---------------------------------------------------------------------------
__global__ void split_bf16(const float* __restrict__ in,
                           __nv_bfloat16* __restrict__ hi,
                           __nv_bfloat16* __restrict__ lo, int n) {
    int i = (blockIdx.x * blockDim.x + threadIdx.x) * 4;
    if (i >= n) return;
    float4 v = *(const float4*)(in + i);
    __nv_bfloat16 h0 = __float2bfloat16(v.x);
    __nv_bfloat16 h1 = __float2bfloat16(v.y);
    __nv_bfloat16 h2 = __float2bfloat16(v.z);
    __nv_bfloat16 h3 = __float2bfloat16(v.w);
    __nv_bfloat162 hp0 = {h0, h1}, hp1 = {h2, h3};
    *(__nv_bfloat162*)(hi + i)     = hp0;
    *(__nv_bfloat162*)(hi + i + 2) = hp1;
    __nv_bfloat162 lp0 = {__float2bfloat16(v.x - __bfloat162float(h0)),
                          __float2bfloat16(v.y - __bfloat162float(h1))};
    __nv_bfloat162 lp1 = {__float2bfloat16(v.z - __bfloat162float(h2)),
                          __float2bfloat16(v.w - __bfloat162float(h3))};
    *(__nv_bfloat162*)(lo + i)     = lp0;
    *(__nv_bfloat162*)(lo + i + 2) = lp1;
}

// ---------------------------------------------------------------------------
// bf16x3 GEMM via mma.sync: C[M,N] = A[M,K]*B[N,K]^T, fp32 accum.
// 128x128x32 CTA tile, 256 threads, warps 2m x 4n (64x32 each).
// Double-buffered cp.async; smem rows of 64B with XOR-4 quad swizzle.
// ---------------------------------------------------------------------------
#define GK       1024
#define BK       32
#define NKC      (GK / BK)         // 32
#define TILE8KB  8192              // one 128x32 bf16 tile
#define STAGE_B  (4 * TILE8KB)     // Ah, Al, Bh, Bl
#define GSMEM    (2 * STAGE_B)     // 64 KB

__global__ void __launch_bounds__(256, 1)
gemm_bf16x3(const __nv_bfloat16* __restrict__ Ah, const __nv_bfloat16* __restrict__ Al,
            const __nv_bfloat16* __restrict__ Bh, const __nv_bfloat16* __restrict__ Bl,
            float* __restrict__ C) {
    extern __shared__ char sm[];
    const int tid  = threadIdx.x;
    const int lane = tid & 31;
    const int warp = tid >> 5;
    const int wm   = warp & 1;          // 0..1
    const int wn   = warp >> 1;         // 0..3
    const int bm   = blockIdx.y * 128;
    const int bn   = blockIdx.x * 128;

    const __nv_bfloat16* srcs[4] = {Ah, Al, Bh, Bl};

    // Stage loader: 4 tiles x 512 quads(16B); 2 quads per thread per tile.
    auto load_stage = [&](int kt, int buf) {
        const int koff = kt * BK;
        char* sbase = sm + buf * STAGE_B;
        #pragma unroll
        for (int mtx = 0; mtx < 4; mtx++) {
            const __nv_bfloat16* src = srcs[mtx];
            const int rbase = (mtx < 2) ? bm : bn;
            char* stile = sbase + mtx * TILE8KB;
            #pragma unroll
            for (int j = 0; j < 2; j++) {
                int qi  = tid + j * 256;
                int row = qi >> 2, q = qi & 3;
                int pq  = q ^ (row & 3);
                uint32_t sa = smem_u32(stile + row * 64 + pq * 16);
                const void* ga = src + (size_t)(rbase + row) * GK + koff + q * 8;
                CP_ASYNC16(sa, ga);
            }
        }
    };

    float d[4][4][4];
    #pragma unroll
    for (int i = 0; i < 4; i++)
        #pragma unroll
        for (int j = 0; j < 4; j++)
            #pragma unroll
            for (int k = 0; k < 4; k++) d[i][j][k] = 0.f;

    load_stage(0, 0);
    CP_COMMIT();

    // ldmatrix lane addressing (constant per thread)
    const int a_row = lane & 15;          // row within 16-row frag
    const int a_qs  = lane >> 4;          // 0/1: k-halves
    const int b_row = ((lane >> 4) & 1) * 8 + (lane & 7);   // n within 16
    const int b_qs  = (lane >> 3) & 1;    // 0/1: k-halves

    for (int kt = 0; kt < NKC; kt++) {
        if (kt + 1 < NKC) { load_stage(kt + 1, (kt + 1) & 1); CP_COMMIT(); CP_WAIT(1); }
        else              { CP_WAIT(0); }
        __syncthreads();

        char* sbase = sm + (kt & 1) * STAGE_B;
        char* tAh = sbase + 0 * TILE8KB;
        char* tAl = sbase + 1 * TILE8KB;
        char* tBh = sbase + 2 * TILE8KB;
        char* tBl = sbase + 3 * TILE8KB;

        #pragma unroll
        for (int ks = 0; ks < 2; ks++) {        // two k16 steps per BK=32
            uint32_t ah[4][4], al[4][4], bh[4][2], bl[4][2];
            #pragma unroll
            for (int mi = 0; mi < 4; mi++) {
                int row = wm * 64 + mi * 16 + a_row;
                int pq  = (ks * 2 + a_qs) ^ (row & 3);
                ldsm4(ah[mi], smem_u32(tAh + row * 64 + pq * 16));
                ldsm4(al[mi], smem_u32(tAl + row * 64 + pq * 16));
            }
            #pragma unroll
            for (int gi = 0; gi < 2; gi++) {    // each covers 2 n-frags
                int row = wn * 32 + gi * 16 + b_row;
                int pq  = (ks * 2 + b_qs) ^ (row & 3);
                uint32_t rh[4], rl[4];
                ldsm4(rh, smem_u32(tBh + row * 64 + pq * 16));
                ldsm4(rl, smem_u32(tBl + row * 64 + pq * 16));
                bh[gi * 2 + 0][0] = rh[0]; bh[gi * 2 + 0][1] = rh[1];
                bh[gi * 2 + 1][0] = rh[2]; bh[gi * 2 + 1][1] = rh[3];
                bl[gi * 2 + 0][0] = rl[0]; bl[gi * 2 + 0][1] = rl[1];
                bl[gi * 2 + 1][0] = rl[2]; bl[gi * 2 + 1][1] = rl[3];
            }
            #pragma unroll
            for (int mi = 0; mi < 4; mi++)
                #pragma unroll
                for (int ni = 0; ni < 4; ni++) {
                    mma16816(d[mi][ni], ah[mi], bh[ni]);
                    mma16816(d[mi][ni], ah[mi], bl[ni]);
                    mma16816(d[mi][ni], al[mi], bh[ni]);
                }
        }
        __syncthreads();
    }

    // Epilogue: fragment layout -> C
    const int er = lane >> 2;             // 0..7
    const int ec = (lane & 3) * 2;        // 0,2,4,6
    #pragma unroll
    for (int mi = 0; mi < 4; mi++) {
        int r0 = bm + wm * 64 + mi * 16 + er;
        #pragma unroll
        for (int ni = 0; ni < 4; ni++) {
            int c0 = bn + wn * 32 + ni * 8 + ec;
            *(float2*)(C + (size_t)r0 * D_MODEL + c0)       = make_float2(d[mi][ni][0], d[mi][ni][1]);
            *(float2*)(C + (size_t)(r0 + 8) * D_MODEL + c0) = make_float2(d[mi][ni][2], d[mi][ni][3]);
        }
    }
}

// ---------------------------------------------------------------------------
// RoPE applied in-place to Q and K.
// ---------------------------------------------------------------------------
__global__ void rope_kernel(float* __restrict__ Q, float* __restrict__ K,
                            const int* __restrict__ pos) {
    int idx = blockIdx.x * blockDim.x + threadIdx.x;
    if (idx >= S_LEN * (D_MODEL / 2)) return;
    int s = idx >> 9;
    int p = idx & 511;
    int h = p >> 5;
    int i = p & 31;

    float inv = (float)exp(-(double)i * (1.0 / 32.0) * 9.210340371976184);
    float ang = (float)pos[s] * inv;
    float sn, cs;
    sincosf(ang, &sn, &cs);

    int base = s * D_MODEL + h * HDK + 2 * i;
    float q1 = Q[base], q2 = Q[base + 1];
    Q[base]     = q1 * cs - q2 * sn;
    Q[base + 1] = q1 * sn + q2 * cs;
    float k1 = K[base], k2 = K[base + 1];
    K[base]     = k1 * cs - k2 * sn;
    K[base + 1] = k1 * sn + k2 * cs;
}

// ---------------------------------------------------------------------------
// Flash attention (causal), fp32 SIMT. 64q x 64kv tiles, 256 threads.
// ---------------------------------------------------------------------------
#define PADW 68
#define ATTN_SMEM ((64 * PADW * 2 + 64 * 64 * 2) * 4)

__global__ void __launch_bounds__(256, 2)
attn_kernel(const float* __restrict__ Q, const float* __restrict__ K,
            const float* __restrict__ V, float* __restrict__ Out) {
    extern __shared__ float smf[];
    float* Qt = smf;
    float* Kt = Qt + 64 * PADW;
    float* Vs = Kt + 64 * PADW;
    float* Ps = Vs + 64 * 64;

    const int tid = threadIdx.x;
    const int h   = blockIdx.y;
    const int q0  = blockIdx.x * 64;
    const int ty  = tid >> 4, tx = tid & 15;
    const int row = ty << 2, col = tx << 2;

    {
        const int r  = tid >> 2;
        const int db = (tid & 3) << 4;
        const float* src = Q + (q0 + r) * D_MODEL + h * HDK + db;
        #pragma unroll
        for (int v4 = 0; v4 < 4; v4++) {
            float4 a = *(const float4*)(src + v4 * 4);
            int d = db + v4 * 4;
            Qt[(d + 0) * PADW + r] = a.x * 0.125f;
            Qt[(d + 1) * PADW + r] = a.y * 0.125f;
            Qt[(d + 2) * PADW + r] = a.z * 0.125f;
            Qt[(d + 3) * PADW + r] = a.w * 0.125f;
        }
    }

    float o[4][4];
    float m_run[4], l_run[4];
    #pragma unroll
    for (int i = 0; i < 4; i++) {
        m_run[i] = -1e30f; l_run[i] = 0.f;
        #pragma unroll
        for (int j = 0; j < 4; j++) o[i][j] = 0.f;
    }

    const int ntiles = blockIdx.x + 1;
    for (int jt = 0; jt < ntiles; jt++) {
        const int n0 = jt * 64;
        __syncthreads();
        {
            const int r  = tid >> 2;
            const int db = (tid & 3) << 4;
            const float* ksrc = K + (n0 + r) * D_MODEL + h * HDK + db;
            const float* vsrc = V + (n0 + r) * D_MODEL + h * HDK + db;
            #pragma unroll
            for (int v4 = 0; v4 < 4; v4++) {
                int d = db + v4 * 4;
                float4 a = *(const float4*)(ksrc + v4 * 4);
                Kt[(d + 0) * PADW + r] = a.x;
                Kt[(d + 1) * PADW + r] = a.y;
                Kt[(d + 2) * PADW + r] = a.z;
                Kt[(d + 3) * PADW + r] = a.w;
                float4 b = *(const float4*)(vsrc + v4 * 4);
                *(float4*)&Vs[r * 64 + d] = b;
            }
        }
        __syncthreads();

        float s[4][4];
        #pragma unroll
        for (int i = 0; i < 4; i++)
            #pragma unroll
            for (int j = 0; j < 4; j++) s[i][j] = 0.f;
        #pragma unroll 8
        for (int d = 0; d < 64; d++) {
            float4 qa = *(const float4*)&Qt[d * PADW + row];
            float4 kb = *(const float4*)&Kt[d * PADW + col];
            float ra[4] = {qa.x, qa.y, qa.z, qa.w};
            float rb[4] = {kb.x, kb.y, kb.z, kb.w};
            #pragma unroll
            for (int i = 0; i < 4; i++)
                #pragma unroll
                for (int j = 0; j < 4; j++)
                    s[i][j] = fmaf(ra[i], rb[j], s[i][j]);
        }

        if (jt == blockIdx.x) {
            #pragma unroll
            for (int i = 0; i < 4; i++)
                #pragma unroll
                for (int j = 0; j < 4; j++)
                    if (col + j > row + i) s[i][j] = -1e30f;
        }

        #pragma unroll
        for (int i = 0; i < 4; i++) {
            float mx = fmaxf(fmaxf(s[i][0], s[i][1]), fmaxf(s[i][2], s[i][3]));
            mx = fmaxf(mx, __shfl_xor_sync(0xffffffffu, mx, 1));
            mx = fmaxf(mx, __shfl_xor_sync(0xffffffffu, mx, 2));
            mx = fmaxf(mx, __shfl_xor_sync(0xffffffffu, mx, 4));
            mx = fmaxf(mx, __shfl_xor_sync(0xffffffffu, mx, 8));
            float m_new = fmaxf(m_run[i], mx);
            float corr  = __expf(m_run[i] - m_new);
            float sum = 0.f;
            #pragma unroll
            for (int j = 0; j < 4; j++) {
                float pv = __expf(s[i][j] - m_new);
                s[i][j] = pv;
                sum += pv;
            }
            sum += __shfl_xor_sync(0xffffffffu, sum, 1);
            sum += __shfl_xor_sync(0xffffffffu, sum, 2);
            sum += __shfl_xor_sync(0xffffffffu, sum, 4);
            sum += __shfl_xor_sync(0xffffffffu, sum, 8);
            l_run[i] = l_run[i] * corr + sum;
            m_run[i] = m_new;
            #pragma unroll
            for (int j = 0; j < 4; j++) o[i][j] *= corr;
            *(float4*)&Ps[(row + i) * 64 + col] =
                make_float4(s[i][0], s[i][1], s[i][2], s[i][3]);
        }
        __syncthreads();

        #pragma unroll 4
        for (int n = 0; n < 64; n++) {
            float4 v = *(const float4*)&Vs[n * 64 + col];
            #pragma unroll
            for (int i = 0; i < 4; i++) {
                float pv = Ps[(row + i) * 64 + n];
                o[i][0] = fmaf(pv, v.x, o[i][0]);
                o[i][1] = fmaf(pv, v.y, o[i][1]);
                o[i][2] = fmaf(pv, v.z, o[i][2]);
                o[i][3] = fmaf(pv, v.w, o[i][3]);
            }
        }
    }

    #pragma unroll
    for (int i = 0; i < 4; i++) {
        float inv = 1.f / l_run[i];
        float4 v = make_float4(o[i][0] * inv, o[i][1] * inv,
                               o[i][2] * inv, o[i][3] * inv);
        *(float4*)(Out + (q0 + row + i) * D_MODEL + h * HDK + col) = v;
    }
}

// ---------------------------------------------------------------------------
extern "C" void kernel_launch(void* const* d_in, const int* in_sizes, int n_in,
                              void* d_out, int out_size) {
    const float* x   = (const float*)d_in[0];
    const int*   pos = (const int*)d_in[1];
    const float* Wq  = (const float*)d_in[2];
    const float* Wk  = (const float*)d_in[3];
    const float* Wv  = (const float*)d_in[4];
    const float* Wo  = (const float*)d_in[5];
    float* out = (float*)d_out;

    float *qp, *kp, *vp, *ap;
    cudaGetSymbolAddress((void**)&qp, g_Q);
    cudaGetSymbolAddress((void**)&kp, g_K);
    cudaGetSymbolAddress((void**)&vp, g_V);
    cudaGetSymbolAddress((void**)&ap, g_A);

    __nv_bfloat16 *xh, *xl, *ah, *al;
    __nv_bfloat16 *wqh, *wql, *wkh, *wkl, *wvh, *wvl, *woh, *wol;
    cudaGetSymbolAddress((void**)&xh, g_xh);   cudaGetSymbolAddress((void**)&xl, g_xl);
    cudaGetSymbolAddress((void**)&ah, g_ah);   cudaGetSymbolAddress((void**)&al, g_al);
    cudaGetSymbolAddress((void**)&wqh, g_wqh); cudaGetSymbolAddress((void**)&wql, g_wql);
    cudaGetSymbolAddress((void**)&wkh, g_wkh); cudaGetSymbolAddress((void**)&wkl, g_wkl);
    cudaGetSymbolAddress((void**)&wvh, g_wvh); cudaGetSymbolAddress((void**)&wvl, g_wvl);
    cudaGetSymbolAddress((void**)&woh, g_woh); cudaGetSymbolAddress((void**)&wol, g_wol);

    cudaFuncSetAttribute(attn_kernel,
                         cudaFuncAttributeMaxDynamicSharedMemorySize, ATTN_SMEM);
    cudaFuncSetAttribute(gemm_bf16x3,
                         cudaFuncAttributeMaxDynamicSharedMemorySize, GSMEM);

    const int nx = S_LEN * D_MODEL;     // 4.19M
    const int nw = D_MODEL * D_MODEL;   // 1.05M
    split_bf16<<<nx / 1024, 256>>>(x,  xh,  xl,  nx);
    split_bf16<<<nw / 1024, 256>>>(Wq, wqh, wql, nw);
    split_bf16<<<nw / 1024, 256>>>(Wk, wkh, wkl, nw);
    split_bf16<<<nw / 1024, 256>>>(Wv, wvh, wvl, nw);
    split_bf16<<<nw / 1024, 256>>>(Wo, woh, wol, nw);

    dim3 gproj(D_MODEL / 128, S_LEN / 128);   // (8, 32)
    gemm_bf16x3<<<gproj, 256, GSMEM>>>(xh, xl, wqh, wql, qp);
    gemm_bf16x3<<<gproj, 256, GSMEM>>>(xh, xl, wkh, wkl, kp);
    gemm_bf16x3<<<gproj, 256, GSMEM>>>(xh, xl, wvh, wvl, vp);

    int npairs = S_LEN * (D_MODEL / 2);
    rope_kernel<<<(npairs + 255) / 256, 256>>>(qp, kp, pos);

    dim3 gattn(S_LEN / 64, NHEAD);            // (64, 16)
    attn_kernel<<<gattn, 256, ATTN_SMEM>>>(qp, kp, vp, ap);

    split_bf16<<<nx / 1024, 256>>>(ap, ah, al, nx);
    gemm_bf16x3<<<gproj, 256, GSMEM>>>(ah, al, woh, wol, out);
}

// round 7
// speedup vs baseline: 2.9789x; 2.2300x over previous
#include <cuda_runtime.h>
#include <cuda_bf16.h>
#include <stdint.h>
#include <math.h>

#define S_LEN 4096
#define D_MODEL 1024
#define NHEAD 16
#define HDK 64

// ---------------------------------------------------------------------------
// Scratch (__device__ globals; allocation-free rule)
// ---------------------------------------------------------------------------
__device__ float g_Q[S_LEN * D_MODEL];
__device__ float g_K[S_LEN * D_MODEL];
__device__ float g_V[S_LEN * D_MODEL];

__device__ __nv_bfloat16 g_xh[S_LEN * D_MODEL];
__device__ __nv_bfloat16 g_xl[S_LEN * D_MODEL];
__device__ __nv_bfloat16 g_ah[S_LEN * D_MODEL];
__device__ __nv_bfloat16 g_al[S_LEN * D_MODEL];
__device__ __nv_bfloat16 g_qh[S_LEN * D_MODEL];
__device__ __nv_bfloat16 g_ql[S_LEN * D_MODEL];
__device__ __nv_bfloat16 g_kh[S_LEN * D_MODEL];
__device__ __nv_bfloat16 g_kl[S_LEN * D_MODEL];
__device__ __nv_bfloat16 g_vh[S_LEN * D_MODEL];
__device__ __nv_bfloat16 g_vl[S_LEN * D_MODEL];
__device__ __nv_bfloat16 g_wqh[D_MODEL * D_MODEL];
__device__ __nv_bfloat16 g_wql[D_MODEL * D_MODEL];
__device__ __nv_bfloat16 g_wkh[D_MODEL * D_MODEL];
__device__ __nv_bfloat16 g_wkl[D_MODEL * D_MODEL];
__device__ __nv_bfloat16 g_wvh[D_MODEL * D_MODEL];
__device__ __nv_bfloat16 g_wvl[D_MODEL * D_MODEL];
__device__ __nv_bfloat16 g_woh[D_MODEL * D_MODEL];
__device__ __nv_bfloat16 g_wol[D_MODEL * D_MODEL];

// ---------------------------------------------------------------------------
// Portable (sm_80+) tensor-core primitives
// ---------------------------------------------------------------------------
__device__ __forceinline__ uint32_t smem_u32(const void* p) {
    uint32_t a;
    asm("{ .reg .u64 t; cvta.to.shared.u64 t, %1; cvt.u32.u64 %0, t; }"
        : "=r"(a) : "l"(p));
    return a;
}

__device__ __forceinline__ void ldsm4(uint32_t* r, uint32_t addr) {
    asm volatile("ldmatrix.sync.aligned.m8n8.x4.shared.b16 {%0,%1,%2,%3}, [%4];"
        : "=r"(r[0]), "=r"(r[1]), "=r"(r[2]), "=r"(r[3]) : "r"(addr));
}

__device__ __forceinline__ void ldsm4t(uint32_t* r, uint32_t addr) {
    asm volatile("ldmatrix.sync.aligned.m8n8.x4.trans.shared.b16 {%0,%1,%2,%3}, [%4];"
        : "=r"(r[0]), "=r"(r[1]), "=r"(r[2]), "=r"(r[3]) : "r"(addr));
}

__device__ __forceinline__ void mma16816(float* d, const uint32_t* a, const uint32_t* b) {
    asm volatile(
        "mma.sync.aligned.m16n8k16.row.col.f32.bf16.bf16.f32 "
        "{%0,%1,%2,%3}, {%4,%5,%6,%7}, {%8,%9}, {%0,%1,%2,%3};"
        : "+f"(d[0]), "+f"(d[1]), "+f"(d[2]), "+f"(d[3])
        : "r"(a[0]), "r"(a[1]), "r"(a[2]), "r"(a[3]), "r"(b[0]), "r"(b[1]));
}

#define CP_ASYNC16(sa, ga) \
    asm volatile("cp.async.cg.shared.global [%0], [%1], 16;" :: "r"(sa), "l"(ga))
#define CP_COMMIT()  asm volatile("cp.async.commit_group;")
#define CP_WAIT(N)   asm volatile("cp.async.wait_group %0;" :: "n"(N))

// split a float pair into packed bf16x2 hi + lo residual
__device__ __forceinline__ void split2(float a, float b, uint32_t& hi, uint32_t& lo) {
    __nv_bfloat16 ha = __float2bfloat16(a), hb = __float2bfloat16(b);
    __nv_bfloat162 hv; hv.x = ha; hv.y = hb;
    hi = *reinterpret_cast<uint32_t*>(&hv);
    __nv_bfloat162 lv;
    lv.x = __float2bfloat16(a - __bfloat162float(ha));
    lv.y = __float2bfloat16(b - __bfloat162float(hb));
    lo = *reinterpret_cast<uint32_t*>(&lv);
}

// ---------------------------------------------------------------------------
// fp32 -> bf16 hi/lo split
// ---------------------------------------------------------------------------
__global__ void split_bf16(const float* __restrict__ in,
                           __nv_bfloat16* __restrict__ hi,
                           __nv_bfloat16* __restrict__ lo, int n) {
    int i = (blockIdx.x * blockDim.x + threadIdx.x) * 4;
    if (i >= n) return;
    float4 v = *(const float4*)(in + i);
    uint32_t h0, l0, h1, l1;
    split2(v.x, v.y, h0, l0);
    split2(v.z, v.w, h1, l1);
    *(uint32_t*)(hi + i)     = h0;  *(uint32_t*)(hi + i + 2) = h1;
    *(uint32_t*)(lo + i)     = l0;  *(uint32_t*)(lo + i + 2) = l1;
}

// ---------------------------------------------------------------------------
// bf16x3 GEMM via mma.sync (unchanged from R6 WIN)
// ---------------------------------------------------------------------------
#define GK       1024
#define BK       32
#define NKC      (GK / BK)
#define TILE8KB  8192
#define STAGE_B  (4 * TILE8KB)
#define GSMEM    (2 * STAGE_B)

__global__ void __launch_bounds__(256, 1)
gemm_bf16x3(const __nv_bfloat16* __restrict__ Ah, const __nv_bfloat16* __restrict__ Al,
            const __nv_bfloat16* __restrict__ Bh, const __nv_bfloat16* __restrict__ Bl,
            float* __restrict__ C) {
    extern __shared__ char sm[];
    const int tid  = threadIdx.x;
    const int lane = tid & 31;
    const int warp = tid >> 5;
    const int wm   = warp & 1;
    const int wn   = warp >> 1;
    const int bm   = blockIdx.y * 128;
    const int bn   = blockIdx.x * 128;

    const __nv_bfloat16* srcs[4] = {Ah, Al, Bh, Bl};

    auto load_stage = [&](int kt, int buf) {
        const int koff = kt * BK;
        char* sbase = sm + buf * STAGE_B;
        #pragma unroll
        for (int mtx = 0; mtx < 4; mtx++) {
            const __nv_bfloat16* src = srcs[mtx];
            const int rbase = (mtx < 2) ? bm : bn;
            char* stile = sbase + mtx * TILE8KB;
            #pragma unroll
            for (int j = 0; j < 2; j++) {
                int qi  = tid + j * 256;
                int row = qi >> 2, q = qi & 3;
                int pq  = q ^ (row & 3);
                uint32_t sa = smem_u32(stile + row * 64 + pq * 16);
                const void* ga = src + (size_t)(rbase + row) * GK + koff + q * 8;
                CP_ASYNC16(sa, ga);
            }
        }
    };

    float d[4][4][4];
    #pragma unroll
    for (int i = 0; i < 4; i++)
        #pragma unroll
        for (int j = 0; j < 4; j++)
            #pragma unroll
            for (int k = 0; k < 4; k++) d[i][j][k] = 0.f;

    load_stage(0, 0);
    CP_COMMIT();

    const int a_row = lane & 15;
    const int a_qs  = lane >> 4;
    const int b_row = ((lane >> 4) & 1) * 8 + (lane & 7);
    const int b_qs  = (lane >> 3) & 1;

    for (int kt = 0; kt < NKC; kt++) {
        if (kt + 1 < NKC) { load_stage(kt + 1, (kt + 1) & 1); CP_COMMIT(); CP_WAIT(1); }
        else              { CP_WAIT(0); }
        __syncthreads();

        char* sbase = sm + (kt & 1) * STAGE_B;
        char* tAh = sbase + 0 * TILE8KB;
        char* tAl = sbase + 1 * TILE8KB;
        char* tBh = sbase + 2 * TILE8KB;
        char* tBl = sbase + 3 * TILE8KB;

        #pragma unroll
        for (int ks = 0; ks < 2; ks++) {
            uint32_t ah[4][4], al[4][4], bh[4][2], bl[4][2];
            #pragma unroll
            for (int mi = 0; mi < 4; mi++) {
                int row = wm * 64 + mi * 16 + a_row;
                int pq  = (ks * 2 + a_qs) ^ (row & 3);
                ldsm4(ah[mi], smem_u32(tAh + row * 64 + pq * 16));
                ldsm4(al[mi], smem_u32(tAl + row * 64 + pq * 16));
            }
            #pragma unroll
            for (int gi = 0; gi < 2; gi++) {
                int row = wn * 32 + gi * 16 + b_row;
                int pq  = (ks * 2 + b_qs) ^ (row & 3);
                uint32_t rh[4], rl[4];
                ldsm4(rh, smem_u32(tBh + row * 64 + pq * 16));
                ldsm4(rl, smem_u32(tBl + row * 64 + pq * 16));
                bh[gi * 2 + 0][0] = rh[0]; bh[gi * 2 + 0][1] = rh[1];
                bh[gi * 2 + 1][0] = rh[2]; bh[gi * 2 + 1][1] = rh[3];
                bl[gi * 2 + 0][0] = rl[0]; bl[gi * 2 + 0][1] = rl[1];
                bl[gi * 2 + 1][0] = rl[2]; bl[gi * 2 + 1][1] = rl[3];
            }
            #pragma unroll
            for (int mi = 0; mi < 4; mi++)
                #pragma unroll
                for (int ni = 0; ni < 4; ni++) {
                    mma16816(d[mi][ni], ah[mi], bh[ni]);
                    mma16816(d[mi][ni], ah[mi], bl[ni]);
                    mma16816(d[mi][ni], al[mi], bh[ni]);
                }
        }
        __syncthreads();
    }

    const int er = lane >> 2;
    const int ec = (lane & 3) * 2;
    #pragma unroll
    for (int mi = 0; mi < 4; mi++) {
        int r0 = bm + wm * 64 + mi * 16 + er;
        #pragma unroll
        for (int ni = 0; ni < 4; ni++) {
            int c0 = bn + wn * 32 + ni * 8 + ec;
            *(float2*)(C + (size_t)r0 * D_MODEL + c0)       = make_float2(d[mi][ni][0], d[mi][ni][1]);
            *(float2*)(C + (size_t)(r0 + 8) * D_MODEL + c0) = make_float2(d[mi][ni][2], d[mi][ni][3]);
        }
    }
}

// ---------------------------------------------------------------------------
// RoPE fused with bf16 hi/lo split. Q pre-scaled by 1/sqrt(dk)=0.125.
// ---------------------------------------------------------------------------
__global__ void rope_split(const float* __restrict__ Q, const float* __restrict__ K,
                           const int* __restrict__ pos,
                           __nv_bfloat16* __restrict__ qh, __nv_bfloat16* __restrict__ ql,
                           __nv_bfloat16* __restrict__ kh, __nv_bfloat16* __restrict__ kl) {
    int idx = blockIdx.x * blockDim.x + threadIdx.x;
    if (idx >= S_LEN * (D_MODEL / 2)) return;
    int s = idx >> 9;
    int p = idx & 511;
    int h = p >> 5;
    int i = p & 31;

    float inv = (float)exp(-(double)i * (1.0 / 32.0) * 9.210340371976184);
    float ang = (float)pos[s] * inv;
    float sn, cs;
    sincosf(ang, &sn, &cs);

    int base = s * D_MODEL + h * HDK + 2 * i;
    float q1 = Q[base], q2 = Q[base + 1];
    float qe = (q1 * cs - q2 * sn) * 0.125f;
    float qo = (q1 * sn + q2 * cs) * 0.125f;
    uint32_t hw, lw;
    split2(qe, qo, hw, lw);
    *(uint32_t*)(qh + base) = hw;
    *(uint32_t*)(ql + base) = lw;

    float k1 = K[base], k2 = K[base + 1];
    float ke = k1 * cs - k2 * sn;
    float ko = k1 * sn + k2 * cs;
    split2(ke, ko, hw, lw);
    *(uint32_t*)(kh + base) = hw;
    *(uint32_t*)(kl + base) = lw;
}

// ---------------------------------------------------------------------------
// Flash attention (causal) on mma.sync with bf16x3 precision.
// CTA: 1 head x 64 q-rows, 4 warps (16 q each). kv tiles of 64.
// smem: Qh,Ql tiles (8KB each) + 2 stages x {Kh,Kl,Vh,Vl} (32KB/stage) = 80KB
// Tiles are [64 rows][128B], quad-swizzle q ^= row&7.
// ---------------------------------------------------------------------------
#define QS_B      8192
#define ASTAGE_B  (4 * QS_B)
#define ATT_SMEM  (2 * QS_B + 2 * ASTAGE_B)

__global__ void __launch_bounds__(128)
attn_mma(const __nv_bfloat16* __restrict__ qh, const __nv_bfloat16* __restrict__ ql,
         const __nv_bfloat16* __restrict__ kh, const __nv_bfloat16* __restrict__ kl,
         const __nv_bfloat16* __restrict__ vh, const __nv_bfloat16* __restrict__ vl,
         __nv_bfloat16* __restrict__ oh, __nv_bfloat16* __restrict__ ol) {
    extern __shared__ char sm[];
    const int tid  = threadIdx.x;
    const int lane = tid & 31;
    const int warp = tid >> 5;
    const int h    = blockIdx.y;
    const int qi   = gridDim.x - 1 - blockIdx.x;   // heavy tiles first
    const int q0   = qi * 64;
    const int ntiles = qi + 1;
    const int cbase  = h * HDK;

    char* Qh_t = sm;
    char* Ql_t = sm + QS_B;

    // Stage Q hi/lo tiles
    #pragma unroll
    for (int j = 0; j < 4; j++) {
        int qq  = tid + j * 128;          // 0..511 quads
        int row = qq >> 3, q = qq & 7;
        int pq  = q ^ (row & 7);
        CP_ASYNC16(smem_u32(Qh_t + row * 128 + pq * 16),
                   qh + (size_t)(q0 + row) * D_MODEL + cbase + q * 8);
        CP_ASYNC16(smem_u32(Ql_t + row * 128 + pq * 16),
                   ql + (size_t)(q0 + row) * D_MODEL + cbase + q * 8);
    }

    const __nv_bfloat16* kvsrc[4] = {kh, kl, vh, vl};
    auto load_kv = [&](int jt, int buf) {
        int n0 = jt * 64;
        char* sb = sm + 2 * QS_B + buf * ASTAGE_B;
        #pragma unroll
        for (int m = 0; m < 4; m++) {
            char* tile = sb + m * QS_B;
            #pragma unroll
            for (int j = 0; j < 4; j++) {
                int qq  = tid + j * 128;
                int row = qq >> 3, q = qq & 7;
                int pq  = q ^ (row & 7);
                CP_ASYNC16(smem_u32(tile + row * 128 + pq * 16),
                           kvsrc[m] + (size_t)(n0 + row) * D_MODEL + cbase + q * 8);
            }
        }
    };

    load_kv(0, 0);
    CP_COMMIT();

    uint32_t qfh[4][4], qfl[4][4];
    float o[8][4];
    #pragma unroll
    for (int f = 0; f < 8; f++)
        #pragma unroll
        for (int k = 0; k < 4; k++) o[f][k] = 0.f;
    float m0 = -1e30f, m1 = -1e30f, l0 = 0.f, l1 = 0.f;
    const int g = lane >> 2;

    for (int jt = 0; jt < ntiles; jt++) {
        if (jt + 1 < ntiles) { load_kv(jt + 1, (jt + 1) & 1); CP_COMMIT(); CP_WAIT(1); }
        else                 { CP_WAIT(0); }
        __syncthreads();

        if (jt == 0) {
            #pragma unroll
            for (int ks = 0; ks < 4; ks++) {
                int row = warp * 16 + (lane & 15);
                int aq  = ks * 2 + (lane >> 4);
                int pq  = aq ^ (row & 7);
                ldsm4(qfh[ks], smem_u32(Qh_t + row * 128 + pq * 16));
                ldsm4(qfl[ks], smem_u32(Ql_t + row * 128 + pq * 16));
            }
        }

        char* sb   = sm + 2 * QS_B + (jt & 1) * ASTAGE_B;
        char* Kh_t = sb;
        char* Kl_t = sb + QS_B;
        char* Vh_t = sb + 2 * QS_B;
        char* Vl_t = sb + 3 * QS_B;

        // ---- S = (Q/8) K^T, bf16x3 ----
        float s[8][4];
        #pragma unroll
        for (int f = 0; f < 8; f++)
            #pragma unroll
            for (int k = 0; k < 4; k++) s[f][k] = 0.f;

        #pragma unroll
        for (int ks = 0; ks < 4; ks++) {
            #pragma unroll
            for (int gi = 0; gi < 4; gi++) {
                int brow = gi * 16 + ((lane >> 4) & 1) * 8 + (lane & 7);
                int bq   = ks * 2 + ((lane >> 3) & 1);
                int pq   = bq ^ (brow & 7);
                uint32_t rh[4], rl[4];
                ldsm4(rh, smem_u32(Kh_t + brow * 128 + pq * 16));
                ldsm4(rl, smem_u32(Kl_t + brow * 128 + pq * 16));
                mma16816(s[gi * 2],     qfh[ks], rh);
                mma16816(s[gi * 2],     qfh[ks], rl);
                mma16816(s[gi * 2],     qfl[ks], rh);
                mma16816(s[gi * 2 + 1], qfh[ks], rh + 2);
                mma16816(s[gi * 2 + 1], qfh[ks], rl + 2);
                mma16816(s[gi * 2 + 1], qfl[ks], rh + 2);
            }
        }

        // ---- causal mask (diagonal tile only) ----
        if (jt == ntiles - 1) {
            int lr0 = warp * 16 + g, lr1 = lr0 + 8;
            #pragma unroll
            for (int f = 0; f < 8; f++) {
                int c0 = f * 8 + (lane & 3) * 2;
                if (c0     > lr0) s[f][0] = -1e30f;
                if (c0 + 1 > lr0) s[f][1] = -1e30f;
                if (c0     > lr1) s[f][2] = -1e30f;
                if (c0 + 1 > lr1) s[f][3] = -1e30f;
            }
        }

        // ---- online softmax ----
        float mx0 = -1e30f, mx1 = -1e30f;
        #pragma unroll
        for (int f = 0; f < 8; f++) {
            mx0 = fmaxf(mx0, fmaxf(s[f][0], s[f][1]));
            mx1 = fmaxf(mx1, fmaxf(s[f][2], s[f][3]));
        }
        mx0 = fmaxf(mx0, __shfl_xor_sync(0xffffffffu, mx0, 1));
        mx0 = fmaxf(mx0, __shfl_xor_sync(0xffffffffu, mx0, 2));
        mx1 = fmaxf(mx1, __shfl_xor_sync(0xffffffffu, mx1, 1));
        mx1 = fmaxf(mx1, __shfl_xor_sync(0xffffffffu, mx1, 2));

        float mn0 = fmaxf(m0, mx0), mn1 = fmaxf(m1, mx1);
        float cr0 = __expf(m0 - mn0), cr1 = __expf(m1 - mn1);
        float sum0 = 0.f, sum1 = 0.f;
        #pragma unroll
        for (int f = 0; f < 8; f++) {
            s[f][0] = __expf(s[f][0] - mn0);
            s[f][1] = __expf(s[f][1] - mn0);
            s[f][2] = __expf(s[f][2] - mn1);
            s[f][3] = __expf(s[f][3] - mn1);
            sum0 += s[f][0] + s[f][1];
            sum1 += s[f][2] + s[f][3];
        }
        sum0 += __shfl_xor_sync(0xffffffffu, sum0, 1);
        sum0 += __shfl_xor_sync(0xffffffffu, sum0, 2);
        sum1 += __shfl_xor_sync(0xffffffffu, sum1, 1);
        sum1 += __shfl_xor_sync(0xffffffffu, sum1, 2);
        m0 = mn0; m1 = mn1;
        l0 = l0 * cr0 + sum0;
        l1 = l1 * cr1 + sum1;
        #pragma unroll
        for (int f = 0; f < 8; f++) {
            o[f][0] *= cr0; o[f][1] *= cr0;
            o[f][2] *= cr1; o[f][3] *= cr1;
        }

        // ---- O += P V, bf16x3 (P hi/lo packed from S frags) ----
        #pragma unroll
        for (int ks2 = 0; ks2 < 4; ks2++) {
            const int f0 = ks2 * 2, f1 = f0 + 1;
            uint32_t pah[4], pal[4];
            split2(s[f0][0], s[f0][1], pah[0], pal[0]);
            split2(s[f0][2], s[f0][3], pah[1], pal[1]);
            split2(s[f1][0], s[f1][1], pah[2], pal[2]);
            split2(s[f1][2], s[f1][3], pah[3], pal[3]);

            int vrow = ks2 * 16 + ((lane >> 3) & 1) * 8 + (lane & 7);
            #pragma unroll
            for (int nv = 0; nv < 8; nv += 2) {
                int vq = nv + (lane >> 4);
                int pq = vq ^ (vrow & 7);
                uint32_t bvh[4], bvl[4];
                ldsm4t(bvh, smem_u32(Vh_t + vrow * 128 + pq * 16));
                ldsm4t(bvl, smem_u32(Vl_t + vrow * 128 + pq * 16));
                mma16816(o[nv],     pah, bvh);
                mma16816(o[nv],     pah, bvl);
                mma16816(o[nv],     pal, bvh);
                mma16816(o[nv + 1], pah, bvh + 2);
                mma16816(o[nv + 1], pah, bvl + 2);
                mma16816(o[nv + 1], pal, bvh + 2);
            }
        }
        __syncthreads();   // protect stage buffer before next prefetch
    }

    // ---- epilogue: normalize, split to bf16 hi/lo, store ----
    float inv0 = 1.f / l0, inv1 = 1.f / l1;
    int row0 = q0 + warp * 16 + g;
    int colb = cbase + (lane & 3) * 2;
    #pragma unroll
    for (int f = 0; f < 8; f++) {
        int c = colb + f * 8;
        uint32_t hw, lw;
        split2(o[f][0] * inv0, o[f][1] * inv0, hw, lw);
        *(uint32_t*)(oh + (size_t)row0 * D_MODEL + c) = hw;
        *(uint32_t*)(ol + (size_t)row0 * D_MODEL + c) = lw;
        split2(o[f][2] * inv1, o[f][3] * inv1, hw, lw);
        *(uint32_t*)(oh + (size_t)(row0 + 8) * D_MODEL + c) = hw;
        *(uint32_t*)(ol + (size_t)(row0 + 8) * D_MODEL + c) = lw;
    }
}

// ---------------------------------------------------------------------------
extern "C" void kernel_launch(void* const* d_in, const int* in_sizes, int n_in,
                              void* d_out, int out_size) {
    const float* x   = (const float*)d_in[0];
    const int*   pos = (const int*)d_in[1];
    const float* Wq  = (const float*)d_in[2];
    const float* Wk  = (const float*)d_in[3];
    const float* Wv  = (const float*)d_in[4];
    const float* Wo  = (const float*)d_in[5];
    float* out = (float*)d_out;

    float *qp, *kp, *vp;
    cudaGetSymbolAddress((void**)&qp, g_Q);
    cudaGetSymbolAddress((void**)&kp, g_K);
    cudaGetSymbolAddress((void**)&vp, g_V);

    __nv_bfloat16 *xh, *xl, *ah, *al, *qhp, *qlp, *khp, *klp, *vhp, *vlp;
    __nv_bfloat16 *wqh, *wql, *wkh, *wkl, *wvh, *wvl, *woh, *wol;
    cudaGetSymbolAddress((void**)&xh, g_xh);   cudaGetSymbolAddress((void**)&xl, g_xl);
    cudaGetSymbolAddress((void**)&ah, g_ah);   cudaGetSymbolAddress((void**)&al, g_al);
    cudaGetSymbolAddress((void**)&qhp, g_qh);  cudaGetSymbolAddress((void**)&qlp, g_ql);
    cudaGetSymbolAddress((void**)&khp, g_kh);  cudaGetSymbolAddress((void**)&klp, g_kl);
    cudaGetSymbolAddress((void**)&vhp, g_vh);  cudaGetSymbolAddress((void**)&vlp, g_vl);
    cudaGetSymbolAddress((void**)&wqh, g_wqh); cudaGetSymbolAddress((void**)&wql, g_wql);
    cudaGetSymbolAddress((void**)&wkh, g_wkh); cudaGetSymbolAddress((void**)&wkl, g_wkl);
    cudaGetSymbolAddress((void**)&wvh, g_wvh); cudaGetSymbolAddress((void**)&wvl, g_wvl);
    cudaGetSymbolAddress((void**)&woh, g_woh); cudaGetSymbolAddress((void**)&wol, g_wol);

    cudaFuncSetAttribute(gemm_bf16x3,
                         cudaFuncAttributeMaxDynamicSharedMemorySize, GSMEM);
    cudaFuncSetAttribute(attn_mma,
                         cudaFuncAttributeMaxDynamicSharedMemorySize, ATT_SMEM);

    const int nx = S_LEN * D_MODEL;
    const int nw = D_MODEL * D_MODEL;
    split_bf16<<<nx / 1024, 256>>>(x,  xh,  xl,  nx);
    split_bf16<<<nw / 1024, 256>>>(Wq, wqh, wql, nw);
    split_bf16<<<nw / 1024, 256>>>(Wk, wkh, wkl, nw);
    split_bf16<<<nw / 1024, 256>>>(Wv, wvh, wvl, nw);
    split_bf16<<<nw / 1024, 256>>>(Wo, woh, wol, nw);

    dim3 gproj(D_MODEL / 128, S_LEN / 128);
    gemm_bf16x3<<<gproj, 256, GSMEM>>>(xh, xl, wqh, wql, qp);
    gemm_bf16x3<<<gproj, 256, GSMEM>>>(xh, xl, wkh, wkl, kp);
    gemm_bf16x3<<<gproj, 256, GSMEM>>>(xh, xl, wvh, wvl, vp);

    int npairs = S_LEN * (D_MODEL / 2);
    rope_split<<<(npairs + 255) / 256, 256>>>(qp, kp, pos, qhp, qlp, khp, klp);
    split_bf16<<<nx / 1024, 256>>>(vp, vhp, vlp, nx);

    dim3 gattn(S_LEN / 64, NHEAD);            // (64, 16)
    attn_mma<<<gattn, 128, ATT_SMEM>>>(qhp, qlp, khp, klp, vhp, vlp, ah, al);

    gemm_bf16x3<<<gproj, 256, GSMEM>>>(ah, al, woh, wol, out);
}

// round 8
// speedup vs baseline: 3.0071x; 1.0094x over previous
#include <cuda_runtime.h>
#include <cuda_bf16.h>
#include <stdint.h>
#include <math.h>

#define S_LEN 4096
#define D_MODEL 1024
#define NHEAD 16
#define HDK 64

// ---------------------------------------------------------------------------
// Scratch (__device__ globals; allocation-free rule)
// ---------------------------------------------------------------------------
__device__ __nv_bfloat16 g_xh[S_LEN * D_MODEL];
__device__ __nv_bfloat16 g_xl[S_LEN * D_MODEL];
__device__ __nv_bfloat16 g_ah[S_LEN * D_MODEL];
__device__ __nv_bfloat16 g_al[S_LEN * D_MODEL];
__device__ __nv_bfloat16 g_qh[S_LEN * D_MODEL];
__device__ __nv_bfloat16 g_ql[S_LEN * D_MODEL];
__device__ __nv_bfloat16 g_kh[S_LEN * D_MODEL];
__device__ __nv_bfloat16 g_kl[S_LEN * D_MODEL];
__device__ __nv_bfloat16 g_vh[S_LEN * D_MODEL];
__device__ __nv_bfloat16 g_vl[S_LEN * D_MODEL];
__device__ __nv_bfloat16 g_wqh[D_MODEL * D_MODEL];
__device__ __nv_bfloat16 g_wql[D_MODEL * D_MODEL];
__device__ __nv_bfloat16 g_wkh[D_MODEL * D_MODEL];
__device__ __nv_bfloat16 g_wkl[D_MODEL * D_MODEL];
__device__ __nv_bfloat16 g_wvh[D_MODEL * D_MODEL];
__device__ __nv_bfloat16 g_wvl[D_MODEL * D_MODEL];
__device__ __nv_bfloat16 g_woh[D_MODEL * D_MODEL];
__device__ __nv_bfloat16 g_wol[D_MODEL * D_MODEL];

// ---------------------------------------------------------------------------
// Portable (sm_80+) tensor-core primitives
// ---------------------------------------------------------------------------
__device__ __forceinline__ uint32_t smem_u32(const void* p) {
    uint32_t a;
    asm("{ .reg .u64 t; cvta.to.shared.u64 t, %1; cvt.u32.u64 %0, t; }"
        : "=r"(a) : "l"(p));
    return a;
}

__device__ __forceinline__ void ldsm4(uint32_t* r, uint32_t addr) {
    asm volatile("ldmatrix.sync.aligned.m8n8.x4.shared.b16 {%0,%1,%2,%3}, [%4];"
        : "=r"(r[0]), "=r"(r[1]), "=r"(r[2]), "=r"(r[3]) : "r"(addr));
}

__device__ __forceinline__ void ldsm4t(uint32_t* r, uint32_t addr) {
    asm volatile("ldmatrix.sync.aligned.m8n8.x4.trans.shared.b16 {%0,%1,%2,%3}, [%4];"
        : "=r"(r[0]), "=r"(r[1]), "=r"(r[2]), "=r"(r[3]) : "r"(addr));
}

__device__ __forceinline__ void mma16816(float* d, const uint32_t* a, const uint32_t* b) {
    asm volatile(
        "mma.sync.aligned.m16n8k16.row.col.f32.bf16.bf16.f32 "
        "{%0,%1,%2,%3}, {%4,%5,%6,%7}, {%8,%9}, {%0,%1,%2,%3};"
        : "+f"(d[0]), "+f"(d[1]), "+f"(d[2]), "+f"(d[3])
        : "r"(a[0]), "r"(a[1]), "r"(a[2]), "r"(a[3]), "r"(b[0]), "r"(b[1]));
}

#define CP_ASYNC16(sa, ga) \
    asm volatile("cp.async.cg.shared.global [%0], [%1], 16;" :: "r"(sa), "l"(ga))
#define CP_COMMIT()  asm volatile("cp.async.commit_group;")
#define CP_WAIT(N)   asm volatile("cp.async.wait_group %0;" :: "n"(N))

__device__ __forceinline__ void split2(float a, float b, uint32_t& hi, uint32_t& lo) {
    __nv_bfloat16 ha = __float2bfloat16(a), hb = __float2bfloat16(b);
    __nv_bfloat162 hv; hv.x = ha; hv.y = hb;
    hi = *reinterpret_cast<uint32_t*>(&hv);
    __nv_bfloat162 lv;
    lv.x = __float2bfloat16(a - __bfloat162float(ha));
    lv.y = __float2bfloat16(b - __bfloat162float(hb));
    lo = *reinterpret_cast<uint32_t*>(&lv);
}

// ---------------------------------------------------------------------------
// fp32 -> bf16 hi/lo split
// ---------------------------------------------------------------------------
__global__ void split_bf16(const float* __restrict__ in,
                           __nv_bfloat16* __restrict__ hi,
                           __nv_bfloat16* __restrict__ lo, int n) {
    int i = (blockIdx.x * blockDim.x + threadIdx.x) * 4;
    if (i >= n) return;
    float4 v = *(const float4*)(in + i);
    uint32_t h0, l0, h1, l1;
    split2(v.x, v.y, h0, l0);
    split2(v.z, v.w, h1, l1);
    *(uint32_t*)(hi + i)     = h0;  *(uint32_t*)(hi + i + 2) = h1;
    *(uint32_t*)(lo + i)     = l0;  *(uint32_t*)(lo + i + 2) = l1;
}

// ---------------------------------------------------------------------------
// bf16x3 GEMM, term-major MMA ordering, fused epilogues.
// MODE 0: plain fp32 C.  MODE 1: rope+scale(0.125)+split -> H/L (Q path)
// MODE 2: rope+split -> H/L (K path).  MODE 3: split -> H/L (V path)
// ---------------------------------------------------------------------------
#define GK       1024
#define BK       32
#define NKC      (GK / BK)
#define TILE8KB  8192
#define STAGE_B  (4 * TILE8KB)
#define GSMEM    (2 * STAGE_B)

template<int MODE>
__global__ void __launch_bounds__(256, 1)
gemm_bf16x3(const __nv_bfloat16* __restrict__ Ah, const __nv_bfloat16* __restrict__ Al,
            const __nv_bfloat16* __restrict__ Bh, const __nv_bfloat16* __restrict__ Bl,
            float* __restrict__ C,
            __nv_bfloat16* __restrict__ H, __nv_bfloat16* __restrict__ L,
            const int* __restrict__ pos) {
    extern __shared__ char sm[];
    const int tid  = threadIdx.x;
    const int lane = tid & 31;
    const int warp = tid >> 5;
    const int wm   = warp & 1;
    const int wn   = warp >> 1;
    const int bm   = blockIdx.y * 128;
    const int bn   = blockIdx.x * 128;

    const __nv_bfloat16* srcs[4] = {Ah, Al, Bh, Bl};

    auto load_stage = [&](int kt, int buf) {
        const int koff = kt * BK;
        char* sbase = sm + buf * STAGE_B;
        #pragma unroll
        for (int mtx = 0; mtx < 4; mtx++) {
            const __nv_bfloat16* src = srcs[mtx];
            const int rbase = (mtx < 2) ? bm : bn;
            char* stile = sbase + mtx * TILE8KB;
            #pragma unroll
            for (int j = 0; j < 2; j++) {
                int qi  = tid + j * 256;
                int row = qi >> 2, q = qi & 3;
                int pq  = q ^ (row & 3);
                uint32_t sa = smem_u32(stile + row * 64 + pq * 16);
                const void* ga = src + (size_t)(rbase + row) * GK + koff + q * 8;
                CP_ASYNC16(sa, ga);
            }
        }
    };

    float d[4][4][4];
    #pragma unroll
    for (int i = 0; i < 4; i++)
        #pragma unroll
        for (int j = 0; j < 4; j++)
            #pragma unroll
            for (int k = 0; k < 4; k++) d[i][j][k] = 0.f;

    load_stage(0, 0);
    CP_COMMIT();

    const int a_row = lane & 15;
    const int a_qs  = lane >> 4;
    const int b_row = ((lane >> 4) & 1) * 8 + (lane & 7);
    const int b_qs  = (lane >> 3) & 1;

    for (int kt = 0; kt < NKC; kt++) {
        if (kt + 1 < NKC) { load_stage(kt + 1, (kt + 1) & 1); CP_COMMIT(); CP_WAIT(1); }
        else              { CP_WAIT(0); }
        __syncthreads();

        char* sbase = sm + (kt & 1) * STAGE_B;
        char* tAh = sbase + 0 * TILE8KB;
        char* tAl = sbase + 1 * TILE8KB;
        char* tBh = sbase + 2 * TILE8KB;
        char* tBl = sbase + 3 * TILE8KB;

        #pragma unroll
        for (int ks = 0; ks < 2; ks++) {
            uint32_t ah[4][4], al[4][4], bh[4][2], bl[4][2];
            #pragma unroll
            for (int mi = 0; mi < 4; mi++) {
                int row = wm * 64 + mi * 16 + a_row;
                int pq  = (ks * 2 + a_qs) ^ (row & 3);
                ldsm4(ah[mi], smem_u32(tAh + row * 64 + pq * 16));
                ldsm4(al[mi], smem_u32(tAl + row * 64 + pq * 16));
            }
            #pragma unroll
            for (int gi = 0; gi < 2; gi++) {
                int row = wn * 32 + gi * 16 + b_row;
                int pq  = (ks * 2 + b_qs) ^ (row & 3);
                uint32_t rh[4], rl[4];
                ldsm4(rh, smem_u32(tBh + row * 64 + pq * 16));
                ldsm4(rl, smem_u32(tBl + row * 64 + pq * 16));
                bh[gi * 2 + 0][0] = rh[0]; bh[gi * 2 + 0][1] = rh[1];
                bh[gi * 2 + 1][0] = rh[2]; bh[gi * 2 + 1][1] = rh[3];
                bl[gi * 2 + 0][0] = rl[0]; bl[gi * 2 + 0][1] = rl[1];
                bl[gi * 2 + 1][0] = rl[2]; bl[gi * 2 + 1][1] = rl[3];
            }
            // term-major: 16 distinct accumulators between same-d reuses
            #pragma unroll
            for (int mi = 0; mi < 4; mi++)
                #pragma unroll
                for (int ni = 0; ni < 4; ni++)
                    mma16816(d[mi][ni], ah[mi], bh[ni]);
            #pragma unroll
            for (int mi = 0; mi < 4; mi++)
                #pragma unroll
                for (int ni = 0; ni < 4; ni++)
                    mma16816(d[mi][ni], ah[mi], bl[ni]);
            #pragma unroll
            for (int mi = 0; mi < 4; mi++)
                #pragma unroll
                for (int ni = 0; ni < 4; ni++)
                    mma16816(d[mi][ni], al[mi], bh[ni]);
        }
        __syncthreads();
    }

    const int er = lane >> 2;
    const int ec = (lane & 3) * 2;
    if (MODE == 0) {
        #pragma unroll
        for (int mi = 0; mi < 4; mi++) {
            int r0 = bm + wm * 64 + mi * 16 + er;
            #pragma unroll
            for (int ni = 0; ni < 4; ni++) {
                int c0 = bn + wn * 32 + ni * 8 + ec;
                *(float2*)(C + (size_t)r0 * D_MODEL + c0)       = make_float2(d[mi][ni][0], d[mi][ni][1]);
                *(float2*)(C + (size_t)(r0 + 8) * D_MODEL + c0) = make_float2(d[mi][ni][2], d[mi][ni][3]);
            }
        }
    } else {
        #pragma unroll
        for (int ni = 0; ni < 4; ni++) {
            int c0 = bn + wn * 32 + ni * 8 + ec;
            float finv = 0.f;
            if (MODE == 1 || MODE == 2) {
                int i = (c0 & (HDK - 1)) >> 1;
                finv = (float)exp(-(double)i * (1.0 / 32.0) * 9.210340371976184);
            }
            #pragma unroll
            for (int mi = 0; mi < 4; mi++) {
                int r0 = bm + wm * 64 + mi * 16 + er;
                #pragma unroll
                for (int half = 0; half < 2; half++) {
                    int r = r0 + half * 8;
                    float v0 = d[mi][ni][half * 2], v1 = d[mi][ni][half * 2 + 1];
                    if (MODE == 1 || MODE == 2) {
                        float sn, cs;
                        sincosf((float)pos[r] * finv, &sn, &cs);
                        float e = v0 * cs - v1 * sn;
                        float o = v0 * sn + v1 * cs;
                        if (MODE == 1) { e *= 0.125f; o *= 0.125f; }
                        v0 = e; v1 = o;
                    }
                    uint32_t hw, lw;
                    split2(v0, v1, hw, lw);
                    *(uint32_t*)(H + (size_t)r * D_MODEL + c0) = hw;
                    *(uint32_t*)(L + (size_t)r * D_MODEL + c0) = lw;
                }
            }
        }
    }
}

// ---------------------------------------------------------------------------
// Flash attention (causal), mma.sync bf16x3, term-major MMA ordering.
// ---------------------------------------------------------------------------
#define QS_B      8192
#define ASTAGE_B  (4 * QS_B)
#define ATT_SMEM  (2 * QS_B + 2 * ASTAGE_B)

__global__ void __launch_bounds__(128)
attn_mma(const __nv_bfloat16* __restrict__ qh, const __nv_bfloat16* __restrict__ ql,
         const __nv_bfloat16* __restrict__ kh, const __nv_bfloat16* __restrict__ kl,
         const __nv_bfloat16* __restrict__ vh, const __nv_bfloat16* __restrict__ vl,
         __nv_bfloat16* __restrict__ oh, __nv_bfloat16* __restrict__ ol) {
    extern __shared__ char sm[];
    const int tid  = threadIdx.x;
    const int lane = tid & 31;
    const int warp = tid >> 5;
    const int h    = blockIdx.y;
    const int qi   = gridDim.x - 1 - blockIdx.x;
    const int q0   = qi * 64;
    const int ntiles = qi + 1;
    const int cbase  = h * HDK;

    char* Qh_t = sm;
    char* Ql_t = sm + QS_B;

    #pragma unroll
    for (int j = 0; j < 4; j++) {
        int qq  = tid + j * 128;
        int row = qq >> 3, q = qq & 7;
        int pq  = q ^ (row & 7);
        CP_ASYNC16(smem_u32(Qh_t + row * 128 + pq * 16),
                   qh + (size_t)(q0 + row) * D_MODEL + cbase + q * 8);
        CP_ASYNC16(smem_u32(Ql_t + row * 128 + pq * 16),
                   ql + (size_t)(q0 + row) * D_MODEL + cbase + q * 8);
    }

    const __nv_bfloat16* kvsrc[4] = {kh, kl, vh, vl};
    auto load_kv = [&](int jt, int buf) {
        int n0 = jt * 64;
        char* sb = sm + 2 * QS_B + buf * ASTAGE_B;
        #pragma unroll
        for (int m = 0; m < 4; m++) {
            char* tile = sb + m * QS_B;
            #pragma unroll
            for (int j = 0; j < 4; j++) {
                int qq  = tid + j * 128;
                int row = qq >> 3, q = qq & 7;
                int pq  = q ^ (row & 7);
                CP_ASYNC16(smem_u32(tile + row * 128 + pq * 16),
                           kvsrc[m] + (size_t)(n0 + row) * D_MODEL + cbase + q * 8);
            }
        }
    };

    load_kv(0, 0);
    CP_COMMIT();

    uint32_t qfh[4][4], qfl[4][4];
    float o[8][4];
    #pragma unroll
    for (int f = 0; f < 8; f++)
        #pragma unroll
        for (int k = 0; k < 4; k++) o[f][k] = 0.f;
    float m0 = -1e30f, m1 = -1e30f, l0 = 0.f, l1 = 0.f;
    const int g = lane >> 2;

    for (int jt = 0; jt < ntiles; jt++) {
        if (jt + 1 < ntiles) { load_kv(jt + 1, (jt + 1) & 1); CP_COMMIT(); CP_WAIT(1); }
        else                 { CP_WAIT(0); }
        __syncthreads();

        if (jt == 0) {
            #pragma unroll
            for (int ks = 0; ks < 4; ks++) {
                int row = warp * 16 + (lane & 15);
                int aq  = ks * 2 + (lane >> 4);
                int pq  = aq ^ (row & 7);
                ldsm4(qfh[ks], smem_u32(Qh_t + row * 128 + pq * 16));
                ldsm4(qfl[ks], smem_u32(Ql_t + row * 128 + pq * 16));
            }
        }

        char* sb   = sm + 2 * QS_B + (jt & 1) * ASTAGE_B;
        char* Kh_t = sb;
        char* Kl_t = sb + QS_B;
        char* Vh_t = sb + 2 * QS_B;
        char* Vl_t = sb + 3 * QS_B;

        // ---- S = (Q/8) K^T, bf16x3, term-major ----
        float s[8][4];
        #pragma unroll
        for (int f = 0; f < 8; f++)
            #pragma unroll
            for (int k = 0; k < 4; k++) s[f][k] = 0.f;

        #pragma unroll
        for (int ks = 0; ks < 4; ks++) {
            uint32_t rh[4][4], rl[4][4];
            #pragma unroll
            for (int gi = 0; gi < 4; gi++) {
                int brow = gi * 16 + ((lane >> 4) & 1) * 8 + (lane & 7);
                int bq   = ks * 2 + ((lane >> 3) & 1);
                int pq   = bq ^ (brow & 7);
                ldsm4(rh[gi], smem_u32(Kh_t + brow * 128 + pq * 16));
                ldsm4(rl[gi], smem_u32(Kl_t + brow * 128 + pq * 16));
            }
            #pragma unroll
            for (int gi = 0; gi < 4; gi++) {
                mma16816(s[gi * 2],     qfh[ks], rh[gi]);
                mma16816(s[gi * 2 + 1], qfh[ks], rh[gi] + 2);
            }
            #pragma unroll
            for (int gi = 0; gi < 4; gi++) {
                mma16816(s[gi * 2],     qfh[ks], rl[gi]);
                mma16816(s[gi * 2 + 1], qfh[ks], rl[gi] + 2);
            }
            #pragma unroll
            for (int gi = 0; gi < 4; gi++) {
                mma16816(s[gi * 2],     qfl[ks], rh[gi]);
                mma16816(s[gi * 2 + 1], qfl[ks], rh[gi] + 2);
            }
        }

        // ---- causal mask (diagonal tile only) ----
        if (jt == ntiles - 1) {
            int lr0 = warp * 16 + g, lr1 = lr0 + 8;
            #pragma unroll
            for (int f = 0; f < 8; f++) {
                int c0 = f * 8 + (lane & 3) * 2;
                if (c0     > lr0) s[f][0] = -1e30f;
                if (c0 + 1 > lr0) s[f][1] = -1e30f;
                if (c0     > lr1) s[f][2] = -1e30f;
                if (c0 + 1 > lr1) s[f][3] = -1e30f;
            }
        }

        // ---- online softmax ----
        float mx0 = -1e30f, mx1 = -1e30f;
        #pragma unroll
        for (int f = 0; f < 8; f++) {
            mx0 = fmaxf(mx0, fmaxf(s[f][0], s[f][1]));
            mx1 = fmaxf(mx1, fmaxf(s[f][2], s[f][3]));
        }
        mx0 = fmaxf(mx0, __shfl_xor_sync(0xffffffffu, mx0, 1));
        mx0 = fmaxf(mx0, __shfl_xor_sync(0xffffffffu, mx0, 2));
        mx1 = fmaxf(mx1, __shfl_xor_sync(0xffffffffu, mx1, 1));
        mx1 = fmaxf(mx1, __shfl_xor_sync(0xffffffffu, mx1, 2));

        float mn0 = fmaxf(m0, mx0), mn1 = fmaxf(m1, mx1);
        float cr0 = __expf(m0 - mn0), cr1 = __expf(m1 - mn1);
        float sum0 = 0.f, sum1 = 0.f;
        #pragma unroll
        for (int f = 0; f < 8; f++) {
            s[f][0] = __expf(s[f][0] - mn0);
            s[f][1] = __expf(s[f][1] - mn0);
            s[f][2] = __expf(s[f][2] - mn1);
            s[f][3] = __expf(s[f][3] - mn1);
            sum0 += s[f][0] + s[f][1];
            sum1 += s[f][2] + s[f][3];
        }
        sum0 += __shfl_xor_sync(0xffffffffu, sum0, 1);
        sum0 += __shfl_xor_sync(0xffffffffu, sum0, 2);
        sum1 += __shfl_xor_sync(0xffffffffu, sum1, 1);
        sum1 += __shfl_xor_sync(0xffffffffu, sum1, 2);
        m0 = mn0; m1 = mn1;
        l0 = l0 * cr0 + sum0;
        l1 = l1 * cr1 + sum1;
        #pragma unroll
        for (int f = 0; f < 8; f++) {
            o[f][0] *= cr0; o[f][1] *= cr0;
            o[f][2] *= cr1; o[f][3] *= cr1;
        }

        // ---- O += P V, bf16x3, term-major ----
        #pragma unroll
        for (int ks2 = 0; ks2 < 4; ks2++) {
            const int f0 = ks2 * 2, f1 = f0 + 1;
            uint32_t pah[4], pal[4];
            split2(s[f0][0], s[f0][1], pah[0], pal[0]);
            split2(s[f0][2], s[f0][3], pah[1], pal[1]);
            split2(s[f1][0], s[f1][1], pah[2], pal[2]);
            split2(s[f1][2], s[f1][3], pah[3], pal[3]);

            int vrow = ks2 * 16 + ((lane >> 3) & 1) * 8 + (lane & 7);
            uint32_t bvh[4][4], bvl[4][4];
            #pragma unroll
            for (int nvp = 0; nvp < 4; nvp++) {
                int vq = nvp * 2 + (lane >> 4);
                int pq = vq ^ (vrow & 7);
                ldsm4t(bvh[nvp], smem_u32(Vh_t + vrow * 128 + pq * 16));
                ldsm4t(bvl[nvp], smem_u32(Vl_t + vrow * 128 + pq * 16));
            }
            #pragma unroll
            for (int nvp = 0; nvp < 4; nvp++) {
                mma16816(o[nvp * 2],     pah, bvh[nvp]);
                mma16816(o[nvp * 2 + 1], pah, bvh[nvp] + 2);
            }
            #pragma unroll
            for (int nvp = 0; nvp < 4; nvp++) {
                mma16816(o[nvp * 2],     pah, bvl[nvp]);
                mma16816(o[nvp * 2 + 1], pah, bvl[nvp] + 2);
            }
            #pragma unroll
            for (int nvp = 0; nvp < 4; nvp++) {
                mma16816(o[nvp * 2],     pal, bvh[nvp]);
                mma16816(o[nvp * 2 + 1], pal, bvh[nvp] + 2);
            }
        }
        __syncthreads();
    }

    // ---- epilogue: normalize, split to bf16 hi/lo, store ----
    float inv0 = 1.f / l0, inv1 = 1.f / l1;
    int row0 = q0 + warp * 16 + g;
    int colb = cbase + (lane & 3) * 2;
    #pragma unroll
    for (int f = 0; f < 8; f++) {
        int c = colb + f * 8;
        uint32_t hw, lw;
        split2(o[f][0] * inv0, o[f][1] * inv0, hw, lw);
        *(uint32_t*)(oh + (size_t)row0 * D_MODEL + c) = hw;
        *(uint32_t*)(ol + (size_t)row0 * D_MODEL + c) = lw;
        split2(o[f][2] * inv1, o[f][3] * inv1, hw, lw);
        *(uint32_t*)(oh + (size_t)(row0 + 8) * D_MODEL + c) = hw;
        *(uint32_t*)(ol + (size_t)(row0 + 8) * D_MODEL + c) = lw;
    }
}

// ---------------------------------------------------------------------------
extern "C" void kernel_launch(void* const* d_in, const int* in_sizes, int n_in,
                              void* d_out, int out_size) {
    const float* x   = (const float*)d_in[0];
    const int*   pos = (const int*)d_in[1];
    const float* Wq  = (const float*)d_in[2];
    const float* Wk  = (const float*)d_in[3];
    const float* Wv  = (const float*)d_in[4];
    const float* Wo  = (const float*)d_in[5];
    float* out = (float*)d_out;

    __nv_bfloat16 *xh, *xl, *ah, *al, *qhp, *qlp, *khp, *klp, *vhp, *vlp;
    __nv_bfloat16 *wqh, *wql, *wkh, *wkl, *wvh, *wvl, *woh, *wol;
    cudaGetSymbolAddress((void**)&xh, g_xh);   cudaGetSymbolAddress((void**)&xl, g_xl);
    cudaGetSymbolAddress((void**)&ah, g_ah);   cudaGetSymbolAddress((void**)&al, g_al);
    cudaGetSymbolAddress((void**)&qhp, g_qh);  cudaGetSymbolAddress((void**)&qlp, g_ql);
    cudaGetSymbolAddress((void**)&khp, g_kh);  cudaGetSymbolAddress((void**)&klp, g_kl);
    cudaGetSymbolAddress((void**)&vhp, g_vh);  cudaGetSymbolAddress((void**)&vlp, g_vl);
    cudaGetSymbolAddress((void**)&wqh, g_wqh); cudaGetSymbolAddress((void**)&wql, g_wql);
    cudaGetSymbolAddress((void**)&wkh, g_wkh); cudaGetSymbolAddress((void**)&wkl, g_wkl);
    cudaGetSymbolAddress((void**)&wvh, g_wvh); cudaGetSymbolAddress((void**)&wvl, g_wvl);
    cudaGetSymbolAddress((void**)&woh, g_woh); cudaGetSymbolAddress((void**)&wol, g_wol);

    cudaFuncSetAttribute(gemm_bf16x3<0>, cudaFuncAttributeMaxDynamicSharedMemorySize, GSMEM);
    cudaFuncSetAttribute(gemm_bf16x3<1>, cudaFuncAttributeMaxDynamicSharedMemorySize, GSMEM);
    cudaFuncSetAttribute(gemm_bf16x3<2>, cudaFuncAttributeMaxDynamicSharedMemorySize, GSMEM);
    cudaFuncSetAttribute(gemm_bf16x3<3>, cudaFuncAttributeMaxDynamicSharedMemorySize, GSMEM);
    cudaFuncSetAttribute(attn_mma, cudaFuncAttributeMaxDynamicSharedMemorySize, ATT_SMEM);

    const int nx = S_LEN * D_MODEL;
    const int nw = D_MODEL * D_MODEL;
    split_bf16<<<nx / 1024, 256>>>(x,  xh,  xl,  nx);
    split_bf16<<<nw / 1024, 256>>>(Wq, wqh, wql, nw);
    split_bf16<<<nw / 1024, 256>>>(Wk, wkh, wkl, nw);
    split_bf16<<<nw / 1024, 256>>>(Wv, wvh, wvl, nw);
    split_bf16<<<nw / 1024, 256>>>(Wo, woh, wol, nw);

    dim3 gproj(D_MODEL / 128, S_LEN / 128);
    gemm_bf16x3<1><<<gproj, 256, GSMEM>>>(xh, xl, wqh, wql, nullptr, qhp, qlp, pos);
    gemm_bf16x3<2><<<gproj, 256, GSMEM>>>(xh, xl, wkh, wkl, nullptr, khp, klp, pos);
    gemm_bf16x3<3><<<gproj, 256, GSMEM>>>(xh, xl, wvh, wvl, nullptr, vhp, vlp, pos);

    dim3 gattn(S_LEN / 64, NHEAD);
    attn_mma<<<gattn, 128, ATT_SMEM>>>(qhp, qlp, khp, klp, vhp, vlp, ah, al);

    gemm_bf16x3<0><<<gproj, 256, GSMEM>>>(ah, al, woh, wol, out, nullptr, nullptr, nullptr);
}

// round 9
// speedup vs baseline: 4.0033x; 1.3313x over previous
#include <cuda_runtime.h>
#include <cuda_fp16.h>
#include <stdint.h>
#include <math.h>

#define S_LEN 4096
#define D_MODEL 1024
#define NHEAD 16
#define HDK 64

// ---------------------------------------------------------------------------
// Scratch (__device__ globals; allocation-free rule)
// ---------------------------------------------------------------------------
__device__ __half g_xh[S_LEN * D_MODEL];
__device__ __half g_xl[S_LEN * D_MODEL];
__device__ __half g_ah[S_LEN * D_MODEL];
__device__ __half g_al[S_LEN * D_MODEL];
__device__ __half g_qh[S_LEN * D_MODEL];
__device__ __half g_ql[S_LEN * D_MODEL];
__device__ __half g_kh[S_LEN * D_MODEL];
__device__ __half g_vh[S_LEN * D_MODEL];
__device__ __half g_wq[D_MODEL * D_MODEL];
__device__ __half g_wk[D_MODEL * D_MODEL];
__device__ __half g_wv[D_MODEL * D_MODEL];
__device__ __half g_wo[D_MODEL * D_MODEL];

// ---------------------------------------------------------------------------
// Portable (sm_80+) tensor-core primitives, fp16 flavor
// ---------------------------------------------------------------------------
__device__ __forceinline__ uint32_t smem_u32(const void* p) {
    uint32_t a;
    asm("{ .reg .u64 t; cvta.to.shared.u64 t, %1; cvt.u32.u64 %0, t; }"
        : "=r"(a) : "l"(p));
    return a;
}

__device__ __forceinline__ void ldsm4(uint32_t* r, uint32_t addr) {
    asm volatile("ldmatrix.sync.aligned.m8n8.x4.shared.b16 {%0,%1,%2,%3}, [%4];"
        : "=r"(r[0]), "=r"(r[1]), "=r"(r[2]), "=r"(r[3]) : "r"(addr));
}

__device__ __forceinline__ void ldsm4t(uint32_t* r, uint32_t addr) {
    asm volatile("ldmatrix.sync.aligned.m8n8.x4.trans.shared.b16 {%0,%1,%2,%3}, [%4];"
        : "=r"(r[0]), "=r"(r[1]), "=r"(r[2]), "=r"(r[3]) : "r"(addr));
}

__device__ __forceinline__ void mma16816(float* d, const uint32_t* a, const uint32_t* b) {
    asm volatile(
        "mma.sync.aligned.m16n8k16.row.col.f32.f16.f16.f32 "
        "{%0,%1,%2,%3}, {%4,%5,%6,%7}, {%8,%9}, {%0,%1,%2,%3};"
        : "+f"(d[0]), "+f"(d[1]), "+f"(d[2]), "+f"(d[3])
        : "r"(a[0]), "r"(a[1]), "r"(a[2]), "r"(a[3]), "r"(b[0]), "r"(b[1]));
}

#define CP_ASYNC16(sa, ga) \
    asm volatile("cp.async.cg.shared.global [%0], [%1], 16;" :: "r"(sa), "l"(ga))
#define CP_COMMIT()  asm volatile("cp.async.commit_group;")
#define CP_WAIT(N)   asm volatile("cp.async.wait_group %0;" :: "n"(N))

__device__ __forceinline__ uint32_t pack_h2(float a, float b) {
    __half2 hv; hv.x = __float2half_rn(a); hv.y = __float2half_rn(b);
    return *reinterpret_cast<uint32_t*>(&hv);
}

__device__ __forceinline__ void split2h(float a, float b, uint32_t& hi, uint32_t& lo) {
    __half ha = __float2half_rn(a), hb = __float2half_rn(b);
    __half2 hv; hv.x = ha; hv.y = hb;
    hi = *reinterpret_cast<uint32_t*>(&hv);
    __half2 lv;
    lv.x = __float2half_rn(a - __half2float(ha));
    lv.y = __float2half_rn(b - __half2float(hb));
    lo = *reinterpret_cast<uint32_t*>(&lv);
}

// ---------------------------------------------------------------------------
// fp32 -> fp16 hi/lo split (activations) and plain convert (weights)
// ---------------------------------------------------------------------------
__global__ void split_h(const float* __restrict__ in,
                        __half* __restrict__ hi, __half* __restrict__ lo, int n) {
    int i = (blockIdx.x * blockDim.x + threadIdx.x) * 4;
    if (i >= n) return;
    float4 v = *(const float4*)(in + i);
    uint32_t h0, l0, h1, l1;
    split2h(v.x, v.y, h0, l0);
    split2h(v.z, v.w, h1, l1);
    *(uint32_t*)(hi + i)     = h0;  *(uint32_t*)(hi + i + 2) = h1;
    *(uint32_t*)(lo + i)     = l0;  *(uint32_t*)(lo + i + 2) = l1;
}

__global__ void cvt_h(const float* __restrict__ in, __half* __restrict__ out, int n) {
    int i = (blockIdx.x * blockDim.x + threadIdx.x) * 4;
    if (i >= n) return;
    float4 v = *(const float4*)(in + i);
    *(uint32_t*)(out + i)     = pack_h2(v.x, v.y);
    *(uint32_t*)(out + i + 2) = pack_h2(v.z, v.w);
}

// ---------------------------------------------------------------------------
// fp16x2 GEMM via mma.sync: C[M,N] = (Ah+Al)[M,K] * B[N,K]^T, fp32 accum.
// A split 2-term fp16, B single fp16. 128x128x32 tile, 256 threads.
// MODE 0: fp32 C.  MODE 1: rope+0.125+split -> H/L (Q).
// MODE 2: rope -> H (K).  MODE 3: -> H (V).
// ---------------------------------------------------------------------------
#define GK       1024
#define BK       32
#define NKC      (GK / BK)
#define TILE8KB  8192
#define STAGE_B  (3 * TILE8KB)     // Ah, Al, B
#define GSMEM    (2 * STAGE_B)     // 48 KB

template<int MODE>
__global__ void __launch_bounds__(256, 1)
gemm_f16x2(const __half* __restrict__ Ah, const __half* __restrict__ Al,
           const __half* __restrict__ B,
           float* __restrict__ C,
           __half* __restrict__ H, __half* __restrict__ L,
           const int* __restrict__ pos) {
    extern __shared__ char sm[];
    const int tid  = threadIdx.x;
    const int lane = tid & 31;
    const int warp = tid >> 5;
    const int wm   = warp & 1;
    const int wn   = warp >> 1;
    const int bm   = blockIdx.y * 128;
    const int bn   = blockIdx.x * 128;

    const __half* srcs[3] = {Ah, Al, B};

    auto load_stage = [&](int kt, int buf) {
        const int koff = kt * BK;
        char* sbase = sm + buf * STAGE_B;
        #pragma unroll
        for (int mtx = 0; mtx < 3; mtx++) {
            const __half* src = srcs[mtx];
            const int rbase = (mtx < 2) ? bm : bn;
            char* stile = sbase + mtx * TILE8KB;
            #pragma unroll
            for (int j = 0; j < 2; j++) {
                int qi  = tid + j * 256;
                int row = qi >> 2, q = qi & 3;
                int pq  = q ^ (row & 3);
                uint32_t sa = smem_u32(stile + row * 64 + pq * 16);
                const void* ga = src + (size_t)(rbase + row) * GK + koff + q * 8;
                CP_ASYNC16(sa, ga);
            }
        }
    };

    float d[4][4][4];
    #pragma unroll
    for (int i = 0; i < 4; i++)
        #pragma unroll
        for (int j = 0; j < 4; j++)
            #pragma unroll
            for (int k = 0; k < 4; k++) d[i][j][k] = 0.f;

    load_stage(0, 0);
    CP_COMMIT();

    const int a_row = lane & 15;
    const int a_qs  = lane >> 4;
    const int b_row = ((lane >> 4) & 1) * 8 + (lane & 7);
    const int b_qs  = (lane >> 3) & 1;

    for (int kt = 0; kt < NKC; kt++) {
        if (kt + 1 < NKC) { load_stage(kt + 1, (kt + 1) & 1); CP_COMMIT(); CP_WAIT(1); }
        else              { CP_WAIT(0); }
        __syncthreads();

        char* sbase = sm + (kt & 1) * STAGE_B;
        char* tAh = sbase + 0 * TILE8KB;
        char* tAl = sbase + 1 * TILE8KB;
        char* tB  = sbase + 2 * TILE8KB;

        #pragma unroll
        for (int ks = 0; ks < 2; ks++) {
            uint32_t ah[4][4], al[4][4], bh[4][2];
            #pragma unroll
            for (int mi = 0; mi < 4; mi++) {
                int row = wm * 64 + mi * 16 + a_row;
                int pq  = (ks * 2 + a_qs) ^ (row & 3);
                ldsm4(ah[mi], smem_u32(tAh + row * 64 + pq * 16));
                ldsm4(al[mi], smem_u32(tAl + row * 64 + pq * 16));
            }
            #pragma unroll
            for (int gi = 0; gi < 2; gi++) {
                int row = wn * 32 + gi * 16 + b_row;
                int pq  = (ks * 2 + b_qs) ^ (row & 3);
                uint32_t rh[4];
                ldsm4(rh, smem_u32(tB + row * 64 + pq * 16));
                bh[gi * 2 + 0][0] = rh[0]; bh[gi * 2 + 0][1] = rh[1];
                bh[gi * 2 + 1][0] = rh[2]; bh[gi * 2 + 1][1] = rh[3];
            }
            #pragma unroll
            for (int mi = 0; mi < 4; mi++)
                #pragma unroll
                for (int ni = 0; ni < 4; ni++)
                    mma16816(d[mi][ni], ah[mi], bh[ni]);
            #pragma unroll
            for (int mi = 0; mi < 4; mi++)
                #pragma unroll
                for (int ni = 0; ni < 4; ni++)
                    mma16816(d[mi][ni], al[mi], bh[ni]);
        }
        __syncthreads();
    }

    const int er = lane >> 2;
    const int ec = (lane & 3) * 2;
    if (MODE == 0) {
        #pragma unroll
        for (int mi = 0; mi < 4; mi++) {
            int r0 = bm + wm * 64 + mi * 16 + er;
            #pragma unroll
            for (int ni = 0; ni < 4; ni++) {
                int c0 = bn + wn * 32 + ni * 8 + ec;
                *(float2*)(C + (size_t)r0 * D_MODEL + c0)       = make_float2(d[mi][ni][0], d[mi][ni][1]);
                *(float2*)(C + (size_t)(r0 + 8) * D_MODEL + c0) = make_float2(d[mi][ni][2], d[mi][ni][3]);
            }
        }
    } else {
        #pragma unroll
        for (int ni = 0; ni < 4; ni++) {
            int c0 = bn + wn * 32 + ni * 8 + ec;
            float finv = 0.f;
            if (MODE == 1 || MODE == 2) {
                int i = (c0 & (HDK - 1)) >> 1;
                finv = (float)exp(-(double)i * (1.0 / 32.0) * 9.210340371976184);
            }
            #pragma unroll
            for (int mi = 0; mi < 4; mi++) {
                int r0 = bm + wm * 64 + mi * 16 + er;
                #pragma unroll
                for (int half = 0; half < 2; half++) {
                    int r = r0 + half * 8;
                    float v0 = d[mi][ni][half * 2], v1 = d[mi][ni][half * 2 + 1];
                    if (MODE == 1 || MODE == 2) {
                        float sn, cs;
                        sincosf((float)pos[r] * finv, &sn, &cs);
                        float e = v0 * cs - v1 * sn;
                        float o = v0 * sn + v1 * cs;
                        if (MODE == 1) { e *= 0.125f; o *= 0.125f; }
                        v0 = e; v1 = o;
                    }
                    if (MODE == 1) {
                        uint32_t hw, lw;
                        split2h(v0, v1, hw, lw);
                        *(uint32_t*)(H + (size_t)r * D_MODEL + c0) = hw;
                        *(uint32_t*)(L + (size_t)r * D_MODEL + c0) = lw;
                    } else {
                        *(uint32_t*)(H + (size_t)r * D_MODEL + c0) = pack_h2(v0, v1);
                    }
                }
            }
        }
    }
}

// ---------------------------------------------------------------------------
// Flash attention (causal), mma.sync fp16x2.
// Q split 2-term; K, V single fp16; P split 2-term in-register.
// smem: Qh,Ql (8KB each) + 2 stages x {K,V} (16KB/stage) = 48KB
// ---------------------------------------------------------------------------
#define QS_B      8192
#define ASTAGE_B  (2 * QS_B)
#define ATT_SMEM  (2 * QS_B + 2 * ASTAGE_B)

__global__ void __launch_bounds__(128)
attn_mma(const __half* __restrict__ qh, const __half* __restrict__ ql,
         const __half* __restrict__ kh, const __half* __restrict__ vh,
         __half* __restrict__ oh, __half* __restrict__ ol) {
    extern __shared__ char sm[];
    const int tid  = threadIdx.x;
    const int lane = tid & 31;
    const int warp = tid >> 5;
    const int h    = blockIdx.y;
    const int qi   = gridDim.x - 1 - blockIdx.x;
    const int q0   = qi * 64;
    const int ntiles = qi + 1;
    const int cbase  = h * HDK;

    char* Qh_t = sm;
    char* Ql_t = sm + QS_B;

    #pragma unroll
    for (int j = 0; j < 4; j++) {
        int qq  = tid + j * 128;
        int row = qq >> 3, q = qq & 7;
        int pq  = q ^ (row & 7);
        CP_ASYNC16(smem_u32(Qh_t + row * 128 + pq * 16),
                   qh + (size_t)(q0 + row) * D_MODEL + cbase + q * 8);
        CP_ASYNC16(smem_u32(Ql_t + row * 128 + pq * 16),
                   ql + (size_t)(q0 + row) * D_MODEL + cbase + q * 8);
    }

    const __half* kvsrc[2] = {kh, vh};
    auto load_kv = [&](int jt, int buf) {
        int n0 = jt * 64;
        char* sb = sm + 2 * QS_B + buf * ASTAGE_B;
        #pragma unroll
        for (int m = 0; m < 2; m++) {
            char* tile = sb + m * QS_B;
            #pragma unroll
            for (int j = 0; j < 4; j++) {
                int qq  = tid + j * 128;
                int row = qq >> 3, q = qq & 7;
                int pq  = q ^ (row & 7);
                CP_ASYNC16(smem_u32(tile + row * 128 + pq * 16),
                           kvsrc[m] + (size_t)(n0 + row) * D_MODEL + cbase + q * 8);
            }
        }
    };

    load_kv(0, 0);
    CP_COMMIT();

    uint32_t qfh[4][4], qfl[4][4];
    float o[8][4];
    #pragma unroll
    for (int f = 0; f < 8; f++)
        #pragma unroll
        for (int k = 0; k < 4; k++) o[f][k] = 0.f;
    float m0 = -1e30f, m1 = -1e30f, l0 = 0.f, l1 = 0.f;
    const int g = lane >> 2;

    for (int jt = 0; jt < ntiles; jt++) {
        if (jt + 1 < ntiles) { load_kv(jt + 1, (jt + 1) & 1); CP_COMMIT(); CP_WAIT(1); }
        else                 { CP_WAIT(0); }
        __syncthreads();

        if (jt == 0) {
            #pragma unroll
            for (int ks = 0; ks < 4; ks++) {
                int row = warp * 16 + (lane & 15);
                int aq  = ks * 2 + (lane >> 4);
                int pq  = aq ^ (row & 7);
                ldsm4(qfh[ks], smem_u32(Qh_t + row * 128 + pq * 16));
                ldsm4(qfl[ks], smem_u32(Ql_t + row * 128 + pq * 16));
            }
        }

        char* sb   = sm + 2 * QS_B + (jt & 1) * ASTAGE_B;
        char* K_t  = sb;
        char* V_t  = sb + QS_B;

        // ---- S = (Q/8) K^T, fp16x2 ----
        float s[8][4];
        #pragma unroll
        for (int f = 0; f < 8; f++)
            #pragma unroll
            for (int k = 0; k < 4; k++) s[f][k] = 0.f;

        #pragma unroll
        for (int ks = 0; ks < 4; ks++) {
            uint32_t rk[4][4];
            #pragma unroll
            for (int gi = 0; gi < 4; gi++) {
                int brow = gi * 16 + ((lane >> 4) & 1) * 8 + (lane & 7);
                int bq   = ks * 2 + ((lane >> 3) & 1);
                int pq   = bq ^ (brow & 7);
                ldsm4(rk[gi], smem_u32(K_t + brow * 128 + pq * 16));
            }
            #pragma unroll
            for (int gi = 0; gi < 4; gi++) {
                mma16816(s[gi * 2],     qfh[ks], rk[gi]);
                mma16816(s[gi * 2 + 1], qfh[ks], rk[gi] + 2);
            }
            #pragma unroll
            for (int gi = 0; gi < 4; gi++) {
                mma16816(s[gi * 2],     qfl[ks], rk[gi]);
                mma16816(s[gi * 2 + 1], qfl[ks], rk[gi] + 2);
            }
        }

        // ---- causal mask (diagonal tile only) ----
        if (jt == ntiles - 1) {
            int lr0 = warp * 16 + g, lr1 = lr0 + 8;
            #pragma unroll
            for (int f = 0; f < 8; f++) {
                int c0 = f * 8 + (lane & 3) * 2;
                if (c0     > lr0) s[f][0] = -1e30f;
                if (c0 + 1 > lr0) s[f][1] = -1e30f;
                if (c0     > lr1) s[f][2] = -1e30f;
                if (c0 + 1 > lr1) s[f][3] = -1e30f;
            }
        }

        // ---- online softmax ----
        float mx0 = -1e30f, mx1 = -1e30f;
        #pragma unroll
        for (int f = 0; f < 8; f++) {
            mx0 = fmaxf(mx0, fmaxf(s[f][0], s[f][1]));
            mx1 = fmaxf(mx1, fmaxf(s[f][2], s[f][3]));
        }
        mx0 = fmaxf(mx0, __shfl_xor_sync(0xffffffffu, mx0, 1));
        mx0 = fmaxf(mx0, __shfl_xor_sync(0xffffffffu, mx0, 2));
        mx1 = fmaxf(mx1, __shfl_xor_sync(0xffffffffu, mx1, 1));
        mx1 = fmaxf(mx1, __shfl_xor_sync(0xffffffffu, mx1, 2));

        float mn0 = fmaxf(m0, mx0), mn1 = fmaxf(m1, mx1);
        float cr0 = __expf(m0 - mn0), cr1 = __expf(m1 - mn1);
        float sum0 = 0.f, sum1 = 0.f;
        #pragma unroll
        for (int f = 0; f < 8; f++) {
            s[f][0] = __expf(s[f][0] - mn0);
            s[f][1] = __expf(s[f][1] - mn0);
            s[f][2] = __expf(s[f][2] - mn1);
            s[f][3] = __expf(s[f][3] - mn1);
            sum0 += s[f][0] + s[f][1];
            sum1 += s[f][2] + s[f][3];
        }
        sum0 += __shfl_xor_sync(0xffffffffu, sum0, 1);
        sum0 += __shfl_xor_sync(0xffffffffu, sum0, 2);
        sum1 += __shfl_xor_sync(0xffffffffu, sum1, 1);
        sum1 += __shfl_xor_sync(0xffffffffu, sum1, 2);
        m0 = mn0; m1 = mn1;
        l0 = l0 * cr0 + sum0;
        l1 = l1 * cr1 + sum1;
        #pragma unroll
        for (int f = 0; f < 8; f++) {
            o[f][0] *= cr0; o[f][1] *= cr0;
            o[f][2] *= cr1; o[f][3] *= cr1;
        }

        // ---- O += P V, fp16x2 ----
        #pragma unroll
        for (int ks2 = 0; ks2 < 4; ks2++) {
            const int f0 = ks2 * 2, f1 = f0 + 1;
            uint32_t pah[4], pal[4];
            split2h(s[f0][0], s[f0][1], pah[0], pal[0]);
            split2h(s[f0][2], s[f0][3], pah[1], pal[1]);
            split2h(s[f1][0], s[f1][1], pah[2], pal[2]);
            split2h(s[f1][2], s[f1][3], pah[3], pal[3]);

            int vrow = ks2 * 16 + ((lane >> 3) & 1) * 8 + (lane & 7);
            uint32_t bv[4][4];
            #pragma unroll
            for (int nvp = 0; nvp < 4; nvp++) {
                int vq = nvp * 2 + (lane >> 4);
                int pq = vq ^ (vrow & 7);
                ldsm4t(bv[nvp], smem_u32(V_t + vrow * 128 + pq * 16));
            }
            #pragma unroll
            for (int nvp = 0; nvp < 4; nvp++) {
                mma16816(o[nvp * 2],     pah, bv[nvp]);
                mma16816(o[nvp * 2 + 1], pah, bv[nvp] + 2);
            }
            #pragma unroll
            for (int nvp = 0; nvp < 4; nvp++) {
                mma16816(o[nvp * 2],     pal, bv[nvp]);
                mma16816(o[nvp * 2 + 1], pal, bv[nvp] + 2);
            }
        }
        __syncthreads();
    }

    // ---- epilogue: normalize, split to fp16 hi/lo, store ----
    float inv0 = 1.f / l0, inv1 = 1.f / l1;
    int row0 = q0 + warp * 16 + g;
    int colb = cbase + (lane & 3) * 2;
    #pragma unroll
    for (int f = 0; f < 8; f++) {
        int c = colb + f * 8;
        uint32_t hw, lw;
        split2h(o[f][0] * inv0, o[f][1] * inv0, hw, lw);
        *(uint32_t*)(oh + (size_t)row0 * D_MODEL + c) = hw;
        *(uint32_t*)(ol + (size_t)row0 * D_MODEL + c) = lw;
        split2h(o[f][2] * inv1, o[f][3] * inv1, hw, lw);
        *(uint32_t*)(oh + (size_t)(row0 + 8) * D_MODEL + c) = hw;
        *(uint32_t*)(ol + (size_t)(row0 + 8) * D_MODEL + c) = lw;
    }
}

// ---------------------------------------------------------------------------
extern "C" void kernel_launch(void* const* d_in, const int* in_sizes, int n_in,
                              void* d_out, int out_size) {
    const float* x   = (const float*)d_in[0];
    const int*   pos = (const int*)d_in[1];
    const float* Wq  = (const float*)d_in[2];
    const float* Wk  = (const float*)d_in[3];
    const float* Wv  = (const float*)d_in[4];
    const float* Wo  = (const float*)d_in[5];
    float* out = (float*)d_out;

    __half *xh, *xl, *ah, *al, *qhp, *qlp, *khp, *vhp;
    __half *wq, *wk, *wv, *wo;
    cudaGetSymbolAddress((void**)&xh, g_xh);   cudaGetSymbolAddress((void**)&xl, g_xl);
    cudaGetSymbolAddress((void**)&ah, g_ah);   cudaGetSymbolAddress((void**)&al, g_al);
    cudaGetSymbolAddress((void**)&qhp, g_qh);  cudaGetSymbolAddress((void**)&qlp, g_ql);
    cudaGetSymbolAddress((void**)&khp, g_kh);  cudaGetSymbolAddress((void**)&vhp, g_vh);
    cudaGetSymbolAddress((void**)&wq, g_wq);   cudaGetSymbolAddress((void**)&wk, g_wk);
    cudaGetSymbolAddress((void**)&wv, g_wv);   cudaGetSymbolAddress((void**)&wo, g_wo);

    cudaFuncSetAttribute(gemm_f16x2<0>, cudaFuncAttributeMaxDynamicSharedMemorySize, GSMEM);
    cudaFuncSetAttribute(gemm_f16x2<1>, cudaFuncAttributeMaxDynamicSharedMemorySize, GSMEM);
    cudaFuncSetAttribute(gemm_f16x2<2>, cudaFuncAttributeMaxDynamicSharedMemorySize, GSMEM);
    cudaFuncSetAttribute(gemm_f16x2<3>, cudaFuncAttributeMaxDynamicSharedMemorySize, GSMEM);
    cudaFuncSetAttribute(attn_mma, cudaFuncAttributeMaxDynamicSharedMemorySize, ATT_SMEM);

    const int nx = S_LEN * D_MODEL;
    const int nw = D_MODEL * D_MODEL;
    split_h<<<nx / 1024, 256>>>(x, xh, xl, nx);
    cvt_h<<<nw / 1024, 256>>>(Wq, wq, nw);
    cvt_h<<<nw / 1024, 256>>>(Wk, wk, nw);
    cvt_h<<<nw / 1024, 256>>>(Wv, wv, nw);
    cvt_h<<<nw / 1024, 256>>>(Wo, wo, nw);

    dim3 gproj(D_MODEL / 128, S_LEN / 128);
    gemm_f16x2<1><<<gproj, 256, GSMEM>>>(xh, xl, wq, nullptr, qhp, qlp, pos);
    gemm_f16x2<2><<<gproj, 256, GSMEM>>>(xh, xl, wk, nullptr, khp, nullptr, pos);
    gemm_f16x2<3><<<gproj, 256, GSMEM>>>(xh, xl, wv, nullptr, vhp, nullptr, nullptr);

    dim3 gattn(S_LEN / 64, NHEAD);
    attn_mma<<<gattn, 128, ATT_SMEM>>>(qhp, qlp, khp, vhp, ah, al);

    gemm_f16x2<0><<<gproj, 256, GSMEM>>>(ah, al, wo, out, nullptr, nullptr, nullptr);
}

// round 10
// speedup vs baseline: 6.7671x; 1.6904x over previous
#include <cuda_runtime.h>
#include <cuda_fp16.h>
#include <stdint.h>
#include <math.h>

#define S_LEN 4096
#define D_MODEL 1024
#define NHEAD 16
#define HDK 64

// ---------------------------------------------------------------------------
// Scratch (__device__ globals; allocation-free rule)
// ---------------------------------------------------------------------------
__device__ __half g_x[S_LEN * D_MODEL];
__device__ __half g_a[S_LEN * D_MODEL];
__device__ __half g_q[S_LEN * D_MODEL];
__device__ __half g_k[S_LEN * D_MODEL];
__device__ __half g_v[S_LEN * D_MODEL];
__device__ __half g_wq[D_MODEL * D_MODEL];
__device__ __half g_wk[D_MODEL * D_MODEL];
__device__ __half g_wv[D_MODEL * D_MODEL];
__device__ __half g_wo[D_MODEL * D_MODEL];

// ---------------------------------------------------------------------------
// Portable (sm_80+) tensor-core primitives, fp16
// ---------------------------------------------------------------------------
__device__ __forceinline__ uint32_t smem_u32(const void* p) {
    uint32_t a;
    asm("{ .reg .u64 t; cvta.to.shared.u64 t, %1; cvt.u32.u64 %0, t; }"
        : "=r"(a) : "l"(p));
    return a;
}

__device__ __forceinline__ void ldsm4(uint32_t* r, uint32_t addr) {
    asm volatile("ldmatrix.sync.aligned.m8n8.x4.shared.b16 {%0,%1,%2,%3}, [%4];"
        : "=r"(r[0]), "=r"(r[1]), "=r"(r[2]), "=r"(r[3]) : "r"(addr));
}

__device__ __forceinline__ void ldsm4t(uint32_t* r, uint32_t addr) {
    asm volatile("ldmatrix.sync.aligned.m8n8.x4.trans.shared.b16 {%0,%1,%2,%3}, [%4];"
        : "=r"(r[0]), "=r"(r[1]), "=r"(r[2]), "=r"(r[3]) : "r"(addr));
}

__device__ __forceinline__ void mma16816(float* d, const uint32_t* a, const uint32_t* b) {
    asm volatile(
        "mma.sync.aligned.m16n8k16.row.col.f32.f16.f16.f32 "
        "{%0,%1,%2,%3}, {%4,%5,%6,%7}, {%8,%9}, {%0,%1,%2,%3};"
        : "+f"(d[0]), "+f"(d[1]), "+f"(d[2]), "+f"(d[3])
        : "r"(a[0]), "r"(a[1]), "r"(a[2]), "r"(a[3]), "r"(b[0]), "r"(b[1]));
}

#define CP_ASYNC16(sa, ga) \
    asm volatile("cp.async.cg.shared.global [%0], [%1], 16;" :: "r"(sa), "l"(ga))
#define CP_COMMIT()  asm volatile("cp.async.commit_group;")
#define CP_WAIT(N)   asm volatile("cp.async.wait_group %0;" :: "n"(N))

__device__ __forceinline__ uint32_t pack_h2(float a, float b) {
    __half2 hv; hv.x = __float2half_rn(a); hv.y = __float2half_rn(b);
    return *reinterpret_cast<uint32_t*>(&hv);
}

// ---------------------------------------------------------------------------
// fp32 -> fp16 convert
// ---------------------------------------------------------------------------
__global__ void cvt_h(const float* __restrict__ in, __half* __restrict__ out, int n) {
    int i = (blockIdx.x * blockDim.x + threadIdx.x) * 4;
    if (i >= n) return;
    float4 v = *(const float4*)(in + i);
    *(uint32_t*)(out + i)     = pack_h2(v.x, v.y);
    *(uint32_t*)(out + i + 2) = pack_h2(v.z, v.w);
}

// ---------------------------------------------------------------------------
// fp16 GEMM via mma.sync: C[M,N] = A[M,K] * B[N,K]^T, fp32 accum.
// 128x128x32 CTA tile, 256 threads, warps 2m x 4n.
// MODE 0: fp32 C.  MODE 1: rope+0.125 -> H (Q).  MODE 2: rope -> H (K).
// MODE 3: -> H (V).
// ---------------------------------------------------------------------------
#define GK       1024
#define BK       32
#define NKC      (GK / BK)
#define TILE8KB  8192
#define STAGE_B  (2 * TILE8KB)     // A, B
#define GSMEM    (2 * STAGE_B)     // 32 KB

template<int MODE>
__global__ void __launch_bounds__(256, 2)
gemm_f16(const __half* __restrict__ A, const __half* __restrict__ B,
         float* __restrict__ C, __half* __restrict__ H,
         const int* __restrict__ pos) {
    extern __shared__ char sm[];
    const int tid  = threadIdx.x;
    const int lane = tid & 31;
    const int warp = tid >> 5;
    const int wm   = warp & 1;
    const int wn   = warp >> 1;
    const int bm   = blockIdx.y * 128;
    const int bn   = blockIdx.x * 128;

    const __half* srcs[2] = {A, B};

    auto load_stage = [&](int kt, int buf) {
        const int koff = kt * BK;
        char* sbase = sm + buf * STAGE_B;
        #pragma unroll
        for (int mtx = 0; mtx < 2; mtx++) {
            const __half* src = srcs[mtx];
            const int rbase = (mtx == 0) ? bm : bn;
            char* stile = sbase + mtx * TILE8KB;
            #pragma unroll
            for (int j = 0; j < 2; j++) {
                int qi  = tid + j * 256;
                int row = qi >> 2, q = qi & 3;
                int pq  = q ^ (row & 3);
                uint32_t sa = smem_u32(stile + row * 64 + pq * 16);
                const void* ga = src + (size_t)(rbase + row) * GK + koff + q * 8;
                CP_ASYNC16(sa, ga);
            }
        }
    };

    float d[4][4][4];
    #pragma unroll
    for (int i = 0; i < 4; i++)
        #pragma unroll
        for (int j = 0; j < 4; j++)
            #pragma unroll
            for (int k = 0; k < 4; k++) d[i][j][k] = 0.f;

    load_stage(0, 0);
    CP_COMMIT();

    const int a_row = lane & 15;
    const int a_qs  = lane >> 4;
    const int b_row = ((lane >> 4) & 1) * 8 + (lane & 7);
    const int b_qs  = (lane >> 3) & 1;

    for (int kt = 0; kt < NKC; kt++) {
        if (kt + 1 < NKC) { load_stage(kt + 1, (kt + 1) & 1); CP_COMMIT(); CP_WAIT(1); }
        else              { CP_WAIT(0); }
        __syncthreads();

        char* sbase = sm + (kt & 1) * STAGE_B;
        char* tA = sbase;
        char* tB = sbase + TILE8KB;

        #pragma unroll
        for (int ks = 0; ks < 2; ks++) {
            uint32_t af[4][4], bf[4][2];
            #pragma unroll
            for (int mi = 0; mi < 4; mi++) {
                int row = wm * 64 + mi * 16 + a_row;
                int pq  = (ks * 2 + a_qs) ^ (row & 3);
                ldsm4(af[mi], smem_u32(tA + row * 64 + pq * 16));
            }
            #pragma unroll
            for (int gi = 0; gi < 2; gi++) {
                int row = wn * 32 + gi * 16 + b_row;
                int pq  = (ks * 2 + b_qs) ^ (row & 3);
                uint32_t rh[4];
                ldsm4(rh, smem_u32(tB + row * 64 + pq * 16));
                bf[gi * 2 + 0][0] = rh[0]; bf[gi * 2 + 0][1] = rh[1];
                bf[gi * 2 + 1][0] = rh[2]; bf[gi * 2 + 1][1] = rh[3];
            }
            #pragma unroll
            for (int mi = 0; mi < 4; mi++)
                #pragma unroll
                for (int ni = 0; ni < 4; ni++)
                    mma16816(d[mi][ni], af[mi], bf[ni]);
        }
        __syncthreads();
    }

    const int er = lane >> 2;
    const int ec = (lane & 3) * 2;
    if (MODE == 0) {
        #pragma unroll
        for (int mi = 0; mi < 4; mi++) {
            int r0 = bm + wm * 64 + mi * 16 + er;
            #pragma unroll
            for (int ni = 0; ni < 4; ni++) {
                int c0 = bn + wn * 32 + ni * 8 + ec;
                *(float2*)(C + (size_t)r0 * D_MODEL + c0)       = make_float2(d[mi][ni][0], d[mi][ni][1]);
                *(float2*)(C + (size_t)(r0 + 8) * D_MODEL + c0) = make_float2(d[mi][ni][2], d[mi][ni][3]);
            }
        }
    } else {
        #pragma unroll
        for (int ni = 0; ni < 4; ni++) {
            int c0 = bn + wn * 32 + ni * 8 + ec;
            float finv = 0.f;
            if (MODE == 1 || MODE == 2) {
                int i = (c0 & (HDK - 1)) >> 1;
                finv = (float)exp(-(double)i * (1.0 / 32.0) * 9.210340371976184);
            }
            #pragma unroll
            for (int mi = 0; mi < 4; mi++) {
                int r0 = bm + wm * 64 + mi * 16 + er;
                #pragma unroll
                for (int half = 0; half < 2; half++) {
                    int r = r0 + half * 8;
                    float v0 = d[mi][ni][half * 2], v1 = d[mi][ni][half * 2 + 1];
                    if (MODE == 1 || MODE == 2) {
                        float sn, cs;
                        sincosf((float)pos[r] * finv, &sn, &cs);
                        float e = v0 * cs - v1 * sn;
                        float o = v0 * sn + v1 * cs;
                        if (MODE == 1) { e *= 0.125f; o *= 0.125f; }
                        v0 = e; v1 = o;
                    }
                    *(uint32_t*)(H + (size_t)r * D_MODEL + c0) = pack_h2(v0, v1);
                }
            }
        }
    }
}

// ---------------------------------------------------------------------------
// Flash attention (causal), mma.sync, single fp16 operands, fp32 accum.
// CTA: 1 head x 64 q-rows, 4 warps. kv tiles of 64, double-buffered.
// smem: Q (8KB) + 2 stages x {K,V} (16KB/stage) = 40KB
// ---------------------------------------------------------------------------
#define QS_B      8192
#define ASTAGE_B  (2 * QS_B)
#define ATT_SMEM  (QS_B + 2 * ASTAGE_B)

__global__ void __launch_bounds__(128)
attn_mma(const __half* __restrict__ qg, const __half* __restrict__ kg,
         const __half* __restrict__ vg, __half* __restrict__ og) {
    extern __shared__ char sm[];
    const int tid  = threadIdx.x;
    const int lane = tid & 31;
    const int warp = tid >> 5;
    const int h    = blockIdx.y;
    const int qi   = gridDim.x - 1 - blockIdx.x;   // heavy tiles first
    const int q0   = qi * 64;
    const int ntiles = qi + 1;
    const int cbase  = h * HDK;

    char* Q_t = sm;

    #pragma unroll
    for (int j = 0; j < 4; j++) {
        int qq  = tid + j * 128;
        int row = qq >> 3, q = qq & 7;
        int pq  = q ^ (row & 7);
        CP_ASYNC16(smem_u32(Q_t + row * 128 + pq * 16),
                   qg + (size_t)(q0 + row) * D_MODEL + cbase + q * 8);
    }

    const __half* kvsrc[2] = {kg, vg};
    auto load_kv = [&](int jt, int buf) {
        int n0 = jt * 64;
        char* sb = sm + QS_B + buf * ASTAGE_B;
        #pragma unroll
        for (int m = 0; m < 2; m++) {
            char* tile = sb + m * QS_B;
            #pragma unroll
            for (int j = 0; j < 4; j++) {
                int qq  = tid + j * 128;
                int row = qq >> 3, q = qq & 7;
                int pq  = q ^ (row & 7);
                CP_ASYNC16(smem_u32(tile + row * 128 + pq * 16),
                           kvsrc[m] + (size_t)(n0 + row) * D_MODEL + cbase + q * 8);
            }
        }
    };

    load_kv(0, 0);
    CP_COMMIT();

    uint32_t qf[4][4];
    float o[8][4];
    #pragma unroll
    for (int f = 0; f < 8; f++)
        #pragma unroll
        for (int k = 0; k < 4; k++) o[f][k] = 0.f;
    float m0 = -1e30f, m1 = -1e30f, l0 = 0.f, l1 = 0.f;
    const int g = lane >> 2;

    for (int jt = 0; jt < ntiles; jt++) {
        if (jt + 1 < ntiles) { load_kv(jt + 1, (jt + 1) & 1); CP_COMMIT(); CP_WAIT(1); }
        else                 { CP_WAIT(0); }
        __syncthreads();

        if (jt == 0) {
            #pragma unroll
            for (int ks = 0; ks < 4; ks++) {
                int row = warp * 16 + (lane & 15);
                int aq  = ks * 2 + (lane >> 4);
                int pq  = aq ^ (row & 7);
                ldsm4(qf[ks], smem_u32(Q_t + row * 128 + pq * 16));
            }
        }

        char* sb  = sm + QS_B + (jt & 1) * ASTAGE_B;
        char* K_t = sb;
        char* V_t = sb + QS_B;

        // ---- S = (Q/8) K^T ----
        float s[8][4];
        #pragma unroll
        for (int f = 0; f < 8; f++)
            #pragma unroll
            for (int k = 0; k < 4; k++) s[f][k] = 0.f;

        #pragma unroll
        for (int ks = 0; ks < 4; ks++) {
            uint32_t rk[4][4];
            #pragma unroll
            for (int gi = 0; gi < 4; gi++) {
                int brow = gi * 16 + ((lane >> 4) & 1) * 8 + (lane & 7);
                int bq   = ks * 2 + ((lane >> 3) & 1);
                int pq   = bq ^ (brow & 7);
                ldsm4(rk[gi], smem_u32(K_t + brow * 128 + pq * 16));
            }
            #pragma unroll
            for (int gi = 0; gi < 4; gi++) {
                mma16816(s[gi * 2],     qf[ks], rk[gi]);
                mma16816(s[gi * 2 + 1], qf[ks], rk[gi] + 2);
            }
        }

        // ---- causal mask (diagonal tile only) ----
        if (jt == ntiles - 1) {
            int lr0 = warp * 16 + g, lr1 = lr0 + 8;
            #pragma unroll
            for (int f = 0; f < 8; f++) {
                int c0 = f * 8 + (lane & 3) * 2;
                if (c0     > lr0) s[f][0] = -1e30f;
                if (c0 + 1 > lr0) s[f][1] = -1e30f;
                if (c0     > lr1) s[f][2] = -1e30f;
                if (c0 + 1 > lr1) s[f][3] = -1e30f;
            }
        }

        // ---- online softmax ----
        float mx0 = -1e30f, mx1 = -1e30f;
        #pragma unroll
        for (int f = 0; f < 8; f++) {
            mx0 = fmaxf(mx0, fmaxf(s[f][0], s[f][1]));
            mx1 = fmaxf(mx1, fmaxf(s[f][2], s[f][3]));
        }
        mx0 = fmaxf(mx0, __shfl_xor_sync(0xffffffffu, mx0, 1));
        mx0 = fmaxf(mx0, __shfl_xor_sync(0xffffffffu, mx0, 2));
        mx1 = fmaxf(mx1, __shfl_xor_sync(0xffffffffu, mx1, 1));
        mx1 = fmaxf(mx1, __shfl_xor_sync(0xffffffffu, mx1, 2));

        float mn0 = fmaxf(m0, mx0), mn1 = fmaxf(m1, mx1);
        float cr0 = __expf(m0 - mn0), cr1 = __expf(m1 - mn1);
        float sum0 = 0.f, sum1 = 0.f;
        #pragma unroll
        for (int f = 0; f < 8; f++) {
            s[f][0] = __expf(s[f][0] - mn0);
            s[f][1] = __expf(s[f][1] - mn0);
            s[f][2] = __expf(s[f][2] - mn1);
            s[f][3] = __expf(s[f][3] - mn1);
            sum0 += s[f][0] + s[f][1];
            sum1 += s[f][2] + s[f][3];
        }
        sum0 += __shfl_xor_sync(0xffffffffu, sum0, 1);
        sum0 += __shfl_xor_sync(0xffffffffu, sum0, 2);
        sum1 += __shfl_xor_sync(0xffffffffu, sum1, 1);
        sum1 += __shfl_xor_sync(0xffffffffu, sum1, 2);
        m0 = mn0; m1 = mn1;
        l0 = l0 * cr0 + sum0;
        l1 = l1 * cr1 + sum1;
        #pragma unroll
        for (int f = 0; f < 8; f++) {
            o[f][0] *= cr0; o[f][1] *= cr0;
            o[f][2] *= cr1; o[f][3] *= cr1;
        }

        // ---- O += P V (P single fp16) ----
        #pragma unroll
        for (int ks2 = 0; ks2 < 4; ks2++) {
            const int f0 = ks2 * 2, f1 = f0 + 1;
            uint32_t pa[4];
            pa[0] = pack_h2(s[f0][0], s[f0][1]);
            pa[1] = pack_h2(s[f0][2], s[f0][3]);
            pa[2] = pack_h2(s[f1][0], s[f1][1]);
            pa[3] = pack_h2(s[f1][2], s[f1][3]);

            int vrow = ks2 * 16 + ((lane >> 3) & 1) * 8 + (lane & 7);
            uint32_t bv[4][4];
            #pragma unroll
            for (int nvp = 0; nvp < 4; nvp++) {
                int vq = nvp * 2 + (lane >> 4);
                int pq = vq ^ (vrow & 7);
                ldsm4t(bv[nvp], smem_u32(V_t + vrow * 128 + pq * 16));
            }
            #pragma unroll
            for (int nvp = 0; nvp < 4; nvp++) {
                mma16816(o[nvp * 2],     pa, bv[nvp]);
                mma16816(o[nvp * 2 + 1], pa, bv[nvp] + 2);
            }
        }
        __syncthreads();
    }

    // ---- epilogue: normalize, store single fp16 ----
    float inv0 = 1.f / l0, inv1 = 1.f / l1;
    int row0 = q0 + warp * 16 + g;
    int colb = cbase + (lane & 3) * 2;
    #pragma unroll
    for (int f = 0; f < 8; f++) {
        int c = colb + f * 8;
        *(uint32_t*)(og + (size_t)row0 * D_MODEL + c) =
            pack_h2(o[f][0] * inv0, o[f][1] * inv0);
        *(uint32_t*)(og + (size_t)(row0 + 8) * D_MODEL + c) =
            pack_h2(o[f][2] * inv1, o[f][3] * inv1);
    }
}

// ---------------------------------------------------------------------------
extern "C" void kernel_launch(void* const* d_in, const int* in_sizes, int n_in,
                              void* d_out, int out_size) {
    const float* x   = (const float*)d_in[0];
    const int*   pos = (const int*)d_in[1];
    const float* Wq  = (const float*)d_in[2];
    const float* Wk  = (const float*)d_in[3];
    const float* Wv  = (const float*)d_in[4];
    const float* Wo  = (const float*)d_in[5];
    float* out = (float*)d_out;

    __half *xp, *ap, *qp, *kp, *vp, *wq, *wk, *wv, *wo;
    cudaGetSymbolAddress((void**)&xp, g_x);
    cudaGetSymbolAddress((void**)&ap, g_a);
    cudaGetSymbolAddress((void**)&qp, g_q);
    cudaGetSymbolAddress((void**)&kp, g_k);
    cudaGetSymbolAddress((void**)&vp, g_v);
    cudaGetSymbolAddress((void**)&wq, g_wq);
    cudaGetSymbolAddress((void**)&wk, g_wk);
    cudaGetSymbolAddress((void**)&wv, g_wv);
    cudaGetSymbolAddress((void**)&wo, g_wo);

    cudaFuncSetAttribute(gemm_f16<0>, cudaFuncAttributeMaxDynamicSharedMemorySize, GSMEM);
    cudaFuncSetAttribute(gemm_f16<1>, cudaFuncAttributeMaxDynamicSharedMemorySize, GSMEM);
    cudaFuncSetAttribute(gemm_f16<2>, cudaFuncAttributeMaxDynamicSharedMemorySize, GSMEM);
    cudaFuncSetAttribute(gemm_f16<3>, cudaFuncAttributeMaxDynamicSharedMemorySize, GSMEM);
    cudaFuncSetAttribute(attn_mma, cudaFuncAttributeMaxDynamicSharedMemorySize, ATT_SMEM);

    const int nx = S_LEN * D_MODEL;
    const int nw = D_MODEL * D_MODEL;
    cvt_h<<<nx / 1024, 256>>>(x,  xp, nx);
    cvt_h<<<nw / 1024, 256>>>(Wq, wq, nw);
    cvt_h<<<nw / 1024, 256>>>(Wk, wk, nw);
    cvt_h<<<nw / 1024, 256>>>(Wv, wv, nw);
    cvt_h<<<nw / 1024, 256>>>(Wo, wo, nw);

    dim3 gproj(D_MODEL / 128, S_LEN / 128);
    gemm_f16<1><<<gproj, 256, GSMEM>>>(xp, wq, nullptr, qp, pos);
    gemm_f16<2><<<gproj, 256, GSMEM>>>(xp, wk, nullptr, kp, pos);
    gemm_f16<3><<<gproj, 256, GSMEM>>>(xp, wv, nullptr, vp, nullptr);

    dim3 gattn(S_LEN / 64, NHEAD);
    attn_mma<<<gattn, 128, ATT_SMEM>>>(qp, kp, vp, ap);

    gemm_f16<0><<<gproj, 256, GSMEM>>>(ap, wo, out, nullptr, nullptr);
}

// round 12
// speedup vs baseline: 7.1970x; 1.0635x over previous
#include <cuda_runtime.h>
#include <cuda_fp16.h>
#include <stdint.h>
#include <math.h>

#define S_LEN 4096
#define D_MODEL 1024
#define NHEAD 16
#define HDK 64
// Q pre-scale: (1/sqrt(64)) * log2(e)  -> softmax becomes exp2
#define SCALE_Q 0.1803368801111204f

// ---------------------------------------------------------------------------
// Scratch (__device__ globals; allocation-free rule)
// ---------------------------------------------------------------------------
__device__ __half g_x[S_LEN * D_MODEL];
__device__ __half g_a[S_LEN * D_MODEL];
__device__ __half g_q[S_LEN * D_MODEL];
__device__ __half g_k[S_LEN * D_MODEL];
__device__ __half g_v[S_LEN * D_MODEL];
__device__ __half g_wqkv[3 * D_MODEL * D_MODEL];   // rows: [Wq; Wk; Wv]
__device__ __half g_wo[D_MODEL * D_MODEL];

// ---------------------------------------------------------------------------
// Portable (sm_80+) tensor-core primitives, fp16
// ---------------------------------------------------------------------------
__device__ __forceinline__ uint32_t smem_u32(const void* p) {
    uint32_t a;
    asm("{ .reg .u64 t; cvta.to.shared.u64 t, %1; cvt.u32.u64 %0, t; }"
        : "=r"(a) : "l"(p));
    return a;
}

__device__ __forceinline__ void ldsm4(uint32_t* r, uint32_t addr) {
    asm volatile("ldmatrix.sync.aligned.m8n8.x4.shared.b16 {%0,%1,%2,%3}, [%4];"
        : "=r"(r[0]), "=r"(r[1]), "=r"(r[2]), "=r"(r[3]) : "r"(addr));
}

__device__ __forceinline__ void ldsm4t(uint32_t* r, uint32_t addr) {
    asm volatile("ldmatrix.sync.aligned.m8n8.x4.trans.shared.b16 {%0,%1,%2,%3}, [%4];"
        : "=r"(r[0]), "=r"(r[1]), "=r"(r[2]), "=r"(r[3]) : "r"(addr));
}

__device__ __forceinline__ void mma16816(float* d, const uint32_t* a, const uint32_t* b) {
    asm volatile(
        "mma.sync.aligned.m16n8k16.row.col.f32.f16.f16.f32 "
        "{%0,%1,%2,%3}, {%4,%5,%6,%7}, {%8,%9}, {%0,%1,%2,%3};"
        : "+f"(d[0]), "+f"(d[1]), "+f"(d[2]), "+f"(d[3])
        : "r"(a[0]), "r"(a[1]), "r"(a[2]), "r"(a[3]), "r"(b[0]), "r"(b[1]));
}

#define CP_ASYNC16(sa, ga) \
    asm volatile("cp.async.cg.shared.global [%0], [%1], 16;" :: "r"(sa), "l"(ga))
#define CP_COMMIT()  asm volatile("cp.async.commit_group;")
#define CP_WAIT(N)   asm volatile("cp.async.wait_group %0;" :: "n"(N))

__device__ __forceinline__ uint32_t pack_h2(float a, float b) {
    __half2 hv; hv.x = __float2half_rn(a); hv.y = __float2half_rn(b);
    return *reinterpret_cast<uint32_t*>(&hv);
}

// ---------------------------------------------------------------------------
// fp32 -> fp16 converts
// ---------------------------------------------------------------------------
__global__ void cvt_h(const float* __restrict__ in, __half* __restrict__ out, int n) {
    int i = (blockIdx.x * blockDim.x + threadIdx.x) * 4;
    if (i >= n) return;
    float4 v = *(const float4*)(in + i);
    *(uint32_t*)(out + i)     = pack_h2(v.x, v.y);
    *(uint32_t*)(out + i + 2) = pack_h2(v.z, v.w);
}

// one launch converts Wq,Wk,Wv -> g_wqkv (concat) and Wo -> g_wo
__global__ void cvt_weights(const float* __restrict__ Wq, const float* __restrict__ Wk,
                            const float* __restrict__ Wv, const float* __restrict__ Wo,
                            __half* __restrict__ wqkv, __half* __restrict__ wo) {
    const int nw = D_MODEL * D_MODEL;
    int i = (blockIdx.x * blockDim.x + threadIdx.x) * 4;
    int region = i / nw;          // 0..3
    int off = i - region * nw;
    const float* src = (region == 0) ? Wq : (region == 1) ? Wk : (region == 2) ? Wv : Wo;
    __half* dst = (region < 3) ? (wqkv + region * nw) : wo;
    float4 v = *(const float4*)(src + off);
    *(uint32_t*)(dst + off)     = pack_h2(v.x, v.y);
    *(uint32_t*)(dst + off + 2) = pack_h2(v.z, v.w);
}

// ---------------------------------------------------------------------------
// fp16 GEMM via mma.sync: 128x128x32 tile, 256 threads, warps 2m x 4n.
// gemm_f16: plain fp32 C (O-projection).
// gemm_qkv: N=3072 fused QKV; epilogue region (CTA-uniform) applies
//           rope+SCALE_Q (Q) / rope (K) / passthrough (V).
// ---------------------------------------------------------------------------
#define GK       1024
#define BK       32
#define NKC      (GK / BK)
#define TILE8KB  8192
#define STAGE_B  (2 * TILE8KB)
#define GSMEM    (2 * STAGE_B)     // 32 KB

// -------- shared mainloop body (macro to keep both kernels identical) ------
#define GEMM_MAINLOOP(A_PTR, B_PTR)                                            \
    const __half* srcs[2] = {A_PTR, B_PTR};                                    \
    auto load_stage = [&](int kt, int buf) {                                   \
        const int koff = kt * BK;                                              \
        char* sbase = sm + buf * STAGE_B;                                      \
        _Pragma("unroll")                                                      \
        for (int mtx = 0; mtx < 2; mtx++) {                                    \
            const __half* src = srcs[mtx];                                     \
            const int rbase = (mtx == 0) ? bm : bn;                            \
            char* stile = sbase + mtx * TILE8KB;                               \
            _Pragma("unroll")                                                  \
            for (int j = 0; j < 2; j++) {                                      \
                int qi  = tid + j * 256;                                       \
                int row = qi >> 2, q = qi & 3;                                 \
                int pq  = q ^ (row & 3);                                       \
                uint32_t sa = smem_u32(stile + row * 64 + pq * 16);            \
                const void* ga = src + (size_t)(rbase + row) * GK + koff + q * 8; \
                CP_ASYNC16(sa, ga);                                            \
            }                                                                  \
        }                                                                      \
    };                                                                         \
    float d[4][4][4];                                                          \
    _Pragma("unroll")                                                          \
    for (int i = 0; i < 4; i++)                                                \
        _Pragma("unroll")                                                      \
        for (int j = 0; j < 4; j++)                                            \
            _Pragma("unroll")                                                  \
            for (int k = 0; k < 4; k++) d[i][j][k] = 0.f;                      \
    load_stage(0, 0);                                                          \
    CP_COMMIT();                                                               \
    const int a_row = lane & 15;                                               \
    const int a_qs  = lane >> 4;                                               \
    const int b_row = ((lane >> 4) & 1) * 8 + (lane & 7);                      \
    const int b_qs  = (lane >> 3) & 1;                                         \
    for (int kt = 0; kt < NKC; kt++) {                                         \
        if (kt + 1 < NKC) { load_stage(kt + 1, (kt + 1) & 1); CP_COMMIT(); CP_WAIT(1); } \
        else              { CP_WAIT(0); }                                      \
        __syncthreads();                                                       \
        char* sbase = sm + (kt & 1) * STAGE_B;                                 \
        char* tA = sbase;                                                      \
        char* tB = sbase + TILE8KB;                                            \
        _Pragma("unroll")                                                      \
        for (int ks = 0; ks < 2; ks++) {                                       \
            uint32_t af[4][4], bf[4][2];                                       \
            _Pragma("unroll")                                                  \
            for (int mi = 0; mi < 4; mi++) {                                   \
                int row = wm * 64 + mi * 16 + a_row;                           \
                int pq  = (ks * 2 + a_qs) ^ (row & 3);                         \
                ldsm4(af[mi], smem_u32(tA + row * 64 + pq * 16));              \
            }                                                                  \
            _Pragma("unroll")                                                  \
            for (int gi = 0; gi < 2; gi++) {                                   \
                int row = wn * 32 + gi * 16 + b_row;                           \
                int pq  = (ks * 2 + b_qs) ^ (row & 3);                         \
                uint32_t rh[4];                                                \
                ldsm4(rh, smem_u32(tB + row * 64 + pq * 16));                  \
                bf[gi * 2 + 0][0] = rh[0]; bf[gi * 2 + 0][1] = rh[1];          \
                bf[gi * 2 + 1][0] = rh[2]; bf[gi * 2 + 1][1] = rh[3];          \
            }                                                                  \
            _Pragma("unroll")                                                  \
            for (int mi = 0; mi < 4; mi++)                                     \
                _Pragma("unroll")                                              \
                for (int ni = 0; ni < 4; ni++)                                 \
                    mma16816(d[mi][ni], af[mi], bf[ni]);                       \
        }                                                                      \
        __syncthreads();                                                       \
    }

__global__ void __launch_bounds__(256, 2)
gemm_f16(const __half* __restrict__ A, const __half* __restrict__ B,
         float* __restrict__ C) {
    extern __shared__ char sm[];
    const int tid  = threadIdx.x;
    const int lane = tid & 31;
    const int warp = tid >> 5;
    const int wm   = warp & 1;
    const int wn   = warp >> 1;
    const int bm   = blockIdx.y * 128;
    const int bn   = blockIdx.x * 128;

    GEMM_MAINLOOP(A, B)

    const int er = lane >> 2;
    const int ec = (lane & 3) * 2;
    #pragma unroll
    for (int mi = 0; mi < 4; mi++) {
        int r0 = bm + wm * 64 + mi * 16 + er;
        #pragma unroll
        for (int ni = 0; ni < 4; ni++) {
            int c0 = bn + wn * 32 + ni * 8 + ec;
            *(float2*)(C + (size_t)r0 * D_MODEL + c0)       = make_float2(d[mi][ni][0], d[mi][ni][1]);
            *(float2*)(C + (size_t)(r0 + 8) * D_MODEL + c0) = make_float2(d[mi][ni][2], d[mi][ni][3]);
        }
    }
}

__global__ void __launch_bounds__(256, 2)
gemm_qkv(const __half* __restrict__ A, const __half* __restrict__ Bqkv,
         __half* __restrict__ Q, __half* __restrict__ K, __half* __restrict__ V,
         const int* __restrict__ pos) {
    extern __shared__ char sm[];
    const int tid  = threadIdx.x;
    const int lane = tid & 31;
    const int warp = tid >> 5;
    const int wm   = warp & 1;
    const int wn   = warp >> 1;
    const int bm   = blockIdx.y * 128;
    const int bn   = blockIdx.x * 128;       // 0..2944 within concat N=3072

    GEMM_MAINLOOP(A, Bqkv)

    const int er = lane >> 2;
    const int ec = (lane & 3) * 2;
    const int region = bn >> 10;             // 0=Q, 1=K, 2=V (CTA-uniform)
    __half* H = (region == 0) ? Q : (region == 1) ? K : V;

    #pragma unroll
    for (int ni = 0; ni < 4; ni++) {
        int c0g = bn + wn * 32 + ni * 8 + ec;
        int c0  = c0g & 1023;                // column within the region
        float finv = 0.f;
        if (region < 2) {
            int i = (c0 & (HDK - 1)) >> 1;
            finv = (float)exp(-(double)i * (1.0 / 32.0) * 9.210340371976184);
        }
        #pragma unroll
        for (int mi = 0; mi < 4; mi++) {
            int r0 = bm + wm * 64 + mi * 16 + er;
            #pragma unroll
            for (int half = 0; half < 2; half++) {
                int r = r0 + half * 8;
                float v0 = d[mi][ni][half * 2], v1 = d[mi][ni][half * 2 + 1];
                if (region < 2) {
                    float sn, cs;
                    sincosf((float)pos[r] * finv, &sn, &cs);
                    float e = v0 * cs - v1 * sn;
                    float o = v0 * sn + v1 * cs;
                    if (region == 0) { e *= SCALE_Q; o *= SCALE_Q; }
                    v0 = e; v1 = o;
                }
                *(uint32_t*)(H + (size_t)r * D_MODEL + c0) = pack_h2(v0, v1);
            }
        }
    }
}

// ---------------------------------------------------------------------------
// Flash attention (causal), mma.sync fp16, fp32 accum, exp2-domain softmax.
// CTA: 1 head x 64 q-rows, 4 warps. kv tiles of 64, double-buffered.
// smem: Q (8KB) + 2 stages x {K,V} (16KB/stage) = 40KB; 3 CTAs/SM target.
// ---------------------------------------------------------------------------
#define QS_B      8192
#define ASTAGE_B  (2 * QS_B)
#define ATT_SMEM  (QS_B + 2 * ASTAGE_B)

__global__ void __launch_bounds__(128, 3)
attn_mma(const __half* __restrict__ qg, const __half* __restrict__ kg,
         const __half* __restrict__ vg, __half* __restrict__ og) {
    extern __shared__ char sm[];
    const int tid  = threadIdx.x;
    const int lane = tid & 31;
    const int warp = tid >> 5;
    const int h    = blockIdx.y;
    const int qi   = gridDim.x - 1 - blockIdx.x;   // heavy tiles first
    const int q0   = qi * 64;
    const int ntiles = qi + 1;
    const int cbase  = h * HDK;

    char* Q_t = sm;

    #pragma unroll
    for (int j = 0; j < 4; j++) {
        int qq  = tid + j * 128;
        int row = qq >> 3, q = qq & 7;
        int pq  = q ^ (row & 7);
        CP_ASYNC16(smem_u32(Q_t + row * 128 + pq * 16),
                   qg + (size_t)(q0 + row) * D_MODEL + cbase + q * 8);
    }

    const __half* kvsrc[2] = {kg, vg};
    auto load_kv = [&](int jt, int buf) {
        int n0 = jt * 64;
        char* sb = sm + QS_B + buf * ASTAGE_B;
        #pragma unroll
        for (int m = 0; m < 2; m++) {
            char* tile = sb + m * QS_B;
            #pragma unroll
            for (int j = 0; j < 4; j++) {
                int qq  = tid + j * 128;
                int row = qq >> 3, q = qq & 7;
                int pq  = q ^ (row & 7);
                CP_ASYNC16(smem_u32(tile + row * 128 + pq * 16),
                           kvsrc[m] + (size_t)(n0 + row) * D_MODEL + cbase + q * 8);
            }
        }
    };

    load_kv(0, 0);
    CP_COMMIT();

    uint32_t qf[4][4];
    float o[8][4];
    #pragma unroll
    for (int f = 0; f < 8; f++)
        #pragma unroll
        for (int k = 0; k < 4; k++) o[f][k] = 0.f;
    float m0 = -1e30f, m1 = -1e30f, l0 = 0.f, l1 = 0.f;
    const int g = lane >> 2;

    for (int jt = 0; jt < ntiles; jt++) {
        if (jt + 1 < ntiles) { load_kv(jt + 1, (jt + 1) & 1); CP_COMMIT(); CP_WAIT(1); }
        else                 { CP_WAIT(0); }
        __syncthreads();

        if (jt == 0) {
            #pragma unroll
            for (int ks = 0; ks < 4; ks++) {
                int row = warp * 16 + (lane & 15);
                int aq  = ks * 2 + (lane >> 4);
                int pq  = aq ^ (row & 7);
                ldsm4(qf[ks], smem_u32(Q_t + row * 128 + pq * 16));
            }
        }

        char* sb  = sm + QS_B + (jt & 1) * ASTAGE_B;
        char* K_t = sb;
        char* V_t = sb + QS_B;

        // ---- S = Qs K^T (already in log2 domain) ----
        float s[8][4];
        #pragma unroll
        for (int f = 0; f < 8; f++)
            #pragma unroll
            for (int k = 0; k < 4; k++) s[f][k] = 0.f;

        #pragma unroll
        for (int ks = 0; ks < 4; ks++) {
            uint32_t rk[4][4];
            #pragma unroll
            for (int gi = 0; gi < 4; gi++) {
                int brow = gi * 16 + ((lane >> 4) & 1) * 8 + (lane & 7);
                int bq   = ks * 2 + ((lane >> 3) & 1);
                int pq   = bq ^ (brow & 7);
                ldsm4(rk[gi], smem_u32(K_t + brow * 128 + pq * 16));
            }
            #pragma unroll
            for (int gi = 0; gi < 4; gi++) {
                mma16816(s[gi * 2],     qf[ks], rk[gi]);
                mma16816(s[gi * 2 + 1], qf[ks], rk[gi] + 2);
            }
        }

        // ---- causal mask (diagonal tile only) ----
        if (jt == ntiles - 1) {
            int lr0 = warp * 16 + g, lr1 = lr0 + 8;
            #pragma unroll
            for (int f = 0; f < 8; f++) {
                int c0 = f * 8 + (lane & 3) * 2;
                if (c0     > lr0) s[f][0] = -1e30f;
                if (c0 + 1 > lr0) s[f][1] = -1e30f;
                if (c0     > lr1) s[f][2] = -1e30f;
                if (c0 + 1 > lr1) s[f][3] = -1e30f;
            }
        }

        // ---- online softmax (exp2 domain) ----
        float mx0 = -1e30f, mx1 = -1e30f;
        #pragma unroll
        for (int f = 0; f < 8; f++) {
            mx0 = fmaxf(mx0, fmaxf(s[f][0], s[f][1]));
            mx1 = fmaxf(mx1, fmaxf(s[f][2], s[f][3]));
        }
        mx0 = fmaxf(mx0, __shfl_xor_sync(0xffffffffu, mx0, 1));
        mx0 = fmaxf(mx0, __shfl_xor_sync(0xffffffffu, mx0, 2));
        mx1 = fmaxf(mx1, __shfl_xor_sync(0xffffffffu, mx1, 1));
        mx1 = fmaxf(mx1, __shfl_xor_sync(0xffffffffu, mx1, 2));

        float mn0 = fmaxf(m0, mx0), mn1 = fmaxf(m1, mx1);
        float cr0 = exp2f(m0 - mn0), cr1 = exp2f(m1 - mn1);
        float sum0 = 0.f, sum1 = 0.f;
        #pragma unroll
        for (int f = 0; f < 8; f++) {
            s[f][0] = exp2f(s[f][0] - mn0);
            s[f][1] = exp2f(s[f][1] - mn0);
            s[f][2] = exp2f(s[f][2] - mn1);
            s[f][3] = exp2f(s[f][3] - mn1);
            sum0 += s[f][0] + s[f][1];
            sum1 += s[f][2] + s[f][3];
        }
        sum0 += __shfl_xor_sync(0xffffffffu, sum0, 1);
        sum0 += __shfl_xor_sync(0xffffffffu, sum0, 2);
        sum1 += __shfl_xor_sync(0xffffffffu, sum1, 1);
        sum1 += __shfl_xor_sync(0xffffffffu, sum1, 2);
        m0 = mn0; m1 = mn1;
        l0 = l0 * cr0 + sum0;
        l1 = l1 * cr1 + sum1;
        #pragma unroll
        for (int f = 0; f < 8; f++) {
            o[f][0] *= cr0; o[f][1] *= cr0;
            o[f][2] *= cr1; o[f][3] *= cr1;
        }

        // ---- O += P V ----
        #pragma unroll
        for (int ks2 = 0; ks2 < 4; ks2++) {
            const int f0 = ks2 * 2, f1 = f0 + 1;
            uint32_t pa[4];
            pa[0] = pack_h2(s[f0][0], s[f0][1]);
            pa[1] = pack_h2(s[f0][2], s[f0][3]);
            pa[2] = pack_h2(s[f1][0], s[f1][1]);
            pa[3] = pack_h2(s[f1][2], s[f1][3]);

            int vrow = ks2 * 16 + ((lane >> 3) & 1) * 8 + (lane & 7);
            uint32_t bv[4][4];
            #pragma unroll
            for (int nvp = 0; nvp < 4; nvp++) {
                int vq = nvp * 2 + (lane >> 4);
                int pq = vq ^ (vrow & 7);
                ldsm4t(bv[nvp], smem_u32(V_t + vrow * 128 + pq * 16));
            }
            #pragma unroll
            for (int nvp = 0; nvp < 4; nvp++) {
                mma16816(o[nvp * 2],     pa, bv[nvp]);
                mma16816(o[nvp * 2 + 1], pa, bv[nvp] + 2);
            }
        }
        __syncthreads();
    }

    // ---- epilogue: normalize, store fp16 ----
    float inv0 = 1.f / l0, inv1 = 1.f / l1;
    int row0 = q0 + warp * 16 + g;
    int colb = cbase + (lane & 3) * 2;
    #pragma unroll
    for (int f = 0; f < 8; f++) {
        int c = colb + f * 8;
        *(uint32_t*)(og + (size_t)row0 * D_MODEL + c) =
            pack_h2(o[f][0] * inv0, o[f][1] * inv0);
        *(uint32_t*)(og + (size_t)(row0 + 8) * D_MODEL + c) =
            pack_h2(o[f][2] * inv1, o[f][3] * inv1);
    }
}

// ---------------------------------------------------------------------------
extern "C" void kernel_launch(void* const* d_in, const int* in_sizes, int n_in,
                              void* d_out, int out_size) {
    const float* x   = (const float*)d_in[0];
    const int*   pos = (const int*)d_in[1];
    const float* Wq  = (const float*)d_in[2];
    const float* Wk  = (const float*)d_in[3];
    const float* Wv  = (const float*)d_in[4];
    const float* Wo  = (const float*)d_in[5];
    float* out = (float*)d_out;

    __half *xp, *ap, *qp, *kp, *vp, *wqkv, *wo;
    cudaGetSymbolAddress((void**)&xp, g_x);
    cudaGetSymbolAddress((void**)&ap, g_a);
    cudaGetSymbolAddress((void**)&qp, g_q);
    cudaGetSymbolAddress((void**)&kp, g_k);
    cudaGetSymbolAddress((void**)&vp, g_v);
    cudaGetSymbolAddress((void**)&wqkv, g_wqkv);
    cudaGetSymbolAddress((void**)&wo, g_wo);

    cudaFuncSetAttribute(gemm_f16,  cudaFuncAttributeMaxDynamicSharedMemorySize, GSMEM);
    cudaFuncSetAttribute(gemm_qkv,  cudaFuncAttributeMaxDynamicSharedMemorySize, GSMEM);
    cudaFuncSetAttribute(attn_mma,  cudaFuncAttributeMaxDynamicSharedMemorySize, ATT_SMEM);

    const int nx = S_LEN * D_MODEL;
    const int nw = D_MODEL * D_MODEL;
    cvt_h<<<nx / 1024, 256>>>(x, xp, nx);
    cvt_weights<<<(4 * nw) / 1024, 256>>>(Wq, Wk, Wv, Wo, wqkv, wo);

    dim3 gqkv(3 * D_MODEL / 128, S_LEN / 128);   // (24, 32) = 768 CTAs
    gemm_qkv<<<gqkv, 256, GSMEM>>>(xp, wqkv, qp, kp, vp, pos);

    dim3 gattn(S_LEN / 64, NHEAD);               // (64, 16)
    attn_mma<<<gattn, 128, ATT_SMEM>>>(qp, kp, vp, ap);

    dim3 gproj(D_MODEL / 128, S_LEN / 128);      // (8, 32)
    gemm_f16<<<gproj, 256, GSMEM>>>(ap, wo, out);
}

// round 13
// speedup vs baseline: 7.4335x; 1.0329x over previous
#include <cuda_runtime.h>
#include <cuda_fp16.h>
#include <stdint.h>
#include <math.h>

#define S_LEN 4096
#define D_MODEL 1024
#define NHEAD 16
#define HDK 64
// Q pre-scale: (1/sqrt(64)) * log2(e)  -> softmax becomes exp2
#define SCALE_Q 0.1803368801111204f

// ---------------------------------------------------------------------------
// Scratch (__device__ globals; allocation-free rule)
// ---------------------------------------------------------------------------
__device__ __half g_x[S_LEN * D_MODEL];
__device__ __half g_a[S_LEN * D_MODEL];
__device__ __half g_q[S_LEN * D_MODEL];
__device__ __half g_k[S_LEN * D_MODEL];
__device__ __half g_v[S_LEN * D_MODEL];
__device__ __half g_wqkv[3 * D_MODEL * D_MODEL];   // rows: [Wq; Wk; Wv]
__device__ __half g_wo[D_MODEL * D_MODEL];

// ---------------------------------------------------------------------------
// Portable (sm_80+) tensor-core primitives, fp16
// ---------------------------------------------------------------------------
__device__ __forceinline__ uint32_t smem_u32(const void* p) {
    uint32_t a;
    asm("{ .reg .u64 t; cvta.to.shared.u64 t, %1; cvt.u32.u64 %0, t; }"
        : "=r"(a) : "l"(p));
    return a;
}

__device__ __forceinline__ void ldsm4(uint32_t* r, uint32_t addr) {
    asm volatile("ldmatrix.sync.aligned.m8n8.x4.shared.b16 {%0,%1,%2,%3}, [%4];"
        : "=r"(r[0]), "=r"(r[1]), "=r"(r[2]), "=r"(r[3]) : "r"(addr));
}

__device__ __forceinline__ void ldsm4t(uint32_t* r, uint32_t addr) {
    asm volatile("ldmatrix.sync.aligned.m8n8.x4.trans.shared.b16 {%0,%1,%2,%3}, [%4];"
        : "=r"(r[0]), "=r"(r[1]), "=r"(r[2]), "=r"(r[3]) : "r"(addr));
}

__device__ __forceinline__ void mma16816(float* d, const uint32_t* a, const uint32_t* b) {
    asm volatile(
        "mma.sync.aligned.m16n8k16.row.col.f32.f16.f16.f32 "
        "{%0,%1,%2,%3}, {%4,%5,%6,%7}, {%8,%9}, {%0,%1,%2,%3};"
        : "+f"(d[0]), "+f"(d[1]), "+f"(d[2]), "+f"(d[3])
        : "r"(a[0]), "r"(a[1]), "r"(a[2]), "r"(a[3]), "r"(b[0]), "r"(b[1]));
}

#define CP_ASYNC16(sa, ga) \
    asm volatile("cp.async.cg.shared.global [%0], [%1], 16;" :: "r"(sa), "l"(ga))
#define CP_COMMIT()  asm volatile("cp.async.commit_group;")
#define CP_WAIT(N)   asm volatile("cp.async.wait_group %0;" :: "n"(N))

#define EX2_F16X2(d, a) \
    asm volatile("ex2.approx.f16x2 %0, %1;" : "=r"(d) : "r"(a))

__device__ __forceinline__ uint32_t pack_h2(float a, float b) {
    __half2 hv; hv.x = __float2half_rn(a); hv.y = __float2half_rn(b);
    return *reinterpret_cast<uint32_t*>(&hv);
}

// ---------------------------------------------------------------------------
// fp32 -> fp16 converts
// ---------------------------------------------------------------------------
__global__ void cvt_h(const float* __restrict__ in, __half* __restrict__ out, int n) {
    int i = (blockIdx.x * blockDim.x + threadIdx.x) * 4;
    if (i >= n) return;
    float4 v = *(const float4*)(in + i);
    *(uint32_t*)(out + i)     = pack_h2(v.x, v.y);
    *(uint32_t*)(out + i + 2) = pack_h2(v.z, v.w);
}

// one launch converts Wq,Wk,Wv -> g_wqkv (concat) and Wo -> g_wo
__global__ void cvt_weights(const float* __restrict__ Wq, const float* __restrict__ Wk,
                            const float* __restrict__ Wv, const float* __restrict__ Wo,
                            __half* __restrict__ wqkv, __half* __restrict__ wo) {
    const int nw = D_MODEL * D_MODEL;
    int i = (blockIdx.x * blockDim.x + threadIdx.x) * 4;
    int region = i / nw;          // 0..3
    int off = i - region * nw;
    const float* src = (region == 0) ? Wq : (region == 1) ? Wk : (region == 2) ? Wv : Wo;
    __half* dst = (region < 3) ? (wqkv + region * nw) : wo;
    float4 v = *(const float4*)(src + off);
    *(uint32_t*)(dst + off)     = pack_h2(v.x, v.y);
    *(uint32_t*)(dst + off + 2) = pack_h2(v.z, v.w);
}

// ---------------------------------------------------------------------------
// fp16 GEMM via mma.sync: 128x128x32 tile, 256 threads, warps 2m x 4n.
// ---------------------------------------------------------------------------
#define GK       1024
#define BK       32
#define NKC      (GK / BK)
#define TILE8KB  8192
#define STAGE_B  (2 * TILE8KB)
#define GSMEM    (2 * STAGE_B)     // 32 KB

// -------- shared mainloop body --------
#define GEMM_MAINLOOP(A_PTR, B_PTR)                                            \
    const __half* srcs[2] = {A_PTR, B_PTR};                                    \
    auto load_stage = [&](int kt, int buf) {                                   \
        const int koff = kt * BK;                                              \
        char* sbase = sm + buf * STAGE_B;                                      \
        _Pragma("unroll")                                                      \
        for (int mtx = 0; mtx < 2; mtx++) {                                    \
            const __half* src = srcs[mtx];                                     \
            const int rbase = (mtx == 0) ? bm : bn;                            \
            char* stile = sbase + mtx * TILE8KB;                               \
            _Pragma("unroll")                                                  \
            for (int j = 0; j < 2; j++) {                                      \
                int qi  = tid + j * 256;                                       \
                int row = qi >> 2, q = qi & 3;                                 \
                int pq  = q ^ (row & 3);                                       \
                uint32_t sa = smem_u32(stile + row * 64 + pq * 16);            \
                const void* ga = src + (size_t)(rbase + row) * GK + koff + q * 8; \
                CP_ASYNC16(sa, ga);                                            \
            }                                                                  \
        }                                                                      \
    };                                                                         \
    float d[4][4][4];                                                          \
    _Pragma("unroll")                                                          \
    for (int i = 0; i < 4; i++)                                                \
        _Pragma("unroll")                                                      \
        for (int j = 0; j < 4; j++)                                            \
            _Pragma("unroll")                                                  \
            for (int k = 0; k < 4; k++) d[i][j][k] = 0.f;                      \
    load_stage(0, 0);                                                          \
    CP_COMMIT();                                                               \
    const int a_row = lane & 15;                                               \
    const int a_qs  = lane >> 4;                                               \
    const int b_row = ((lane >> 4) & 1) * 8 + (lane & 7);                      \
    const int b_qs  = (lane >> 3) & 1;                                         \
    for (int kt = 0; kt < NKC; kt++) {                                         \
        if (kt + 1 < NKC) { load_stage(kt + 1, (kt + 1) & 1); CP_COMMIT(); CP_WAIT(1); } \
        else              { CP_WAIT(0); }                                      \
        __syncthreads();                                                       \
        char* sbase = sm + (kt & 1) * STAGE_B;                                 \
        char* tA = sbase;                                                      \
        char* tB = sbase + TILE8KB;                                            \
        _Pragma("unroll")                                                      \
        for (int ks = 0; ks < 2; ks++) {                                       \
            uint32_t af[4][4], bf[4][2];                                       \
            _Pragma("unroll")                                                  \
            for (int mi = 0; mi < 4; mi++) {                                   \
                int row = wm * 64 + mi * 16 + a_row;                           \
                int pq  = (ks * 2 + a_qs) ^ (row & 3);                         \
                ldsm4(af[mi], smem_u32(tA + row * 64 + pq * 16));              \
            }                                                                  \
            _Pragma("unroll")                                                  \
            for (int gi = 0; gi < 2; gi++) {                                   \
                int row = wn * 32 + gi * 16 + b_row;                           \
                int pq  = (ks * 2 + b_qs) ^ (row & 3);                         \
                uint32_t rh[4];                                                \
                ldsm4(rh, smem_u32(tB + row * 64 + pq * 16));                  \
                bf[gi * 2 + 0][0] = rh[0]; bf[gi * 2 + 0][1] = rh[1];          \
                bf[gi * 2 + 1][0] = rh[2]; bf[gi * 2 + 1][1] = rh[3];          \
            }                                                                  \
            _Pragma("unroll")                                                  \
            for (int mi = 0; mi < 4; mi++)                                     \
                _Pragma("unroll")                                              \
                for (int ni = 0; ni < 4; ni++)                                 \
                    mma16816(d[mi][ni], af[mi], bf[ni]);                       \
        }                                                                      \
        __syncthreads();                                                       \
    }

__global__ void __launch_bounds__(256, 2)
gemm_f16(const __half* __restrict__ A, const __half* __restrict__ B,
         float* __restrict__ C) {
    extern __shared__ char sm[];
    const int tid  = threadIdx.x;
    const int lane = tid & 31;
    const int warp = tid >> 5;
    const int wm   = warp & 1;
    const int wn   = warp >> 1;
    const int bm   = blockIdx.y * 128;
    const int bn   = blockIdx.x * 128;

    GEMM_MAINLOOP(A, B)

    const int er = lane >> 2;
    const int ec = (lane & 3) * 2;
    #pragma unroll
    for (int mi = 0; mi < 4; mi++) {
        int r0 = bm + wm * 64 + mi * 16 + er;
        #pragma unroll
        for (int ni = 0; ni < 4; ni++) {
            int c0 = bn + wn * 32 + ni * 8 + ec;
            *(float2*)(C + (size_t)r0 * D_MODEL + c0)       = make_float2(d[mi][ni][0], d[mi][ni][1]);
            *(float2*)(C + (size_t)(r0 + 8) * D_MODEL + c0) = make_float2(d[mi][ni][2], d[mi][ni][3]);
        }
    }
}

__global__ void __launch_bounds__(256, 2)
gemm_qkv(const __half* __restrict__ A, const __half* __restrict__ Bqkv,
         __half* __restrict__ Q, __half* __restrict__ K, __half* __restrict__ V,
         const int* __restrict__ pos) {
    extern __shared__ char sm[];
    const int tid  = threadIdx.x;
    const int lane = tid & 31;
    const int warp = tid >> 5;
    const int wm   = warp & 1;
    const int wn   = warp >> 1;
    const int bm   = blockIdx.y * 128;
    const int bn   = blockIdx.x * 128;       // 0..2944 within concat N=3072

    GEMM_MAINLOOP(A, Bqkv)

    const int er = lane >> 2;
    const int ec = (lane & 3) * 2;
    const int region = bn >> 10;             // 0=Q, 1=K, 2=V (CTA-uniform)
    __half* H = (region == 0) ? Q : (region == 1) ? K : V;

    #pragma unroll
    for (int ni = 0; ni < 4; ni++) {
        int c0g = bn + wn * 32 + ni * 8 + ec;
        int c0  = c0g & 1023;                // column within the region
        float finv = 0.f;
        if (region < 2) {
            int i = (c0 & (HDK - 1)) >> 1;
            finv = (float)exp(-(double)i * (1.0 / 32.0) * 9.210340371976184);
        }
        #pragma unroll
        for (int mi = 0; mi < 4; mi++) {
            int r0 = bm + wm * 64 + mi * 16 + er;
            #pragma unroll
            for (int half = 0; half < 2; half++) {
                int r = r0 + half * 8;
                float v0 = d[mi][ni][half * 2], v1 = d[mi][ni][half * 2 + 1];
                if (region < 2) {
                    float sn, cs;
                    sincosf((float)pos[r] * finv, &sn, &cs);
                    float e = v0 * cs - v1 * sn;
                    float o = v0 * sn + v1 * cs;
                    if (region == 0) { e *= SCALE_Q; o *= SCALE_Q; }
                    v0 = e; v1 = o;
                }
                *(uint32_t*)(H + (size_t)r * D_MODEL + c0) = pack_h2(v0, v1);
            }
        }
    }
}

// ---------------------------------------------------------------------------
// Flash attention (causal), mma.sync fp16, fp32 accum, exp2-domain softmax.
// Row-sums of P via ones-column MMA; exp via ex2.approx.f16x2.
// CTA: 1 head x 64 q-rows, 4 warps. kv tiles of 64, double-buffered. 40KB smem.
// ---------------------------------------------------------------------------
#define QS_B      8192
#define ASTAGE_B  (2 * QS_B)
#define ATT_SMEM  (QS_B + 2 * ASTAGE_B)

__global__ void __launch_bounds__(128, 3)
attn_mma(const __half* __restrict__ qg, const __half* __restrict__ kg,
         const __half* __restrict__ vg, __half* __restrict__ og) {
    extern __shared__ char sm[];
    const int tid  = threadIdx.x;
    const int lane = tid & 31;
    const int warp = tid >> 5;
    const int h    = blockIdx.y;
    const int qi   = gridDim.x - 1 - blockIdx.x;   // heavy tiles first
    const int q0   = qi * 64;
    const int ntiles = qi + 1;
    const int cbase  = h * HDK;

    char* Q_t = sm;

    #pragma unroll
    for (int j = 0; j < 4; j++) {
        int qq  = tid + j * 128;
        int row = qq >> 3, q = qq & 7;
        int pq  = q ^ (row & 7);
        CP_ASYNC16(smem_u32(Q_t + row * 128 + pq * 16),
                   qg + (size_t)(q0 + row) * D_MODEL + cbase + q * 8);
    }

    const __half* kvsrc[2] = {kg, vg};
    auto load_kv = [&](int jt, int buf) {
        int n0 = jt * 64;
        char* sb = sm + QS_B + buf * ASTAGE_B;
        #pragma unroll
        for (int m = 0; m < 2; m++) {
            char* tile = sb + m * QS_B;
            #pragma unroll
            for (int j = 0; j < 4; j++) {
                int qq  = tid + j * 128;
                int row = qq >> 3, q = qq & 7;
                int pq  = q ^ (row & 7);
                CP_ASYNC16(smem_u32(tile + row * 128 + pq * 16),
                           kvsrc[m] + (size_t)(n0 + row) * D_MODEL + cbase + q * 8);
            }
        }
    };

    load_kv(0, 0);
    CP_COMMIT();

    uint32_t qf[4][4];
    float o[8][4];
    #pragma unroll
    for (int f = 0; f < 8; f++)
        #pragma unroll
        for (int k = 0; k < 4; k++) o[f][k] = 0.f;
    float m0 = -1e30f, m1 = -1e30f, l0 = 0.f, l1 = 0.f;
    const int g = lane >> 2;
    const uint32_t onesb[2] = {0x3C003C00u, 0x3C003C00u};   // half2(1,1) x2

    for (int jt = 0; jt < ntiles; jt++) {
        if (jt + 1 < ntiles) { load_kv(jt + 1, (jt + 1) & 1); CP_COMMIT(); CP_WAIT(1); }
        else                 { CP_WAIT(0); }
        __syncthreads();

        if (jt == 0) {
            #pragma unroll
            for (int ks = 0; ks < 4; ks++) {
                int row = warp * 16 + (lane & 15);
                int aq  = ks * 2 + (lane >> 4);
                int pq  = aq ^ (row & 7);
                ldsm4(qf[ks], smem_u32(Q_t + row * 128 + pq * 16));
            }
        }

        char* sb  = sm + QS_B + (jt & 1) * ASTAGE_B;
        char* K_t = sb;
        char* V_t = sb + QS_B;

        // ---- S = Qs K^T (log2 domain) ----
        float s[8][4];
        #pragma unroll
        for (int f = 0; f < 8; f++)
            #pragma unroll
            for (int k = 0; k < 4; k++) s[f][k] = 0.f;

        #pragma unroll
        for (int ks = 0; ks < 4; ks++) {
            uint32_t rk[4][4];
            #pragma unroll
            for (int gi = 0; gi < 4; gi++) {
                int brow = gi * 16 + ((lane >> 4) & 1) * 8 + (lane & 7);
                int bq   = ks * 2 + ((lane >> 3) & 1);
                int pq   = bq ^ (brow & 7);
                ldsm4(rk[gi], smem_u32(K_t + brow * 128 + pq * 16));
            }
            #pragma unroll
            for (int gi = 0; gi < 4; gi++) {
                mma16816(s[gi * 2],     qf[ks], rk[gi]);
                mma16816(s[gi * 2 + 1], qf[ks], rk[gi] + 2);
            }
        }

        // ---- causal mask (diagonal tile only) ----
        if (jt == ntiles - 1) {
            int lr0 = warp * 16 + g, lr1 = lr0 + 8;
            #pragma unroll
            for (int f = 0; f < 8; f++) {
                int c0 = f * 8 + (lane & 3) * 2;
                if (c0     > lr0) s[f][0] = -1e30f;
                if (c0 + 1 > lr0) s[f][1] = -1e30f;
                if (c0     > lr1) s[f][2] = -1e30f;
                if (c0 + 1 > lr1) s[f][3] = -1e30f;
            }
        }

        // ---- running max (fp32) ----
        float mx0 = -1e30f, mx1 = -1e30f;
        #pragma unroll
        for (int f = 0; f < 8; f++) {
            mx0 = fmaxf(mx0, fmaxf(s[f][0], s[f][1]));
            mx1 = fmaxf(mx1, fmaxf(s[f][2], s[f][3]));
        }
        mx0 = fmaxf(mx0, __shfl_xor_sync(0xffffffffu, mx0, 1));
        mx0 = fmaxf(mx0, __shfl_xor_sync(0xffffffffu, mx0, 2));
        mx1 = fmaxf(mx1, __shfl_xor_sync(0xffffffffu, mx1, 1));
        mx1 = fmaxf(mx1, __shfl_xor_sync(0xffffffffu, mx1, 2));

        float mn0 = fmaxf(m0, mx0), mn1 = fmaxf(m1, mx1);
        float cr0 = exp2f(m0 - mn0), cr1 = exp2f(m1 - mn1);
        m0 = mn0; m1 = mn1;

        // ---- P = exp2(S - mn): fp32 subtract, then f16x2 ex2 (packed) ----
        uint32_t ph[16];
        #pragma unroll
        for (int f = 0; f < 8; f++) {
            uint32_t p0 = pack_h2(s[f][0] - mn0, s[f][1] - mn0);
            uint32_t p1 = pack_h2(s[f][2] - mn1, s[f][3] - mn1);
            EX2_F16X2(ph[2 * f],     p0);
            EX2_F16X2(ph[2 * f + 1], p1);
        }

        // ---- rescale O ----
        #pragma unroll
        for (int f = 0; f < 8; f++) {
            o[f][0] *= cr0; o[f][1] *= cr0;
            o[f][2] *= cr1; o[f][3] *= cr1;
        }

        // ---- O += P V; row-sums via ones-column MMA ----
        float lf[4] = {0.f, 0.f, 0.f, 0.f};
        #pragma unroll
        for (int ks2 = 0; ks2 < 4; ks2++) {
            const uint32_t* pa = &ph[4 * ks2];
            int vrow = ks2 * 16 + ((lane >> 3) & 1) * 8 + (lane & 7);
            uint32_t bv[4][4];
            #pragma unroll
            for (int nvp = 0; nvp < 4; nvp++) {
                int vq = nvp * 2 + (lane >> 4);
                int pq = vq ^ (vrow & 7);
                ldsm4t(bv[nvp], smem_u32(V_t + vrow * 128 + pq * 16));
            }
            #pragma unroll
            for (int nvp = 0; nvp < 4; nvp++) {
                mma16816(o[nvp * 2],     pa, bv[nvp]);
                mma16816(o[nvp * 2 + 1], pa, bv[nvp] + 2);
            }
            mma16816(lf, pa, onesb);
        }
        l0 = l0 * cr0 + lf[0];
        l1 = l1 * cr1 + lf[2];
        __syncthreads();
    }

    // ---- epilogue: normalize, store fp16 ----
    float inv0 = 1.f / l0, inv1 = 1.f / l1;
    int row0 = q0 + warp * 16 + g;
    int colb = cbase + (lane & 3) * 2;
    #pragma unroll
    for (int f = 0; f < 8; f++) {
        int c = colb + f * 8;
        *(uint32_t*)(og + (size_t)row0 * D_MODEL + c) =
            pack_h2(o[f][0] * inv0, o[f][1] * inv0);
        *(uint32_t*)(og + (size_t)(row0 + 8) * D_MODEL + c) =
            pack_h2(o[f][2] * inv1, o[f][3] * inv1);
    }
}

// ---------------------------------------------------------------------------
extern "C" void kernel_launch(void* const* d_in, const int* in_sizes, int n_in,
                              void* d_out, int out_size) {
    const float* x   = (const float*)d_in[0];
    const int*   pos = (const int*)d_in[1];
    const float* Wq  = (const float*)d_in[2];
    const float* Wk  = (const float*)d_in[3];
    const float* Wv  = (const float*)d_in[4];
    const float* Wo  = (const float*)d_in[5];
    float* out = (float*)d_out;

    __half *xp, *ap, *qp, *kp, *vp, *wqkv, *wo;
    cudaGetSymbolAddress((void**)&xp, g_x);
    cudaGetSymbolAddress((void**)&ap, g_a);
    cudaGetSymbolAddress((void**)&qp, g_q);
    cudaGetSymbolAddress((void**)&kp, g_k);
    cudaGetSymbolAddress((void**)&vp, g_v);
    cudaGetSymbolAddress((void**)&wqkv, g_wqkv);
    cudaGetSymbolAddress((void**)&wo, g_wo);

    cudaFuncSetAttribute(gemm_f16,  cudaFuncAttributeMaxDynamicSharedMemorySize, GSMEM);
    cudaFuncSetAttribute(gemm_qkv,  cudaFuncAttributeMaxDynamicSharedMemorySize, GSMEM);
    cudaFuncSetAttribute(attn_mma,  cudaFuncAttributeMaxDynamicSharedMemorySize, ATT_SMEM);

    const int nx = S_LEN * D_MODEL;
    const int nw = D_MODEL * D_MODEL;
    cvt_h<<<nx / 1024, 256>>>(x, xp, nx);
    cvt_weights<<<(4 * nw) / 1024, 256>>>(Wq, Wk, Wv, Wo, wqkv, wo);

    dim3 gqkv(3 * D_MODEL / 128, S_LEN / 128);   // (24, 32) = 768 CTAs
    gemm_qkv<<<gqkv, 256, GSMEM>>>(xp, wqkv, qp, kp, vp, pos);

    dim3 gattn(S_LEN / 64, NHEAD);               // (64, 16)
    attn_mma<<<gattn, 128, ATT_SMEM>>>(qp, kp, vp, ap);

    dim3 gproj(D_MODEL / 128, S_LEN / 128);      // (8, 32)
    gemm_f16<<<gproj, 256, GSMEM>>>(ap, wo, out);
}

// round 14
// speedup vs baseline: 7.4564x; 1.0031x over previous
#include <cuda_runtime.h>
#include <cuda_fp16.h>
#include <stdint.h>
#include <math.h>

#define S_LEN 4096
#define D_MODEL 1024
#define NHEAD 16
#define HDK 64
// Q pre-scale: (1/sqrt(64)) * log2(e)  -> softmax becomes exp2
#define SCALE_Q 0.1803368801111204f

// ---------------------------------------------------------------------------
// Scratch (__device__ globals; allocation-free rule)
// ---------------------------------------------------------------------------
__device__ __half g_x[S_LEN * D_MODEL];
__device__ __half g_a[S_LEN * D_MODEL];
__device__ __half g_q[S_LEN * D_MODEL];
__device__ __half g_k[S_LEN * D_MODEL];
__device__ __half g_v[S_LEN * D_MODEL];
__device__ __half g_wqkv[3 * D_MODEL * D_MODEL];   // rows: [Wq; Wk; Wv]
__device__ __half g_wo[D_MODEL * D_MODEL];

// ---------------------------------------------------------------------------
// Portable (sm_80+) tensor-core primitives, fp16
// ---------------------------------------------------------------------------
__device__ __forceinline__ uint32_t smem_u32(const void* p) {
    uint32_t a;
    asm("{ .reg .u64 t; cvta.to.shared.u64 t, %1; cvt.u32.u64 %0, t; }"
        : "=r"(a) : "l"(p));
    return a;
}

__device__ __forceinline__ void ldsm4(uint32_t* r, uint32_t addr) {
    asm volatile("ldmatrix.sync.aligned.m8n8.x4.shared.b16 {%0,%1,%2,%3}, [%4];"
        : "=r"(r[0]), "=r"(r[1]), "=r"(r[2]), "=r"(r[3]) : "r"(addr));
}

__device__ __forceinline__ void ldsm4t(uint32_t* r, uint32_t addr) {
    asm volatile("ldmatrix.sync.aligned.m8n8.x4.trans.shared.b16 {%0,%1,%2,%3}, [%4];"
        : "=r"(r[0]), "=r"(r[1]), "=r"(r[2]), "=r"(r[3]) : "r"(addr));
}

__device__ __forceinline__ void mma16816(float* d, const uint32_t* a, const uint32_t* b) {
    asm volatile(
        "mma.sync.aligned.m16n8k16.row.col.f32.f16.f16.f32 "
        "{%0,%1,%2,%3}, {%4,%5,%6,%7}, {%8,%9}, {%0,%1,%2,%3};"
        : "+f"(d[0]), "+f"(d[1]), "+f"(d[2]), "+f"(d[3])
        : "r"(a[0]), "r"(a[1]), "r"(a[2]), "r"(a[3]), "r"(b[0]), "r"(b[1]));
}

#define CP_ASYNC16(sa, ga) \
    asm volatile("cp.async.cg.shared.global [%0], [%1], 16;" :: "r"(sa), "l"(ga))
#define CP_COMMIT()  asm volatile("cp.async.commit_group;")
#define CP_WAIT(N)   asm volatile("cp.async.wait_group %0;" :: "n"(N))

#define EX2_F16X2(d, a) \
    asm volatile("ex2.approx.f16x2 %0, %1;" : "=r"(d) : "r"(a))

__device__ __forceinline__ uint32_t pack_h2(float a, float b) {
    __half2 hv; hv.x = __float2half_rn(a); hv.y = __float2half_rn(b);
    return *reinterpret_cast<uint32_t*>(&hv);
}

// ---------------------------------------------------------------------------
// One launch converts x, Wq, Wk, Wv, Wo -> fp16 (x to g_x, W's concat/wo)
// Grid covers 8M elements: region 0 = x (4M), regions 1..4 = weights (1M each)
// ---------------------------------------------------------------------------
__global__ void cvt_all(const float* __restrict__ x,
                        const float* __restrict__ Wq, const float* __restrict__ Wk,
                        const float* __restrict__ Wv, const float* __restrict__ Wo,
                        __half* __restrict__ xo, __half* __restrict__ wqkv,
                        __half* __restrict__ wo) {
    const int nx = S_LEN * D_MODEL;          // 4M
    const int nw = D_MODEL * D_MODEL;        // 1M
    int i = (blockIdx.x * blockDim.x + threadIdx.x) * 4;
    const float* src;
    __half* dst;
    int off;
    if (i < nx) { src = x; dst = xo; off = i; }
    else {
        int j = i - nx;
        int region = j / nw;                 // 0..3
        off = j - region * nw;
        src = (region == 0) ? Wq : (region == 1) ? Wk : (region == 2) ? Wv : Wo;
        dst = (region < 3) ? (wqkv + region * nw) : wo;
    }
    float4 v = *(const float4*)(src + off);
    *(uint32_t*)(dst + off)     = pack_h2(v.x, v.y);
    *(uint32_t*)(dst + off + 2) = pack_h2(v.z, v.w);
}

// ---------------------------------------------------------------------------
// fp16 GEMM via mma.sync: 128x128x32 tile, 256 threads, warps 2m x 4n.
// ---------------------------------------------------------------------------
#define GK       1024
#define BK       32
#define NKC      (GK / BK)
#define TILE8KB  8192
#define STAGE_B  (2 * TILE8KB)
#define GSMEM    (2 * STAGE_B)     // 32 KB

// -------- shared mainloop body --------
#define GEMM_MAINLOOP(A_PTR, B_PTR)                                            \
    const __half* srcs[2] = {A_PTR, B_PTR};                                    \
    auto load_stage = [&](int kt, int buf) {                                   \
        const int koff = kt * BK;                                              \
        char* sbase = sm + buf * STAGE_B;                                      \
        _Pragma("unroll")                                                      \
        for (int mtx = 0; mtx < 2; mtx++) {                                    \
            const __half* src = srcs[mtx];                                     \
            const int rbase = (mtx == 0) ? bm : bn;                            \
            char* stile = sbase + mtx * TILE8KB;                               \
            _Pragma("unroll")                                                  \
            for (int j = 0; j < 2; j++) {                                      \
                int qi  = tid + j * 256;                                       \
                int row = qi >> 2, q = qi & 3;                                 \
                int pq  = q ^ (row & 3);                                       \
                uint32_t sa = smem_u32(stile + row * 64 + pq * 16);            \
                const void* ga = src + (size_t)(rbase + row) * GK + koff + q * 8; \
                CP_ASYNC16(sa, ga);                                            \
            }                                                                  \
        }                                                                      \
    };                                                                         \
    float d[4][4][4];                                                          \
    _Pragma("unroll")                                                          \
    for (int i = 0; i < 4; i++)                                                \
        _Pragma("unroll")                                                      \
        for (int j = 0; j < 4; j++)                                            \
            _Pragma("unroll")                                                  \
            for (int k = 0; k < 4; k++) d[i][j][k] = 0.f;                      \
    load_stage(0, 0);                                                          \
    CP_COMMIT();                                                               \
    const int a_row = lane & 15;                                               \
    const int a_qs  = lane >> 4;                                               \
    const int b_row = ((lane >> 4) & 1) * 8 + (lane & 7);                      \
    const int b_qs  = (lane >> 3) & 1;                                         \
    for (int kt = 0; kt < NKC; kt++) {                                         \
        if (kt + 1 < NKC) { load_stage(kt + 1, (kt + 1) & 1); CP_COMMIT(); CP_WAIT(1); } \
        else              { CP_WAIT(0); }                                      \
        __syncthreads();                                                       \
        char* sbase = sm + (kt & 1) * STAGE_B;                                 \
        char* tA = sbase;                                                      \
        char* tB = sbase + TILE8KB;                                            \
        _Pragma("unroll")                                                      \
        for (int ks = 0; ks < 2; ks++) {                                       \
            uint32_t af[4][4], bf[4][2];                                       \
            _Pragma("unroll")                                                  \
            for (int mi = 0; mi < 4; mi++) {                                   \
                int row = wm * 64 + mi * 16 + a_row;                           \
                int pq  = (ks * 2 + a_qs) ^ (row & 3);                         \
                ldsm4(af[mi], smem_u32(tA + row * 64 + pq * 16));              \
            }                                                                  \
            _Pragma("unroll")                                                  \
            for (int gi = 0; gi < 2; gi++) {                                   \
                int row = wn * 32 + gi * 16 + b_row;                           \
                int pq  = (ks * 2 + b_qs) ^ (row & 3);                         \
                uint32_t rh[4];                                                \
                ldsm4(rh, smem_u32(tB + row * 64 + pq * 16));                  \
                bf[gi * 2 + 0][0] = rh[0]; bf[gi * 2 + 0][1] = rh[1];          \
                bf[gi * 2 + 1][0] = rh[2]; bf[gi * 2 + 1][1] = rh[3];          \
            }                                                                  \
            _Pragma("unroll")                                                  \
            for (int mi = 0; mi < 4; mi++)                                     \
                _Pragma("unroll")                                              \
                for (int ni = 0; ni < 4; ni++)                                 \
                    mma16816(d[mi][ni], af[mi], bf[ni]);                       \
        }                                                                      \
        __syncthreads();                                                       \
    }

__global__ void __launch_bounds__(256, 2)
gemm_f16(const __half* __restrict__ A, const __half* __restrict__ B,
         float* __restrict__ C) {
    extern __shared__ char sm[];
    const int tid  = threadIdx.x;
    const int lane = tid & 31;
    const int warp = tid >> 5;
    const int wm   = warp & 1;
    const int wn   = warp >> 1;
    const int bm   = blockIdx.y * 128;
    const int bn   = blockIdx.x * 128;

    GEMM_MAINLOOP(A, B)

    const int er = lane >> 2;
    const int ec = (lane & 3) * 2;
    #pragma unroll
    for (int mi = 0; mi < 4; mi++) {
        int r0 = bm + wm * 64 + mi * 16 + er;
        #pragma unroll
        for (int ni = 0; ni < 4; ni++) {
            int c0 = bn + wn * 32 + ni * 8 + ec;
            *(float2*)(C + (size_t)r0 * D_MODEL + c0)       = make_float2(d[mi][ni][0], d[mi][ni][1]);
            *(float2*)(C + (size_t)(r0 + 8) * D_MODEL + c0) = make_float2(d[mi][ni][2], d[mi][ni][3]);
        }
    }
}

__global__ void __launch_bounds__(256, 2)
gemm_qkv(const __half* __restrict__ A, const __half* __restrict__ Bqkv,
         __half* __restrict__ Q, __half* __restrict__ K, __half* __restrict__ V,
         const int* __restrict__ pos) {
    extern __shared__ char sm[];
    const int tid  = threadIdx.x;
    const int lane = tid & 31;
    const int warp = tid >> 5;
    const int wm   = warp & 1;
    const int wn   = warp >> 1;
    const int bm   = blockIdx.y * 128;
    const int bn   = blockIdx.x * 128;       // 0..2944 within concat N=3072

    GEMM_MAINLOOP(A, Bqkv)

    const int er = lane >> 2;
    const int ec = (lane & 3) * 2;
    const int region = bn >> 10;             // 0=Q, 1=K, 2=V (CTA-uniform)
    __half* H = (region == 0) ? Q : (region == 1) ? K : V;

    #pragma unroll
    for (int ni = 0; ni < 4; ni++) {
        int c0g = bn + wn * 32 + ni * 8 + ec;
        int c0  = c0g & 1023;                // column within the region
        float finv = 0.f;
        if (region < 2) {
            int i = (c0 & (HDK - 1)) >> 1;
            finv = (float)exp(-(double)i * (1.0 / 32.0) * 9.210340371976184);
        }
        #pragma unroll
        for (int mi = 0; mi < 4; mi++) {
            int r0 = bm + wm * 64 + mi * 16 + er;
            #pragma unroll
            for (int half = 0; half < 2; half++) {
                int r = r0 + half * 8;
                float v0 = d[mi][ni][half * 2], v1 = d[mi][ni][half * 2 + 1];
                if (region < 2) {
                    float sn, cs;
                    sincosf((float)pos[r] * finv, &sn, &cs);
                    float e = v0 * cs - v1 * sn;
                    float o = v0 * sn + v1 * cs;
                    if (region == 0) { e *= SCALE_Q; o *= SCALE_Q; }
                    v0 = e; v1 = o;
                }
                *(uint32_t*)(H + (size_t)r * D_MODEL + c0) = pack_h2(v0, v1);
            }
        }
    }
}

// ---------------------------------------------------------------------------
// Flash attention (causal), mma.sync fp16, fp32 accum, exp2-domain softmax.
// Row-sums via ones-column MMA; exp via ex2.approx.f16x2; Q frags reloaded
// from smem each tile to cut live registers (target 4 CTAs/SM).
// ---------------------------------------------------------------------------
#define QS_B      8192
#define ASTAGE_B  (2 * QS_B)
#define ATT_SMEM  (QS_B + 2 * ASTAGE_B)

__global__ void __launch_bounds__(128, 4)
attn_mma(const __half* __restrict__ qg, const __half* __restrict__ kg,
         const __half* __restrict__ vg, __half* __restrict__ og) {
    extern __shared__ char sm[];
    const int tid  = threadIdx.x;
    const int lane = tid & 31;
    const int warp = tid >> 5;
    const int h    = blockIdx.y;
    const int qi   = gridDim.x - 1 - blockIdx.x;   // heavy tiles first
    const int q0   = qi * 64;
    const int ntiles = qi + 1;
    const int cbase  = h * HDK;

    char* Q_t = sm;

    #pragma unroll
    for (int j = 0; j < 4; j++) {
        int qq  = tid + j * 128;
        int row = qq >> 3, q = qq & 7;
        int pq  = q ^ (row & 7);
        CP_ASYNC16(smem_u32(Q_t + row * 128 + pq * 16),
                   qg + (size_t)(q0 + row) * D_MODEL + cbase + q * 8);
    }

    const __half* kvsrc[2] = {kg, vg};
    auto load_kv = [&](int jt, int buf) {
        int n0 = jt * 64;
        char* sb = sm + QS_B + buf * ASTAGE_B;
        #pragma unroll
        for (int m = 0; m < 2; m++) {
            char* tile = sb + m * QS_B;
            #pragma unroll
            for (int j = 0; j < 4; j++) {
                int qq  = tid + j * 128;
                int row = qq >> 3, q = qq & 7;
                int pq  = q ^ (row & 7);
                CP_ASYNC16(smem_u32(tile + row * 128 + pq * 16),
                           kvsrc[m] + (size_t)(n0 + row) * D_MODEL + cbase + q * 8);
            }
        }
    };

    load_kv(0, 0);
    CP_COMMIT();

    float o[8][4];
    #pragma unroll
    for (int f = 0; f < 8; f++)
        #pragma unroll
        for (int k = 0; k < 4; k++) o[f][k] = 0.f;
    float m0 = -1e30f, m1 = -1e30f, l0 = 0.f, l1 = 0.f;
    const int g = lane >> 2;
    const uint32_t onesb[2] = {0x3C003C00u, 0x3C003C00u};   // half2(1,1) x2

    for (int jt = 0; jt < ntiles; jt++) {
        if (jt + 1 < ntiles) { load_kv(jt + 1, (jt + 1) & 1); CP_COMMIT(); CP_WAIT(1); }
        else                 { CP_WAIT(0); }
        __syncthreads();

        char* sb  = sm + QS_B + (jt & 1) * ASTAGE_B;
        char* K_t = sb;
        char* V_t = sb + QS_B;

        // ---- S = Qs K^T (log2 domain); Q frags reloaded per tile ----
        float s[8][4];
        #pragma unroll
        for (int f = 0; f < 8; f++)
            #pragma unroll
            for (int k = 0; k < 4; k++) s[f][k] = 0.f;

        #pragma unroll
        for (int ks = 0; ks < 4; ks++) {
            uint32_t qf[4];
            {
                int row = warp * 16 + (lane & 15);
                int aq  = ks * 2 + (lane >> 4);
                int pq  = aq ^ (row & 7);
                ldsm4(qf, smem_u32(Q_t + row * 128 + pq * 16));
            }
            uint32_t rk[4][4];
            #pragma unroll
            for (int gi = 0; gi < 4; gi++) {
                int brow = gi * 16 + ((lane >> 4) & 1) * 8 + (lane & 7);
                int bq   = ks * 2 + ((lane >> 3) & 1);
                int pq   = bq ^ (brow & 7);
                ldsm4(rk[gi], smem_u32(K_t + brow * 128 + pq * 16));
            }
            #pragma unroll
            for (int gi = 0; gi < 4; gi++) {
                mma16816(s[gi * 2],     qf, rk[gi]);
                mma16816(s[gi * 2 + 1], qf, rk[gi] + 2);
            }
        }

        // ---- causal mask (diagonal tile only) ----
        if (jt == ntiles - 1) {
            int lr0 = warp * 16 + g, lr1 = lr0 + 8;
            #pragma unroll
            for (int f = 0; f < 8; f++) {
                int c0 = f * 8 + (lane & 3) * 2;
                if (c0     > lr0) s[f][0] = -1e30f;
                if (c0 + 1 > lr0) s[f][1] = -1e30f;
                if (c0     > lr1) s[f][2] = -1e30f;
                if (c0 + 1 > lr1) s[f][3] = -1e30f;
            }
        }

        // ---- running max (fp32) ----
        float mx0 = -1e30f, mx1 = -1e30f;
        #pragma unroll
        for (int f = 0; f < 8; f++) {
            mx0 = fmaxf(mx0, fmaxf(s[f][0], s[f][1]));
            mx1 = fmaxf(mx1, fmaxf(s[f][2], s[f][3]));
        }
        mx0 = fmaxf(mx0, __shfl_xor_sync(0xffffffffu, mx0, 1));
        mx0 = fmaxf(mx0, __shfl_xor_sync(0xffffffffu, mx0, 2));
        mx1 = fmaxf(mx1, __shfl_xor_sync(0xffffffffu, mx1, 1));
        mx1 = fmaxf(mx1, __shfl_xor_sync(0xffffffffu, mx1, 2));

        float mn0 = fmaxf(m0, mx0), mn1 = fmaxf(m1, mx1);
        float cr0 = exp2f(m0 - mn0), cr1 = exp2f(m1 - mn1);
        m0 = mn0; m1 = mn1;

        // ---- P = exp2(S - mn): fp32 subtract, then f16x2 ex2 (packed) ----
        uint32_t ph[16];
        #pragma unroll
        for (int f = 0; f < 8; f++) {
            uint32_t p0 = pack_h2(s[f][0] - mn0, s[f][1] - mn0);
            uint32_t p1 = pack_h2(s[f][2] - mn1, s[f][3] - mn1);
            EX2_F16X2(ph[2 * f],     p0);
            EX2_F16X2(ph[2 * f + 1], p1);
        }

        // ---- rescale O ----
        #pragma unroll
        for (int f = 0; f < 8; f++) {
            o[f][0] *= cr0; o[f][1] *= cr0;
            o[f][2] *= cr1; o[f][3] *= cr1;
        }

        // ---- O += P V; row-sums via ones-column MMA ----
        float lf[4] = {0.f, 0.f, 0.f, 0.f};
        #pragma unroll
        for (int ks2 = 0; ks2 < 4; ks2++) {
            const uint32_t* pa = &ph[4 * ks2];
            int vrow = ks2 * 16 + ((lane >> 3) & 1) * 8 + (lane & 7);
            uint32_t bv[4][4];
            #pragma unroll
            for (int nvp = 0; nvp < 4; nvp++) {
                int vq = nvp * 2 + (lane >> 4);
                int pq = vq ^ (vrow & 7);
                ldsm4t(bv[nvp], smem_u32(V_t + vrow * 128 + pq * 16));
            }
            #pragma unroll
            for (int nvp = 0; nvp < 4; nvp++) {
                mma16816(o[nvp * 2],     pa, bv[nvp]);
                mma16816(o[nvp * 2 + 1], pa, bv[nvp] + 2);
            }
            mma16816(lf, pa, onesb);
        }
        l0 = l0 * cr0 + lf[0];
        l1 = l1 * cr1 + lf[2];
        __syncthreads();
    }

    // ---- epilogue: normalize, store fp16 ----
    float inv0 = 1.f / l0, inv1 = 1.f / l1;
    int row0 = q0 + warp * 16 + g;
    int colb = cbase + (lane & 3) * 2;
    #pragma unroll
    for (int f = 0; f < 8; f++) {
        int c = colb + f * 8;
        *(uint32_t*)(og + (size_t)row0 * D_MODEL + c) =
            pack_h2(o[f][0] * inv0, o[f][1] * inv0);
        *(uint32_t*)(og + (size_t)(row0 + 8) * D_MODEL + c) =
            pack_h2(o[f][2] * inv1, o[f][3] * inv1);
    }
}

// ---------------------------------------------------------------------------
extern "C" void kernel_launch(void* const* d_in, const int* in_sizes, int n_in,
                              void* d_out, int out_size) {
    const float* x   = (const float*)d_in[0];
    const int*   pos = (const int*)d_in[1];
    const float* Wq  = (const float*)d_in[2];
    const float* Wk  = (const float*)d_in[3];
    const float* Wv  = (const float*)d_in[4];
    const float* Wo  = (const float*)d_in[5];
    float* out = (float*)d_out;

    __half *xp, *ap, *qp, *kp, *vp, *wqkv, *wo;
    cudaGetSymbolAddress((void**)&xp, g_x);
    cudaGetSymbolAddress((void**)&ap, g_a);
    cudaGetSymbolAddress((void**)&qp, g_q);
    cudaGetSymbolAddress((void**)&kp, g_k);
    cudaGetSymbolAddress((void**)&vp, g_v);
    cudaGetSymbolAddress((void**)&wqkv, g_wqkv);
    cudaGetSymbolAddress((void**)&wo, g_wo);

    cudaFuncSetAttribute(gemm_f16,  cudaFuncAttributeMaxDynamicSharedMemorySize, GSMEM);
    cudaFuncSetAttribute(gemm_qkv,  cudaFuncAttributeMaxDynamicSharedMemorySize, GSMEM);
    cudaFuncSetAttribute(attn_mma,  cudaFuncAttributeMaxDynamicSharedMemorySize, ATT_SMEM);

    const int nx = S_LEN * D_MODEL;
    const int nw = D_MODEL * D_MODEL;
    cvt_all<<<(nx + 4 * nw) / 1024, 256>>>(x, Wq, Wk, Wv, Wo, xp, wqkv, wo);

    dim3 gqkv(3 * D_MODEL / 128, S_LEN / 128);   // (24, 32) = 768 CTAs
    gemm_qkv<<<gqkv, 256, GSMEM>>>(xp, wqkv, qp, kp, vp, pos);

    dim3 gattn(S_LEN / 64, NHEAD);               // (64, 16)
    attn_mma<<<gattn, 128, ATT_SMEM>>>(qp, kp, vp, ap);

    dim3 gproj(D_MODEL / 128, S_LEN / 128);      // (8, 32)
    gemm_f16<<<gproj, 256, GSMEM>>>(ap, wo, out);
}